// round 1
// baseline (speedup 1.0000x reference)
#include <cuda_runtime.h>
#include <math.h>

// ---------------- problem constants ----------------
#define NTOK   8192      // 8 batches * 32*32 tokens
#define CDIM   512
#define FFDIM  2048
#define NHEAD  8
#define HD     64
#define SEQ    1024      // tokens per batch
#define NBATCH 8

// ---------------- scratch (device globals; no allocation allowed) ----------
__device__ float g_xn  [NTOK * CDIM];
__device__ float g_q   [NTOK * CDIM];
__device__ float g_k   [NTOK * CDIM];
__device__ float g_v   [NTOK * CDIM];
__device__ float g_o   [NTOK * CDIM];
__device__ float g_attn[NTOK * CDIM];
__device__ float g_yn  [NTOK * CDIM];
__device__ float g_h1  [NTOK * FFDIM];

// ---------------- LayerNorm: one block per row of 512 ----------------------
__global__ __launch_bounds__(128) void ln_kernel(
    const float* __restrict__ in, const float* __restrict__ gam,
    const float* __restrict__ bet, float* __restrict__ out)
{
    const int row = blockIdx.x;
    const int t = threadIdx.x;                 // 128 threads, one float4 each
    const float4* x4 = (const float4*)(in + (size_t)row * CDIM);
    float4 v = x4[t];
    float s  = v.x + v.y + v.z + v.w;
    float ss = fmaf(v.x, v.x, fmaf(v.y, v.y, fmaf(v.z, v.z, v.w * v.w)));
    #pragma unroll
    for (int o = 16; o > 0; o >>= 1) {
        s  += __shfl_xor_sync(0xffffffffu, s,  o);
        ss += __shfl_xor_sync(0xffffffffu, ss, o);
    }
    __shared__ float sh[4], shh[4];
    const int wid = t >> 5, lane = t & 31;
    if (lane == 0) { sh[wid] = s; shh[wid] = ss; }
    __syncthreads();
    float tot  = sh[0] + sh[1] + sh[2] + sh[3];
    float tot2 = shh[0] + shh[1] + shh[2] + shh[3];
    const float mean = tot * (1.0f / CDIM);
    const float var  = tot2 * (1.0f / CDIM) - mean * mean;
    const float r    = rsqrtf(var + 1e-5f);
    float4 g = ((const float4*)gam)[t];
    float4 b = ((const float4*)bet)[t];
    float4 o;
    o.x = (v.x - mean) * r * g.x + b.x;
    o.y = (v.y - mean) * r * g.y + b.y;
    o.z = (v.z - mean) * r * g.z + b.z;
    o.w = (v.w - mean) * r * g.w + b.w;
    ((float4*)(out + (size_t)row * CDIM))[t] = o;
}

// ---------------- GEMM: C[M,N] = A[M,K] @ B[K,N] (+bias)(+res)(relu) -------
// 128x64 block tile, BK=16, 256 threads, 8x4 per-thread microtile.
// Requires M%128==0, N%64==0, K%16==0 (true for all uses here).
template <bool BIAS, bool RES, bool RELU>
__global__ __launch_bounds__(256, 2) void gemm_k(
    const float* __restrict__ A, const float* __restrict__ B,
    const float* __restrict__ bias, const float* __restrict__ res,
    float* __restrict__ C, int M, int N, int K)
{
    __shared__ float As[128][17];
    __shared__ float Bs[16][64];

    const int tid = threadIdx.x;
    const int tx  = tid & 15;
    const int ty  = tid >> 4;
    const int bm0 = blockIdx.y * 128;
    const int bn0 = blockIdx.x * 64;

    float acc[8][4];
    #pragma unroll
    for (int i = 0; i < 8; i++)
        #pragma unroll
        for (int j = 0; j < 4; j++) acc[i][j] = 0.0f;

    const int av0 = tid * 2;        // two A float4 vectors per thread
    const int brw = tid >> 4;       // B tile row 0..15
    const int bvc = tid & 15;       // B tile float4 col 0..15

    for (int kt = 0; kt < K; kt += 16) {
        #pragma unroll
        for (int j = 0; j < 2; j++) {
            int v = av0 + j;
            int r = v >> 2, kc = (v & 3) << 2;
            float4 a = *(const float4*)&A[(size_t)(bm0 + r) * K + kt + kc];
            As[r][kc + 0] = a.x; As[r][kc + 1] = a.y;
            As[r][kc + 2] = a.z; As[r][kc + 3] = a.w;
        }
        float4 bl = *(const float4*)&B[(size_t)(kt + brw) * N + bn0 + (bvc << 2)];
        *(float4*)&Bs[brw][bvc << 2] = bl;
        __syncthreads();

        #pragma unroll
        for (int k = 0; k < 16; k++) {
            float4 bv = *(const float4*)&Bs[k][tx << 2];
            #pragma unroll
            for (int i = 0; i < 8; i++) {
                float a = As[(ty << 3) + i][k];
                acc[i][0] = fmaf(a, bv.x, acc[i][0]);
                acc[i][1] = fmaf(a, bv.y, acc[i][1]);
                acc[i][2] = fmaf(a, bv.z, acc[i][2]);
                acc[i][3] = fmaf(a, bv.w, acc[i][3]);
            }
        }
        __syncthreads();
    }

    float4 bia = make_float4(0.f, 0.f, 0.f, 0.f);
    if (BIAS) bia = *(const float4*)&bias[bn0 + (tx << 2)];
    #pragma unroll
    for (int i = 0; i < 8; i++) {
        int row = bm0 + (ty << 3) + i;
        size_t off = (size_t)row * N + bn0 + (tx << 2);
        float4 o;
        o.x = acc[i][0] + bia.x;
        o.y = acc[i][1] + bia.y;
        o.z = acc[i][2] + bia.z;
        o.w = acc[i][3] + bia.w;
        if (RES) {
            float4 rr = *(const float4*)&res[off];
            o.x += rr.x; o.y += rr.y; o.z += rr.z; o.w += rr.w;
        }
        if (RELU) {
            o.x = fmaxf(o.x, 0.f); o.y = fmaxf(o.y, 0.f);
            o.z = fmaxf(o.z, 0.f); o.w = fmaxf(o.w, 0.f);
        }
        *(float4*)&C[off] = o;
    }
}

// ---------------- fused attention: scores -> softmax -> probs out -> P@V ---
// One block = (batch b, head hd, 32 query rows). Scores tile 32x1024 lives in
// dynamic smem (128 KB); probs written once to gmem; O = P@V computed from smem.
__global__ __launch_bounds__(256, 1) void attn_kernel(float* __restrict__ probs)
{
    extern __shared__ float sm[];
    float* S  = sm;                  // 32 * 1024
    float* Qs = S + 32 * 1024;       // 32 * 64
    float* KV = Qs + 32 * 64;        // 64 * 68 (padded)

    const int tid = threadIdx.x;
    const int tx  = tid & 15;
    const int ty  = tid >> 4;
    const int qb  = blockIdx.x;      // 0..31
    const int hd  = blockIdx.y;      // 0..7
    const int b   = blockIdx.z;      // 0..7
    const int q0  = qb * 32;
    const size_t tokbase = (size_t)b * SEQ;

    // load Q tile [32 x 64]
    for (int i = tid; i < 512; i += 256) {
        int r = i >> 4, v = i & 15;
        *(float4*)&Qs[r * 64 + (v << 2)] =
            *(const float4*)&g_q[(tokbase + q0 + r) * CDIM + hd * HD + (v << 2)];
    }

    const int r0 = ty * 2;

    // ---- scores: S[32,1024] = Q @ K^T / 8 ----
    for (int kv0 = 0; kv0 < SEQ; kv0 += 64) {
        {   // load K tile transposed: KV[d*68 + kv]
            int kvr = tid >> 2;
            int seg = (tid & 3) * 16;
            const float* kp = &g_k[(tokbase + kv0 + kvr) * CDIM + hd * HD + seg];
            #pragma unroll
            for (int c = 0; c < 4; c++) {
                float4 kd = *(const float4*)&kp[c * 4];
                KV[(seg + c * 4 + 0) * 68 + kvr] = kd.x;
                KV[(seg + c * 4 + 1) * 68 + kvr] = kd.y;
                KV[(seg + c * 4 + 2) * 68 + kvr] = kd.z;
                KV[(seg + c * 4 + 3) * 68 + kvr] = kd.w;
            }
        }
        __syncthreads();
        float a0c[4] = {0.f, 0.f, 0.f, 0.f};
        float a1c[4] = {0.f, 0.f, 0.f, 0.f};
        #pragma unroll
        for (int d = 0; d < 64; d++) {
            float4 kvv = *(const float4*)&KV[d * 68 + (tx << 2)];
            float a0 = Qs[r0 * 64 + d];
            float a1 = Qs[(r0 + 1) * 64 + d];
            a0c[0] = fmaf(a0, kvv.x, a0c[0]); a0c[1] = fmaf(a0, kvv.y, a0c[1]);
            a0c[2] = fmaf(a0, kvv.z, a0c[2]); a0c[3] = fmaf(a0, kvv.w, a0c[3]);
            a1c[0] = fmaf(a1, kvv.x, a1c[0]); a1c[1] = fmaf(a1, kvv.y, a1c[1]);
            a1c[2] = fmaf(a1, kvv.z, a1c[2]); a1c[3] = fmaf(a1, kvv.w, a1c[3]);
        }
        float4 s0 = make_float4(a0c[0] * 0.125f, a0c[1] * 0.125f, a0c[2] * 0.125f, a0c[3] * 0.125f);
        float4 s1 = make_float4(a1c[0] * 0.125f, a1c[1] * 0.125f, a1c[2] * 0.125f, a1c[3] * 0.125f);
        *(float4*)&S[r0 * 1024 + kv0 + (tx << 2)] = s0;
        *(float4*)&S[(r0 + 1) * 1024 + kv0 + (tx << 2)] = s1;
        __syncthreads();
    }

    // ---- softmax per row (8 warps x 4 rows), write probs to gmem ----
    const int wid = tid >> 5, lane = tid & 31;
    #pragma unroll
    for (int rr = 0; rr < 4; rr++) {
        int row = wid * 4 + rr;
        float4 vals[8];
        float mx = -1e30f;
        #pragma unroll
        for (int v = 0; v < 8; v++) {
            vals[v] = *(float4*)&S[row * 1024 + (v * 32 + lane) * 4];
            mx = fmaxf(mx, fmaxf(fmaxf(vals[v].x, vals[v].y), fmaxf(vals[v].z, vals[v].w)));
        }
        #pragma unroll
        for (int o = 16; o > 0; o >>= 1) mx = fmaxf(mx, __shfl_xor_sync(0xffffffffu, mx, o));
        float sum = 0.f;
        #pragma unroll
        for (int v = 0; v < 8; v++) {
            vals[v].x = __expf(vals[v].x - mx);
            vals[v].y = __expf(vals[v].y - mx);
            vals[v].z = __expf(vals[v].z - mx);
            vals[v].w = __expf(vals[v].w - mx);
            sum += vals[v].x + vals[v].y + vals[v].z + vals[v].w;
        }
        #pragma unroll
        for (int o = 16; o > 0; o >>= 1) sum += __shfl_xor_sync(0xffffffffu, sum, o);
        float inv = 1.0f / sum;
        size_t pbase = ((((size_t)b * SEQ + q0 + row) * NHEAD) + hd) * SEQ;
        #pragma unroll
        for (int v = 0; v < 8; v++) {
            float4 p = make_float4(vals[v].x * inv, vals[v].y * inv,
                                   vals[v].z * inv, vals[v].w * inv);
            *(float4*)&S[row * 1024 + (v * 32 + lane) * 4] = p;
            *(float4*)&probs[pbase + (v * 32 + lane) * 4] = p;
        }
    }

    // ---- O = P @ V ----
    float o0[4] = {0.f, 0.f, 0.f, 0.f};
    float o1[4] = {0.f, 0.f, 0.f, 0.f};
    for (int kv0 = 0; kv0 < SEQ; kv0 += 64) {
        __syncthreads();             // previous KV consumers done
        {   // load V tile untransposed: KV[kv*68 + d]
            int kvr = tid >> 2;
            int seg = (tid & 3) * 16;
            const float* vp = &g_v[(tokbase + kv0 + kvr) * CDIM + hd * HD + seg];
            #pragma unroll
            for (int c = 0; c < 4; c++) {
                *(float4*)&KV[kvr * 68 + seg + c * 4] = *(const float4*)&vp[c * 4];
            }
        }
        __syncthreads();
        #pragma unroll 8
        for (int kk = 0; kk < 64; kk++) {
            float4 vv = *(const float4*)&KV[kk * 68 + (tx << 2)];
            float p0 = S[r0 * 1024 + kv0 + kk];
            float p1 = S[(r0 + 1) * 1024 + kv0 + kk];
            o0[0] = fmaf(p0, vv.x, o0[0]); o0[1] = fmaf(p0, vv.y, o0[1]);
            o0[2] = fmaf(p0, vv.z, o0[2]); o0[3] = fmaf(p0, vv.w, o0[3]);
            o1[0] = fmaf(p1, vv.x, o1[0]); o1[1] = fmaf(p1, vv.y, o1[1]);
            o1[2] = fmaf(p1, vv.z, o1[2]); o1[3] = fmaf(p1, vv.w, o1[3]);
        }
    }
    *(float4*)&g_o[(tokbase + q0 + r0) * CDIM + hd * HD + (tx << 2)] =
        make_float4(o0[0], o0[1], o0[2], o0[3]);
    *(float4*)&g_o[(tokbase + q0 + r0 + 1) * CDIM + hd * HD + (tx << 2)] =
        make_float4(o1[0], o1[1], o1[2], o1[3]);
}

// ---------------- launcher ----------------
extern "C" void kernel_launch(void* const* d_in, const int* in_sizes, int n_in,
                              void* d_out, int out_size)
{
    const float* x     = (const float*)d_in[0];
    const float* Wq    = (const float*)d_in[1];
    const float* Wk    = (const float*)d_in[2];
    const float* Wv    = (const float*)d_in[3];
    const float* Wo    = (const float*)d_in[4];
    const float* ln1_g = (const float*)d_in[5];
    const float* ln1_b = (const float*)d_in[6];
    const float* fc1_w = (const float*)d_in[7];
    const float* fc1_b = (const float*)d_in[8];
    const float* fc2_w = (const float*)d_in[9];
    const float* fc2_b = (const float*)d_in[10];
    const float* ln2_g = (const float*)d_in[11];
    const float* ln2_b = (const float*)d_in[12];

    float* out   = (float*)d_out;                    // [8192, 512]
    float* probs = out + (size_t)NTOK * CDIM;        // [8, 1024, 8, 1024]

    float *p_xn, *p_q, *p_k, *p_v, *p_o, *p_attn, *p_yn, *p_h1;
    cudaGetSymbolAddress((void**)&p_xn,   g_xn);
    cudaGetSymbolAddress((void**)&p_q,    g_q);
    cudaGetSymbolAddress((void**)&p_k,    g_k);
    cudaGetSymbolAddress((void**)&p_v,    g_v);
    cudaGetSymbolAddress((void**)&p_o,    g_o);
    cudaGetSymbolAddress((void**)&p_attn, g_attn);
    cudaGetSymbolAddress((void**)&p_yn,   g_yn);
    cudaGetSymbolAddress((void**)&p_h1,   g_h1);

    const int ATTN_SMEM = (32 * 1024 + 32 * 64 + 64 * 68) * 4;  // 156672 B
    cudaFuncSetAttribute(attn_kernel,
                         cudaFuncAttributeMaxDynamicSharedMemorySize, ATTN_SMEM);

    // 1. LN1
    ln_kernel<<<NTOK, 128>>>(x, ln1_g, ln1_b, p_xn);

    // 2. QKV projections
    dim3 g512(CDIM / 64, NTOK / 128);
    gemm_k<false, false, false><<<g512, 256>>>(p_xn, Wq, nullptr, nullptr, p_q, NTOK, CDIM, CDIM);
    gemm_k<false, false, false><<<g512, 256>>>(p_xn, Wk, nullptr, nullptr, p_k, NTOK, CDIM, CDIM);
    gemm_k<false, false, false><<<g512, 256>>>(p_xn, Wv, nullptr, nullptr, p_v, NTOK, CDIM, CDIM);

    // 3. attention (writes probs region of d_out and g_o)
    attn_kernel<<<dim3(32, NHEAD, NBATCH), 256, ATTN_SMEM>>>(probs);

    // 4. attn_out = O @ Wo + xn
    gemm_k<false, true, false><<<g512, 256>>>(p_o, Wo, nullptr, p_xn, p_attn, NTOK, CDIM, CDIM);

    // 5. LN2
    ln_kernel<<<NTOK, 128>>>(p_attn, ln2_g, ln2_b, p_yn);

    // 6. h1 = relu(yn @ fc1 + b1)
    dim3 gff(FFDIM / 64, NTOK / 128);
    gemm_k<true, false, true><<<gff, 256>>>(p_yn, fc1_w, fc1_b, nullptr, p_h1, NTOK, FFDIM, CDIM);

    // 7. out = h1 @ fc2 + b2 + yn   (written straight into d_out)
    gemm_k<true, true, false><<<g512, 256>>>(p_h1, fc2_w, fc2_b, p_yn, out, NTOK, CDIM, FFDIM);
}

// round 4
// speedup vs baseline: 1.5403x; 1.5403x over previous
#include <cuda_runtime.h>
#include <cuda_bf16.h>
#include <math.h>
#include <stdint.h>

// ---------------- problem constants ----------------
#define NTOK   8192
#define CDIM   512
#define FFDIM  2048
#define NHEAD  8
#define HD     64
#define SEQ    1024
#define NBATCH 8

// ---------------- scratch ----------------
__device__ float g_xn  [NTOK * CDIM];
__device__ float g_q   [NTOK * CDIM];
__device__ float g_k   [NTOK * CDIM];
__device__ float g_v   [NTOK * CDIM];
__device__ float g_attn[NTOK * CDIM];
__device__ float g_yn  [NTOK * CDIM];

__device__ __nv_bfloat16 g_xnh[NTOK * CDIM], g_xnl[NTOK * CDIM];
__device__ __nv_bfloat16 g_ynh[NTOK * CDIM], g_ynl[NTOK * CDIM];
__device__ __nv_bfloat16 g_oh [NTOK * CDIM], g_ol [NTOK * CDIM];
__device__ __nv_bfloat16 g_h1h[NTOK * FFDIM], g_h1l[NTOK * FFDIM];

__device__ __nv_bfloat16 g_wqth[CDIM * CDIM], g_wqtl[CDIM * CDIM];
__device__ __nv_bfloat16 g_wkth[CDIM * CDIM], g_wktl[CDIM * CDIM];
__device__ __nv_bfloat16 g_wvth[CDIM * CDIM], g_wvtl[CDIM * CDIM];
__device__ __nv_bfloat16 g_woth[CDIM * CDIM], g_wotl[CDIM * CDIM];
__device__ __nv_bfloat16 g_f1th[CDIM * FFDIM], g_f1tl[CDIM * FFDIM];
__device__ __nv_bfloat16 g_f2th[FFDIM * CDIM], g_f2tl[FFDIM * CDIM];

// ---------------- helpers ----------------
__device__ __forceinline__ void split_bf16(float x, __nv_bfloat16& h, __nv_bfloat16& l) {
    h = __float2bfloat16(x);
    l = __float2bfloat16(x - __bfloat162float(h));
}
__device__ __forceinline__ uint32_t smem_u32(const void* p) {
    uint32_t a;
    asm("{ .reg .u64 t; cvta.to.shared.u64 t, %1; cvt.u32.u64 %0, t; }" : "=r"(a) : "l"(p));
    return a;
}
__device__ __forceinline__ void cpa16(uint32_t s, const void* g) {
    asm volatile("cp.async.cg.shared.global [%0], [%1], 16;" :: "r"(s), "l"(g) : "memory");
}
#define CP_COMMIT() asm volatile("cp.async.commit_group;" ::: "memory")

__device__ __forceinline__ void mma16816(float* c, const uint32_t* a, const uint32_t* b) {
    asm volatile("mma.sync.aligned.m16n8k16.row.col.f32.bf16.bf16.f32 "
        "{%0,%1,%2,%3}, {%4,%5,%6,%7}, {%8,%9}, {%0,%1,%2,%3};"
        : "+f"(c[0]), "+f"(c[1]), "+f"(c[2]), "+f"(c[3])
        : "r"(a[0]), "r"(a[1]), "r"(a[2]), "r"(a[3]), "r"(b[0]), "r"(b[1]));
}

// ---------------- LayerNorm (+optional bf16 hi/lo) ----------------
template <bool HL>
__global__ __launch_bounds__(128) void ln_kernel(
    const float* __restrict__ in, const float* __restrict__ gam,
    const float* __restrict__ bet, float* __restrict__ out,
    __nv_bfloat16* __restrict__ oh, __nv_bfloat16* __restrict__ ol)
{
    const int row = blockIdx.x;
    const int t = threadIdx.x;
    const float4* x4 = (const float4*)(in + (size_t)row * CDIM);
    float4 v = x4[t];
    float s  = v.x + v.y + v.z + v.w;
    float ss = fmaf(v.x, v.x, fmaf(v.y, v.y, fmaf(v.z, v.z, v.w * v.w)));
    #pragma unroll
    for (int o = 16; o > 0; o >>= 1) {
        s  += __shfl_xor_sync(0xffffffffu, s,  o);
        ss += __shfl_xor_sync(0xffffffffu, ss, o);
    }
    __shared__ float sh[4], shh[4];
    const int wid = t >> 5, lane = t & 31;
    if (lane == 0) { sh[wid] = s; shh[wid] = ss; }
    __syncthreads();
    float tot  = sh[0] + sh[1] + sh[2] + sh[3];
    float tot2 = shh[0] + shh[1] + shh[2] + shh[3];
    const float mean = tot * (1.0f / CDIM);
    const float var  = tot2 * (1.0f / CDIM) - mean * mean;
    const float r    = rsqrtf(var + 1e-5f);
    float4 g = ((const float4*)gam)[t];
    float4 b = ((const float4*)bet)[t];
    float o4[4];
    o4[0] = (v.x - mean) * r * g.x + b.x;
    o4[1] = (v.y - mean) * r * g.y + b.y;
    o4[2] = (v.z - mean) * r * g.z + b.z;
    o4[3] = (v.w - mean) * r * g.w + b.w;
    ((float4*)(out + (size_t)row * CDIM))[t] = make_float4(o4[0], o4[1], o4[2], o4[3]);
    if (HL) {
        size_t base = (size_t)row * CDIM + t * 4;
        #pragma unroll
        for (int e = 0; e < 4; e++) {
            __nv_bfloat16 h, l;
            split_bf16(o4[e], h, l);
            oh[base + e] = h; ol[base + e] = l;
        }
    }
}

// ---------------- weight transpose + hi/lo split: W[K][N] -> T[N][K] -------
__global__ __launch_bounds__(256) void transconv(
    const float* __restrict__ W, __nv_bfloat16* __restrict__ Th,
    __nv_bfloat16* __restrict__ Tl, int K, int N)
{
    __shared__ float t[32][33];
    const int n0 = blockIdx.x * 32, k0 = blockIdx.y * 32;
    const int tx = threadIdx.x & 31, ty = threadIdx.x >> 5;
    #pragma unroll
    for (int i = 0; i < 4; i++)
        t[ty + i * 8][tx] = W[(size_t)(k0 + ty + i * 8) * N + n0 + tx];
    __syncthreads();
    #pragma unroll
    for (int i = 0; i < 4; i++) {
        int r = ty + i * 8;
        float v = t[tx][r];
        __nv_bfloat16 h, l;
        split_bf16(v, h, l);
        Th[(size_t)(n0 + r) * K + k0 + tx] = h;
        Tl[(size_t)(n0 + r) * K + k0 + tx] = l;
    }
}

// ---------------- mma.sync split-bf16 GEMM ----------------
// C[M,N] = A[M,K] @ Bt[N,K]^T  (3-term hi/lo bf16, fp32 accum)
#define BM 128
#define BN 128
#define KC 32
#define ROWB 80                          // 64B data + 16B pad, conflict-free
#define MAT_BYTES (128 * ROWB)           // 10240
#define AH_OFF 0
#define AL_OFF MAT_BYTES
#define BH_OFF (2 * MAT_BYTES)
#define BL_OFF (3 * MAT_BYTES)
#define STAGE_BYTES (4 * MAT_BYTES)      // 40960
#define GT_SMEM (2 * STAGE_BYTES)        // 81920

template <bool BIAS, bool RES, bool RELU, bool OUTBF>
__global__ __launch_bounds__(256, 2) void gemm_mma(
    const __nv_bfloat16* __restrict__ Ah, const __nv_bfloat16* __restrict__ Al,
    const __nv_bfloat16* __restrict__ Bh, const __nv_bfloat16* __restrict__ Bl,
    const float* __restrict__ bias, const float* __restrict__ res,
    float* __restrict__ Cf, __nv_bfloat16* __restrict__ Ch,
    __nv_bfloat16* __restrict__ Cl, int M, int N, int K)
{
    extern __shared__ char sm[];
    const uint32_t sbase = smem_u32(sm);
    const int tid  = threadIdx.x;
    const int lane = tid & 31;
    const int warp = tid >> 5;
    const int wm0  = (warp & 3) * 32;      // 4 warps in M
    const int wn0  = (warp >> 2) * 64;     // 2 warps in N
    const int g    = lane >> 2;
    const int tig  = lane & 3;
    const int bm0  = blockIdx.y * BM;
    const int bn0  = blockIdx.x * BN;

    float acc[2][8][4];
    #pragma unroll
    for (int i = 0; i < 2; i++)
        #pragma unroll
        for (int j = 0; j < 8; j++)
            #pragma unroll
            for (int e = 0; e < 4; e++) acc[i][j][e] = 0.0f;

    const __nv_bfloat16* gsrc[4] = {Ah, Al, Bh, Bl};

    auto load_stage = [&](int kt, int buf) {
        const uint32_t st = sbase + buf * STAGE_BYTES;
        #pragma unroll
        for (int i = 0; i < 8; i++) {
            int idx = tid + i * 256;              // 0..2047
            int mat = idx >> 9;                   // 0..3
            int rix = idx & 511;
            int r   = rix >> 2;                   // 0..127
            int cb  = (rix & 3) * 16;             // byte offset in row
            int grow = (mat < 2) ? (bm0 + r) : (bn0 + r);
            const char* src = (const char*)(gsrc[mat] + (size_t)grow * K + kt) + cb;
            cpa16(st + mat * MAT_BYTES + r * ROWB + cb, src);
        }
        CP_COMMIT();
    };

    const int S = K / KC;
    load_stage(0, 0);
    load_stage(KC, 1);

    for (int s = 0; s < S; s++) {
        if (s + 1 < S) asm volatile("cp.async.wait_group 1;" ::: "memory");
        else           asm volatile("cp.async.wait_group 0;" ::: "memory");
        __syncthreads();

        const char* sb = sm + (s & 1) * STAGE_BYTES;
        #pragma unroll
        for (int kk = 0; kk < 2; kk++) {
            const int c0 = (kk * 16 + 2 * tig) * 2;   // byte col within row
            uint32_t afr[2][2][4];
            #pragma unroll
            for (int am = 0; am < 2; am++) {
                const char* rowH = sb + AH_OFF + (wm0 + am * 16 + g) * ROWB;
                const char* rowL = sb + AL_OFF + (wm0 + am * 16 + g) * ROWB;
                afr[am][0][0] = *(const uint32_t*)(rowH + c0);
                afr[am][0][1] = *(const uint32_t*)(rowH + 8 * ROWB + c0);
                afr[am][0][2] = *(const uint32_t*)(rowH + c0 + 16);
                afr[am][0][3] = *(const uint32_t*)(rowH + 8 * ROWB + c0 + 16);
                afr[am][1][0] = *(const uint32_t*)(rowL + c0);
                afr[am][1][1] = *(const uint32_t*)(rowL + 8 * ROWB + c0);
                afr[am][1][2] = *(const uint32_t*)(rowL + c0 + 16);
                afr[am][1][3] = *(const uint32_t*)(rowL + 8 * ROWB + c0 + 16);
            }
            #pragma unroll
            for (int bn = 0; bn < 8; bn++) {
                const char* rH = sb + BH_OFF + (wn0 + bn * 8 + g) * ROWB;
                const char* rL = sb + BL_OFF + (wn0 + bn * 8 + g) * ROWB;
                uint32_t bh[2] = {*(const uint32_t*)(rH + c0),
                                  *(const uint32_t*)(rH + c0 + 16)};
                uint32_t bl[2] = {*(const uint32_t*)(rL + c0),
                                  *(const uint32_t*)(rL + c0 + 16)};
                mma16816(acc[0][bn], afr[0][0], bh);
                mma16816(acc[0][bn], afr[0][1], bh);
                mma16816(acc[0][bn], afr[0][0], bl);
                mma16816(acc[1][bn], afr[1][0], bh);
                mma16816(acc[1][bn], afr[1][1], bh);
                mma16816(acc[1][bn], afr[1][0], bl);
            }
        }
        __syncthreads();
        if (s + 2 < S) load_stage((s + 2) * KC, s & 1);
    }

    // ---------------- epilogue ----------------
    #pragma unroll
    for (int am = 0; am < 2; am++) {
        #pragma unroll
        for (int bn = 0; bn < 8; bn++) {
            const int row = bm0 + wm0 + am * 16 + g;
            const int col = bn0 + wn0 + bn * 8 + 2 * tig;
            float* c = acc[am][bn];
            #pragma unroll
            for (int h = 0; h < 2; h++) {          // h=0 -> row, h=1 -> row+8
                const int r = row + h * 8;
                float v0 = c[h * 2 + 0];
                float v1 = c[h * 2 + 1];
                if (BIAS) { v0 += bias[col]; v1 += bias[col + 1]; }
                if (RES) {
                    float2 rr = *(const float2*)&res[(size_t)r * N + col];
                    v0 += rr.x; v1 += rr.y;
                }
                if (RELU) { v0 = fmaxf(v0, 0.f); v1 = fmaxf(v1, 0.f); }
                if (OUTBF) {
                    __nv_bfloat16 h0, l0, h1, l1;
                    split_bf16(v0, h0, l0);
                    split_bf16(v1, h1, l1);
                    __nv_bfloat162 hp; hp.x = h0; hp.y = h1;
                    __nv_bfloat162 lp; lp.x = l0; lp.y = l1;
                    *(__nv_bfloat162*)(Ch + (size_t)r * N + col) = hp;
                    *(__nv_bfloat162*)(Cl + (size_t)r * N + col) = lp;
                } else {
                    *(float2*)&Cf[(size_t)r * N + col] = make_float2(v0, v1);
                }
            }
        }
    }
}

// ---------------- fused attention (SIMT; bf16 hi/lo O out) ----------------
__global__ __launch_bounds__(256, 1) void attn_kernel(float* __restrict__ probs)
{
    extern __shared__ float smf[];
    float* S  = smf;                 // 32 * 1024
    float* Qs = S + 32 * 1024;       // 32 * 64
    float* KV = Qs + 32 * 64;        // 64 * 68

    const int tid = threadIdx.x;
    const int tx  = tid & 15;
    const int ty  = tid >> 4;
    const int qb  = blockIdx.x;
    const int hd  = blockIdx.y;
    const int b   = blockIdx.z;
    const int q0  = qb * 32;
    const size_t tokbase = (size_t)b * SEQ;

    for (int i = tid; i < 512; i += 256) {
        int r = i >> 4, v = i & 15;
        *(float4*)&Qs[r * 64 + (v << 2)] =
            *(const float4*)&g_q[(tokbase + q0 + r) * CDIM + hd * HD + (v << 2)];
    }

    const int r0 = ty * 2;

    for (int kv0 = 0; kv0 < SEQ; kv0 += 64) {
        {
            int kvr = tid >> 2;
            int seg = (tid & 3) * 16;
            const float* kp = &g_k[(tokbase + kv0 + kvr) * CDIM + hd * HD + seg];
            #pragma unroll
            for (int c = 0; c < 4; c++) {
                float4 kd = *(const float4*)&kp[c * 4];
                KV[(seg + c * 4 + 0) * 68 + kvr] = kd.x;
                KV[(seg + c * 4 + 1) * 68 + kvr] = kd.y;
                KV[(seg + c * 4 + 2) * 68 + kvr] = kd.z;
                KV[(seg + c * 4 + 3) * 68 + kvr] = kd.w;
            }
        }
        __syncthreads();
        float a0c[4] = {0.f, 0.f, 0.f, 0.f};
        float a1c[4] = {0.f, 0.f, 0.f, 0.f};
        #pragma unroll
        for (int d = 0; d < 64; d++) {
            float4 kvv = *(const float4*)&KV[d * 68 + (tx << 2)];
            float a0 = Qs[r0 * 64 + d];
            float a1 = Qs[(r0 + 1) * 64 + d];
            a0c[0] = fmaf(a0, kvv.x, a0c[0]); a0c[1] = fmaf(a0, kvv.y, a0c[1]);
            a0c[2] = fmaf(a0, kvv.z, a0c[2]); a0c[3] = fmaf(a0, kvv.w, a0c[3]);
            a1c[0] = fmaf(a1, kvv.x, a1c[0]); a1c[1] = fmaf(a1, kvv.y, a1c[1]);
            a1c[2] = fmaf(a1, kvv.z, a1c[2]); a1c[3] = fmaf(a1, kvv.w, a1c[3]);
        }
        *(float4*)&S[r0 * 1024 + kv0 + (tx << 2)] =
            make_float4(a0c[0] * 0.125f, a0c[1] * 0.125f, a0c[2] * 0.125f, a0c[3] * 0.125f);
        *(float4*)&S[(r0 + 1) * 1024 + kv0 + (tx << 2)] =
            make_float4(a1c[0] * 0.125f, a1c[1] * 0.125f, a1c[2] * 0.125f, a1c[3] * 0.125f);
        __syncthreads();
    }

    const int wid = tid >> 5, lane = tid & 31;
    #pragma unroll
    for (int rr = 0; rr < 4; rr++) {
        int row = wid * 4 + rr;
        float4 vals[8];
        float mx = -1e30f;
        #pragma unroll
        for (int v = 0; v < 8; v++) {
            vals[v] = *(float4*)&S[row * 1024 + (v * 32 + lane) * 4];
            mx = fmaxf(mx, fmaxf(fmaxf(vals[v].x, vals[v].y), fmaxf(vals[v].z, vals[v].w)));
        }
        #pragma unroll
        for (int o = 16; o > 0; o >>= 1) mx = fmaxf(mx, __shfl_xor_sync(0xffffffffu, mx, o));
        float sum = 0.f;
        #pragma unroll
        for (int v = 0; v < 8; v++) {
            vals[v].x = __expf(vals[v].x - mx);
            vals[v].y = __expf(vals[v].y - mx);
            vals[v].z = __expf(vals[v].z - mx);
            vals[v].w = __expf(vals[v].w - mx);
            sum += vals[v].x + vals[v].y + vals[v].z + vals[v].w;
        }
        #pragma unroll
        for (int o = 16; o > 0; o >>= 1) sum += __shfl_xor_sync(0xffffffffu, sum, o);
        float inv = 1.0f / sum;
        size_t pbase = ((((size_t)b * SEQ + q0 + row) * NHEAD) + hd) * SEQ;
        #pragma unroll
        for (int v = 0; v < 8; v++) {
            float4 p = make_float4(vals[v].x * inv, vals[v].y * inv,
                                   vals[v].z * inv, vals[v].w * inv);
            *(float4*)&S[row * 1024 + (v * 32 + lane) * 4] = p;
            *(float4*)&probs[pbase + (v * 32 + lane) * 4] = p;
        }
    }

    float o0[4] = {0.f, 0.f, 0.f, 0.f};
    float o1[4] = {0.f, 0.f, 0.f, 0.f};
    for (int kv0 = 0; kv0 < SEQ; kv0 += 64) {
        __syncthreads();
        {
            int kvr = tid >> 2;
            int seg = (tid & 3) * 16;
            const float* vp = &g_v[(tokbase + kv0 + kvr) * CDIM + hd * HD + seg];
            #pragma unroll
            for (int c = 0; c < 4; c++)
                *(float4*)&KV[kvr * 68 + seg + c * 4] = *(const float4*)&vp[c * 4];
        }
        __syncthreads();
        #pragma unroll 8
        for (int kk = 0; kk < 64; kk++) {
            float4 vv = *(const float4*)&KV[kk * 68 + (tx << 2)];
            float p0 = S[r0 * 1024 + kv0 + kk];
            float p1 = S[(r0 + 1) * 1024 + kv0 + kk];
            o0[0] = fmaf(p0, vv.x, o0[0]); o0[1] = fmaf(p0, vv.y, o0[1]);
            o0[2] = fmaf(p0, vv.z, o0[2]); o0[3] = fmaf(p0, vv.w, o0[3]);
            o1[0] = fmaf(p1, vv.x, o1[0]); o1[1] = fmaf(p1, vv.y, o1[1]);
            o1[2] = fmaf(p1, vv.z, o1[2]); o1[3] = fmaf(p1, vv.w, o1[3]);
        }
    }
    size_t b0 = (tokbase + q0 + r0) * CDIM + hd * HD + (tx << 2);
    size_t b1 = b0 + CDIM;
    #pragma unroll
    for (int e = 0; e < 4; e++) {
        __nv_bfloat16 h, l;
        split_bf16(o0[e], h, l);
        g_oh[b0 + e] = h; g_ol[b0 + e] = l;
        split_bf16(o1[e], h, l);
        g_oh[b1 + e] = h; g_ol[b1 + e] = l;
    }
}

// ---------------- launcher ----------------
extern "C" void kernel_launch(void* const* d_in, const int* in_sizes, int n_in,
                              void* d_out, int out_size)
{
    const float* x     = (const float*)d_in[0];
    const float* Wq    = (const float*)d_in[1];
    const float* Wk    = (const float*)d_in[2];
    const float* Wv    = (const float*)d_in[3];
    const float* Wo    = (const float*)d_in[4];
    const float* ln1_g = (const float*)d_in[5];
    const float* ln1_b = (const float*)d_in[6];
    const float* fc1_w = (const float*)d_in[7];
    const float* fc1_b = (const float*)d_in[8];
    const float* fc2_w = (const float*)d_in[9];
    const float* fc2_b = (const float*)d_in[10];
    const float* ln2_g = (const float*)d_in[11];
    const float* ln2_b = (const float*)d_in[12];

    float* out   = (float*)d_out;
    float* probs = out + (size_t)NTOK * CDIM;

    float *p_xn, *p_q, *p_k, *p_v, *p_attn, *p_yn;
    __nv_bfloat16 *p_xnh, *p_xnl, *p_ynh, *p_ynl, *p_oh, *p_ol, *p_h1h, *p_h1l;
    __nv_bfloat16 *p_wqth, *p_wqtl, *p_wkth, *p_wktl, *p_wvth, *p_wvtl;
    __nv_bfloat16 *p_woth, *p_wotl, *p_f1th, *p_f1tl, *p_f2th, *p_f2tl;
    cudaGetSymbolAddress((void**)&p_xn,   g_xn);
    cudaGetSymbolAddress((void**)&p_q,    g_q);
    cudaGetSymbolAddress((void**)&p_k,    g_k);
    cudaGetSymbolAddress((void**)&p_v,    g_v);
    cudaGetSymbolAddress((void**)&p_attn, g_attn);
    cudaGetSymbolAddress((void**)&p_yn,   g_yn);
    cudaGetSymbolAddress((void**)&p_xnh,  g_xnh);
    cudaGetSymbolAddress((void**)&p_xnl,  g_xnl);
    cudaGetSymbolAddress((void**)&p_ynh,  g_ynh);
    cudaGetSymbolAddress((void**)&p_ynl,  g_ynl);
    cudaGetSymbolAddress((void**)&p_oh,   g_oh);
    cudaGetSymbolAddress((void**)&p_ol,   g_ol);
    cudaGetSymbolAddress((void**)&p_h1h,  g_h1h);
    cudaGetSymbolAddress((void**)&p_h1l,  g_h1l);
    cudaGetSymbolAddress((void**)&p_wqth, g_wqth);
    cudaGetSymbolAddress((void**)&p_wqtl, g_wqtl);
    cudaGetSymbolAddress((void**)&p_wkth, g_wkth);
    cudaGetSymbolAddress((void**)&p_wktl, g_wktl);
    cudaGetSymbolAddress((void**)&p_wvth, g_wvth);
    cudaGetSymbolAddress((void**)&p_wvtl, g_wvtl);
    cudaGetSymbolAddress((void**)&p_woth, g_woth);
    cudaGetSymbolAddress((void**)&p_wotl, g_wotl);
    cudaGetSymbolAddress((void**)&p_f1th, g_f1th);
    cudaGetSymbolAddress((void**)&p_f1tl, g_f1tl);
    cudaGetSymbolAddress((void**)&p_f2th, g_f2th);
    cudaGetSymbolAddress((void**)&p_f2tl, g_f2tl);

    const int ATTN_SMEM = (32 * 1024 + 32 * 64 + 64 * 68) * 4;
    cudaFuncSetAttribute(attn_kernel,
                         cudaFuncAttributeMaxDynamicSharedMemorySize, ATTN_SMEM);
    cudaFuncSetAttribute(gemm_mma<false, false, false, false>,
                         cudaFuncAttributeMaxDynamicSharedMemorySize, GT_SMEM);
    cudaFuncSetAttribute(gemm_mma<false, true, false, false>,
                         cudaFuncAttributeMaxDynamicSharedMemorySize, GT_SMEM);
    cudaFuncSetAttribute(gemm_mma<true, false, true, true>,
                         cudaFuncAttributeMaxDynamicSharedMemorySize, GT_SMEM);
    cudaFuncSetAttribute(gemm_mma<true, true, false, false>,
                         cudaFuncAttributeMaxDynamicSharedMemorySize, GT_SMEM);

    // LN1 (fp32 + hi/lo)
    ln_kernel<true><<<NTOK, 128>>>(x, ln1_g, ln1_b, p_xn, p_xnh, p_xnl);

    // weight transpose + split
    transconv<<<dim3(16, 16), 256>>>(Wq, p_wqth, p_wqtl, CDIM, CDIM);
    transconv<<<dim3(16, 16), 256>>>(Wk, p_wkth, p_wktl, CDIM, CDIM);
    transconv<<<dim3(16, 16), 256>>>(Wv, p_wvth, p_wvtl, CDIM, CDIM);
    transconv<<<dim3(16, 16), 256>>>(Wo, p_woth, p_wotl, CDIM, CDIM);
    transconv<<<dim3(64, 16), 256>>>(fc1_w, p_f1th, p_f1tl, CDIM, FFDIM);
    transconv<<<dim3(16, 64), 256>>>(fc2_w, p_f2th, p_f2tl, FFDIM, CDIM);

    // QKV projections (tensor core via mma.sync)
    dim3 g512(CDIM / BN, NTOK / BM);
    gemm_mma<false, false, false, false><<<g512, 256, GT_SMEM>>>(
        p_xnh, p_xnl, p_wqth, p_wqtl, nullptr, nullptr, p_q, nullptr, nullptr,
        NTOK, CDIM, CDIM);
    gemm_mma<false, false, false, false><<<g512, 256, GT_SMEM>>>(
        p_xnh, p_xnl, p_wkth, p_wktl, nullptr, nullptr, p_k, nullptr, nullptr,
        NTOK, CDIM, CDIM);
    gemm_mma<false, false, false, false><<<g512, 256, GT_SMEM>>>(
        p_xnh, p_xnl, p_wvth, p_wvtl, nullptr, nullptr, p_v, nullptr, nullptr,
        NTOK, CDIM, CDIM);

    // attention (writes probs + O hi/lo)
    attn_kernel<<<dim3(32, NHEAD, NBATCH), 256, ATTN_SMEM>>>(probs);

    // attn_out = O @ Wo + xn
    gemm_mma<false, true, false, false><<<g512, 256, GT_SMEM>>>(
        p_oh, p_ol, p_woth, p_wotl, nullptr, p_xn, p_attn, nullptr, nullptr,
        NTOK, CDIM, CDIM);

    // LN2 (fp32 + hi/lo)
    ln_kernel<true><<<NTOK, 128>>>(p_attn, ln2_g, ln2_b, p_yn, p_ynh, p_ynl);

    // h1 = relu(yn @ fc1 + b1) -> bf16 hi/lo
    dim3 gff(FFDIM / BN, NTOK / BM);
    gemm_mma<true, false, true, true><<<gff, 256, GT_SMEM>>>(
        p_ynh, p_ynl, p_f1th, p_f1tl, fc1_b, nullptr, nullptr, p_h1h, p_h1l,
        NTOK, FFDIM, CDIM);

    // out = h1 @ fc2 + b2 + yn
    gemm_mma<true, true, false, false><<<g512, 256, GT_SMEM>>>(
        p_h1h, p_h1l, p_f2th, p_f2tl, fc2_b, p_yn, out, nullptr, nullptr,
        NTOK, CDIM, FFDIM);
}

// round 7
// speedup vs baseline: 2.6249x; 1.7041x over previous
#include <cuda_runtime.h>
#include <cuda_bf16.h>
#include <math.h>
#include <stdint.h>

// ---------------- problem constants ----------------
#define NTOK   8192
#define CDIM   512
#define FFDIM  2048
#define NHEAD  8
#define HD     64
#define SEQ    1024
#define NBATCH 8

// ---------------- scratch ----------------
__device__ float g_xn  [NTOK * CDIM];
__device__ float g_attn[NTOK * CDIM];
__device__ float g_yn  [NTOK * CDIM];

__device__ __nv_bfloat16 g_xnh[NTOK * CDIM], g_xnl[NTOK * CDIM];
__device__ __nv_bfloat16 g_ynh[NTOK * CDIM], g_ynl[NTOK * CDIM];
__device__ __nv_bfloat16 g_qh [NTOK * CDIM], g_ql [NTOK * CDIM];
__device__ __nv_bfloat16 g_kh [NTOK * CDIM], g_kl [NTOK * CDIM];
__device__ __nv_bfloat16 g_vth[NTOK * CDIM], g_vtl[NTOK * CDIM];  // [b*8+h][d][kv]
__device__ __nv_bfloat16 g_oh [NTOK * CDIM], g_ol [NTOK * CDIM];
__device__ __nv_bfloat16 g_h1h[NTOK * FFDIM], g_h1l[NTOK * FFDIM];

__device__ __nv_bfloat16 g_wqth[CDIM * CDIM], g_wqtl[CDIM * CDIM];
__device__ __nv_bfloat16 g_wkth[CDIM * CDIM], g_wktl[CDIM * CDIM];
__device__ __nv_bfloat16 g_wvth[CDIM * CDIM], g_wvtl[CDIM * CDIM];
__device__ __nv_bfloat16 g_woth[CDIM * CDIM], g_wotl[CDIM * CDIM];
__device__ __nv_bfloat16 g_f1th[CDIM * FFDIM], g_f1tl[CDIM * FFDIM];
__device__ __nv_bfloat16 g_f2th[FFDIM * CDIM], g_f2tl[FFDIM * CDIM];

// ---------------- helpers ----------------
__device__ __forceinline__ void split_bf16(float x, __nv_bfloat16& h, __nv_bfloat16& l) {
    h = __float2bfloat16(x);
    l = __float2bfloat16(x - __bfloat162float(h));
}
__device__ __forceinline__ uint32_t smem_u32(const void* p) {
    uint32_t a;
    asm("{ .reg .u64 t; cvta.to.shared.u64 t, %1; cvt.u32.u64 %0, t; }" : "=r"(a) : "l"(p));
    return a;
}
__device__ __forceinline__ void cpa16(uint32_t s, const void* g) {
    asm volatile("cp.async.cg.shared.global [%0], [%1], 16;" :: "r"(s), "l"(g) : "memory");
}
#define CP_COMMIT() asm volatile("cp.async.commit_group;" ::: "memory")

__device__ __forceinline__ void mma16816(float* c, const uint32_t* a, const uint32_t* b) {
    asm volatile("mma.sync.aligned.m16n8k16.row.col.f32.bf16.bf16.f32 "
        "{%0,%1,%2,%3}, {%4,%5,%6,%7}, {%8,%9}, {%0,%1,%2,%3};"
        : "+f"(c[0]), "+f"(c[1]), "+f"(c[2]), "+f"(c[3])
        : "r"(a[0]), "r"(a[1]), "r"(a[2]), "r"(a[3]), "r"(b[0]), "r"(b[1]));
}

// ---------------- LayerNorm (fp32 out + bf16 hi/lo) ----------------
__global__ __launch_bounds__(128) void ln_kernel(
    const float* __restrict__ in, const float* __restrict__ gam,
    const float* __restrict__ bet, float* __restrict__ out,
    __nv_bfloat16* __restrict__ oh, __nv_bfloat16* __restrict__ ol)
{
    const int row = blockIdx.x;
    const int t = threadIdx.x;
    const float4* x4 = (const float4*)(in + (size_t)row * CDIM);
    float4 v = x4[t];
    float s  = v.x + v.y + v.z + v.w;
    float ss = fmaf(v.x, v.x, fmaf(v.y, v.y, fmaf(v.z, v.z, v.w * v.w)));
    #pragma unroll
    for (int o = 16; o > 0; o >>= 1) {
        s  += __shfl_xor_sync(0xffffffffu, s,  o);
        ss += __shfl_xor_sync(0xffffffffu, ss, o);
    }
    __shared__ float sh[4], shh[4];
    const int wid = t >> 5, lane = t & 31;
    if (lane == 0) { sh[wid] = s; shh[wid] = ss; }
    __syncthreads();
    float tot  = sh[0] + sh[1] + sh[2] + sh[3];
    float tot2 = shh[0] + shh[1] + shh[2] + shh[3];
    const float mean = tot * (1.0f / CDIM);
    const float var  = tot2 * (1.0f / CDIM) - mean * mean;
    const float r    = rsqrtf(var + 1e-5f);
    float4 g = ((const float4*)gam)[t];
    float4 b = ((const float4*)bet)[t];
    float o4[4];
    o4[0] = (v.x - mean) * r * g.x + b.x;
    o4[1] = (v.y - mean) * r * g.y + b.y;
    o4[2] = (v.z - mean) * r * g.z + b.z;
    o4[3] = (v.w - mean) * r * g.w + b.w;
    ((float4*)(out + (size_t)row * CDIM))[t] = make_float4(o4[0], o4[1], o4[2], o4[3]);
    size_t base = (size_t)row * CDIM + t * 4;
    #pragma unroll
    for (int e = 0; e < 4; e++) {
        __nv_bfloat16 h, l;
        split_bf16(o4[e], h, l);
        oh[base + e] = h; ol[base + e] = l;
    }
}

// ---------------- weight transpose + hi/lo split (optional scale) ---------
__global__ __launch_bounds__(256) void transconv(
    const float* __restrict__ W, __nv_bfloat16* __restrict__ Th,
    __nv_bfloat16* __restrict__ Tl, int K, int N, float scale)
{
    __shared__ float t[32][33];
    const int n0 = blockIdx.x * 32, k0 = blockIdx.y * 32;
    const int tx = threadIdx.x & 31, ty = threadIdx.x >> 5;
    #pragma unroll
    for (int i = 0; i < 4; i++)
        t[ty + i * 8][tx] = W[(size_t)(k0 + ty + i * 8) * N + n0 + tx];
    __syncthreads();
    #pragma unroll
    for (int i = 0; i < 4; i++) {
        int r = ty + i * 8;
        float v = t[tx][r] * scale;
        __nv_bfloat16 h, l;
        split_bf16(v, h, l);
        Th[(size_t)(n0 + r) * K + k0 + tx] = h;
        Tl[(size_t)(n0 + r) * K + k0 + tx] = l;
    }
}

// ---------------- mma.sync split-bf16 GEMM ----------------
#define BM 128
#define BN 128
#define KC 32
#define ROWB 80
#define MAT_BYTES (128 * ROWB)
#define AH_OFF 0
#define AL_OFF MAT_BYTES
#define BH_OFF (2 * MAT_BYTES)
#define BL_OFF (3 * MAT_BYTES)
#define STAGE_BYTES (4 * MAT_BYTES)
#define GT_SMEM (2 * STAGE_BYTES)

template <bool BIAS, bool RES, bool RELU, bool OUTBF, bool OUTT>
__global__ __launch_bounds__(256, 2) void gemm_mma(
    const __nv_bfloat16* __restrict__ Ah, const __nv_bfloat16* __restrict__ Al,
    const __nv_bfloat16* __restrict__ Bh, const __nv_bfloat16* __restrict__ Bl,
    const float* __restrict__ bias, const float* __restrict__ res,
    float* __restrict__ Cf, __nv_bfloat16* __restrict__ Ch,
    __nv_bfloat16* __restrict__ Cl, int M, int N, int K)
{
    extern __shared__ char sm[];
    const uint32_t sbase = smem_u32(sm);
    const int tid  = threadIdx.x;
    const int lane = tid & 31;
    const int warp = tid >> 5;
    const int wm0  = (warp & 3) * 32;
    const int wn0  = (warp >> 2) * 64;
    const int g    = lane >> 2;
    const int tig  = lane & 3;
    const int bm0  = blockIdx.y * BM;
    const int bn0  = blockIdx.x * BN;

    float acc[2][8][4];
    #pragma unroll
    for (int i = 0; i < 2; i++)
        #pragma unroll
        for (int j = 0; j < 8; j++)
            #pragma unroll
            for (int e = 0; e < 4; e++) acc[i][j][e] = 0.0f;

    const __nv_bfloat16* gsrc[4] = {Ah, Al, Bh, Bl};

    auto load_stage = [&](int kt, int buf) {
        const uint32_t st = sbase + buf * STAGE_BYTES;
        #pragma unroll
        for (int i = 0; i < 8; i++) {
            int idx = tid + i * 256;
            int mat = idx >> 9;
            int rix = idx & 511;
            int r   = rix >> 2;
            int cb  = (rix & 3) * 16;
            int grow = (mat < 2) ? (bm0 + r) : (bn0 + r);
            const char* src = (const char*)(gsrc[mat] + (size_t)grow * K + kt) + cb;
            cpa16(st + mat * MAT_BYTES + r * ROWB + cb, src);
        }
        CP_COMMIT();
    };

    const int S = K / KC;
    load_stage(0, 0);
    load_stage(KC, 1);

    for (int s = 0; s < S; s++) {
        if (s + 1 < S) asm volatile("cp.async.wait_group 1;" ::: "memory");
        else           asm volatile("cp.async.wait_group 0;" ::: "memory");
        __syncthreads();

        const char* sb = sm + (s & 1) * STAGE_BYTES;
        #pragma unroll
        for (int kk = 0; kk < 2; kk++) {
            const int c0 = (kk * 16 + 2 * tig) * 2;
            uint32_t afr[2][2][4];
            #pragma unroll
            for (int am = 0; am < 2; am++) {
                const char* rowH = sb + AH_OFF + (wm0 + am * 16 + g) * ROWB;
                const char* rowL = sb + AL_OFF + (wm0 + am * 16 + g) * ROWB;
                afr[am][0][0] = *(const uint32_t*)(rowH + c0);
                afr[am][0][1] = *(const uint32_t*)(rowH + 8 * ROWB + c0);
                afr[am][0][2] = *(const uint32_t*)(rowH + c0 + 16);
                afr[am][0][3] = *(const uint32_t*)(rowH + 8 * ROWB + c0 + 16);
                afr[am][1][0] = *(const uint32_t*)(rowL + c0);
                afr[am][1][1] = *(const uint32_t*)(rowL + 8 * ROWB + c0);
                afr[am][1][2] = *(const uint32_t*)(rowL + c0 + 16);
                afr[am][1][3] = *(const uint32_t*)(rowL + 8 * ROWB + c0 + 16);
            }
            #pragma unroll
            for (int bn = 0; bn < 8; bn++) {
                const char* rH = sb + BH_OFF + (wn0 + bn * 8 + g) * ROWB;
                const char* rL = sb + BL_OFF + (wn0 + bn * 8 + g) * ROWB;
                uint32_t bh[2] = {*(const uint32_t*)(rH + c0),
                                  *(const uint32_t*)(rH + c0 + 16)};
                uint32_t bl[2] = {*(const uint32_t*)(rL + c0),
                                  *(const uint32_t*)(rL + c0 + 16)};
                mma16816(acc[0][bn], afr[0][0], bh);
                mma16816(acc[0][bn], afr[0][1], bh);
                mma16816(acc[0][bn], afr[0][0], bl);
                mma16816(acc[1][bn], afr[1][0], bh);
                mma16816(acc[1][bn], afr[1][1], bh);
                mma16816(acc[1][bn], afr[1][0], bl);
            }
        }
        __syncthreads();
        if (s + 2 < S) load_stage((s + 2) * KC, s & 1);
    }

    // epilogue
    #pragma unroll
    for (int am = 0; am < 2; am++) {
        #pragma unroll
        for (int bn = 0; bn < 8; bn++) {
            const int row = bm0 + wm0 + am * 16 + g;
            const int col = bn0 + wn0 + bn * 8 + 2 * tig;
            float* c = acc[am][bn];
            #pragma unroll
            for (int h = 0; h < 2; h++) {
                const int r = row + h * 8;
                float v0 = c[h * 2 + 0];
                float v1 = c[h * 2 + 1];
                if (BIAS) { v0 += bias[col]; v1 += bias[col + 1]; }
                if (RES) {
                    float2 rr = *(const float2*)&res[(size_t)r * N + col];
                    v0 += rr.x; v1 += rr.y;
                }
                if (RELU) { v0 = fmaxf(v0, 0.f); v1 = fmaxf(v1, 0.f); }
                if (OUTT) {
                    // transposed bf16 hi/lo: [b*8+head][d][kv]
                    int bb = r >> 10, kv = r & 1023;
                    int head = col >> 6, d = col & 63;
                    size_t tb = ((size_t)(bb * 8 + head) * 64 + d) * 1024 + kv;
                    __nv_bfloat16 h0, l0, h1, l1;
                    split_bf16(v0, h0, l0);
                    split_bf16(v1, h1, l1);
                    Ch[tb] = h0;        Cl[tb] = l0;
                    Ch[tb + 1024] = h1; Cl[tb + 1024] = l1;
                } else if (OUTBF) {
                    __nv_bfloat16 h0, l0, h1, l1;
                    split_bf16(v0, h0, l0);
                    split_bf16(v1, h1, l1);
                    __nv_bfloat162 hp; hp.x = h0; hp.y = h1;
                    __nv_bfloat162 lp; lp.x = l0; lp.y = l1;
                    *(__nv_bfloat162*)(Ch + (size_t)r * N + col) = hp;
                    *(__nv_bfloat162*)(Cl + (size_t)r * N + col) = lp;
                } else {
                    *(float2*)&Cf[(size_t)r * N + col] = make_float2(v0, v1);
                }
            }
        }
    }
}

// ---------------- mma attention ----------------
// block = (32 q rows, head, batch); 8 warps.
#define S_STRIDE 1028
#define S_BYTES (32 * S_STRIDE * 4)          // 131584
#define Q_OFF   S_BYTES
#define QROW    144                          // 128B data + 16B pad
#define Q_BYTES (2 * 32 * QROW)              // 9216
#define KV_OFF  (Q_OFF + Q_BYTES)
#define KROW 144
#define KMAT (128 * KROW)
#define KSTG (2 * KMAT)                      // 36864
#define VROW 272
#define VMAT (64 * VROW)
#define VSTG (2 * VMAT)                      // 34816
#define ATTN_SMEM (KV_OFF + 2 * KSTG)        // 214528

__global__ __launch_bounds__(256, 1) void attn_mma(float* __restrict__ probs)
{
    extern __shared__ char sm[];
    float* S = (float*)sm;
    uint32_t* Su = (uint32_t*)sm;
    const uint32_t sb = smem_u32(sm);
    const int tid = threadIdx.x, lane = tid & 31, warp = tid >> 5;
    const int g = lane >> 2, tig = lane & 3;
    const int qb = blockIdx.x, hd = blockIdx.y, b = blockIdx.z;
    const int q0 = qb * 32;
    const size_t tokbase = (size_t)b * SEQ;

    // Q tile (hi/lo) -> smem
    #pragma unroll
    for (int i = 0; i < 2; i++) {
        int idx = tid + i * 256;
        int mat = idx >> 8;
        int rix = idx & 255;
        int r = rix >> 3, v = (rix & 7) * 16;
        const __nv_bfloat16* src = mat ? g_ql : g_qh;
        const char* sp = (const char*)(src + (tokbase + q0 + r) * CDIM + hd * HD) + v;
        *(uint4*)(sm + Q_OFF + mat * 32 * QROW + r * QROW + v) = *(const uint4*)sp;
    }

    auto load_k = [&](int kv0, int buf) {
        const uint32_t st = sb + KV_OFF + buf * KSTG;
        #pragma unroll
        for (int i = 0; i < 8; i++) {
            int idx = tid + i * 256;
            int mat = idx >> 10;
            int rix = idx & 1023;
            int r = rix >> 3, v = (rix & 7) * 16;
            const __nv_bfloat16* src = mat ? g_kl : g_kh;
            const char* sp = (const char*)(src + (tokbase + kv0 + r) * CDIM + hd * HD) + v;
            cpa16(st + mat * KMAT + r * KROW + v, sp);
        }
        CP_COMMIT();
    };
    auto load_v = [&](int kv0, int buf) {
        const uint32_t st = sb + KV_OFF + buf * VSTG;
        #pragma unroll
        for (int i = 0; i < 8; i++) {
            int idx = tid + i * 256;
            int mat = idx >> 10;
            int rix = idx & 1023;
            int r = rix >> 4, v = (rix & 15) * 16;
            const __nv_bfloat16* src = mat ? g_vtl : g_vth;
            const char* sp = (const char*)(src + ((size_t)(b * 8 + hd) * 64 + r) * SEQ + kv0) + v;
            cpa16(st + mat * VMAT + r * VROW + v, sp);
        }
        CP_COMMIT();
    };

    load_k(0, 0);
    load_k(128, 1);

    // ---- scores S = Q @ K^T (Wq pre-scaled by 1/8) ----
    for (int ch = 0; ch < 8; ch++) {
        if (ch < 7) asm volatile("cp.async.wait_group 1;" ::: "memory");
        else        asm volatile("cp.async.wait_group 0;" ::: "memory");
        __syncthreads();
        const char* kb = sm + KV_OFF + (ch & 1) * KSTG;
        float c[2][2][4];
        #pragma unroll
        for (int am = 0; am < 2; am++)
            #pragma unroll
            for (int nt = 0; nt < 2; nt++)
                #pragma unroll
                for (int e = 0; e < 4; e++) c[am][nt][e] = 0.0f;

        #pragma unroll
        for (int kk = 0; kk < 4; kk++) {
            const int c0 = (kk * 16 + 2 * tig) * 2;
            uint32_t aH[2][4], aL[2][4];
            #pragma unroll
            for (int am = 0; am < 2; am++) {
                const char* qh = sm + Q_OFF + (am * 16 + g) * QROW;
                const char* ql = qh + 32 * QROW;
                aH[am][0] = *(const uint32_t*)(qh + c0);
                aH[am][1] = *(const uint32_t*)(qh + 8 * QROW + c0);
                aH[am][2] = *(const uint32_t*)(qh + c0 + 16);
                aH[am][3] = *(const uint32_t*)(qh + 8 * QROW + c0 + 16);
                aL[am][0] = *(const uint32_t*)(ql + c0);
                aL[am][1] = *(const uint32_t*)(ql + 8 * QROW + c0);
                aL[am][2] = *(const uint32_t*)(ql + c0 + 16);
                aL[am][3] = *(const uint32_t*)(ql + 8 * QROW + c0 + 16);
            }
            #pragma unroll
            for (int nt = 0; nt < 2; nt++) {
                const char* kh = kb + (warp * 16 + nt * 8 + g) * KROW;
                const char* kl = kh + KMAT;
                uint32_t bh[2] = {*(const uint32_t*)(kh + c0),
                                  *(const uint32_t*)(kh + c0 + 16)};
                uint32_t bl[2] = {*(const uint32_t*)(kl + c0),
                                  *(const uint32_t*)(kl + c0 + 16)};
                #pragma unroll
                for (int am = 0; am < 2; am++) {
                    mma16816(c[am][nt], aH[am], bh);
                    mma16816(c[am][nt], aL[am], bh);
                    mma16816(c[am][nt], aH[am], bl);
                }
            }
        }
        __syncthreads();
        if (ch + 2 < 8) load_k((ch + 2) * 128, ch & 1);
        #pragma unroll
        for (int am = 0; am < 2; am++)
            #pragma unroll
            for (int nt = 0; nt < 2; nt++) {
                int row = am * 16 + g;
                int col = ch * 128 + warp * 16 + nt * 8 + 2 * tig;
                *(float2*)&S[row * S_STRIDE + col] =
                    make_float2(c[am][nt][0], c[am][nt][1]);
                *(float2*)&S[(row + 8) * S_STRIDE + col] =
                    make_float2(c[am][nt][2], c[am][nt][3]);
            }
    }

    // preload V chunks into KV region (all K reads completed at the final
    // in-loop __syncthreads())
    load_v(0, 0);
    load_v(128, 1);
    __syncthreads();   // S stores visible to all

    // ---- softmax; write probs; repack P as bf16 hi|lo in S ----
    #pragma unroll
    for (int rr = 0; rr < 4; rr++) {
        int row = warp * 4 + rr;
        float4 vals[8];
        float mx = -1e30f;
        #pragma unroll
        for (int v = 0; v < 8; v++) {
            vals[v] = *(float4*)&S[row * S_STRIDE + (v * 32 + lane) * 4];
            mx = fmaxf(mx, fmaxf(fmaxf(vals[v].x, vals[v].y), fmaxf(vals[v].z, vals[v].w)));
        }
        #pragma unroll
        for (int o = 16; o > 0; o >>= 1) mx = fmaxf(mx, __shfl_xor_sync(0xffffffffu, mx, o));
        float sum = 0.f;
        #pragma unroll
        for (int v = 0; v < 8; v++) {
            vals[v].x = __expf(vals[v].x - mx);
            vals[v].y = __expf(vals[v].y - mx);
            vals[v].z = __expf(vals[v].z - mx);
            vals[v].w = __expf(vals[v].w - mx);
            sum += vals[v].x + vals[v].y + vals[v].z + vals[v].w;
        }
        #pragma unroll
        for (int o = 16; o > 0; o >>= 1) sum += __shfl_xor_sync(0xffffffffu, sum, o);
        float inv = 1.0f / sum;
        size_t pbase = ((tokbase + q0 + row) * NHEAD + hd) * SEQ;
        #pragma unroll
        for (int v = 0; v < 8; v++) {
            float p[4] = {vals[v].x * inv, vals[v].y * inv, vals[v].z * inv, vals[v].w * inv};
            *(float4*)&probs[pbase + (v * 32 + lane) * 4] =
                make_float4(p[0], p[1], p[2], p[3]);
            uint32_t w[4];
            #pragma unroll
            for (int e = 0; e < 4; e++) {
                __nv_bfloat16 h, l;
                split_bf16(p[e], h, l);
                w[e] = (uint32_t)__bfloat16_as_ushort(h) |
                       ((uint32_t)__bfloat16_as_ushort(l) << 16);
            }
            *(uint4*)&Su[row * S_STRIDE + (v * 32 + lane) * 4] =
                make_uint4(w[0], w[1], w[2], w[3]);
        }
    }
    __syncthreads();

    // ---- O = P @ V ----
    float o[2][4];
    #pragma unroll
    for (int am = 0; am < 2; am++)
        #pragma unroll
        for (int e = 0; e < 4; e++) o[am][e] = 0.0f;

    for (int ch = 0; ch < 8; ch++) {
        if (ch < 7) asm volatile("cp.async.wait_group 1;" ::: "memory");
        else        asm volatile("cp.async.wait_group 0;" ::: "memory");
        __syncthreads();
        const char* vb = sm + KV_OFF + (ch & 1) * VSTG;
        #pragma unroll
        for (int kk = 0; kk < 8; kk++) {
            const int e0 = ch * 128 + kk * 16 + 2 * tig;
            const int c0 = (kk * 16 + 2 * tig) * 2;
            const char* vh = vb + (warp * 8 + g) * VROW;
            const char* vl = vh + VMAT;
            uint32_t bh[2] = {*(const uint32_t*)(vh + c0),
                              *(const uint32_t*)(vh + c0 + 16)};
            uint32_t bl[2] = {*(const uint32_t*)(vl + c0),
                              *(const uint32_t*)(vl + c0 + 16)};
            #pragma unroll
            for (int am = 0; am < 2; am++) {
                int r = am * 16 + g;
                uint32_t w0 = Su[r * S_STRIDE + e0];
                uint32_t w1 = Su[r * S_STRIDE + e0 + 1];
                uint32_t w2 = Su[r * S_STRIDE + e0 + 8];
                uint32_t w3 = Su[r * S_STRIDE + e0 + 9];
                uint32_t w4 = Su[(r + 8) * S_STRIDE + e0];
                uint32_t w5 = Su[(r + 8) * S_STRIDE + e0 + 1];
                uint32_t w6 = Su[(r + 8) * S_STRIDE + e0 + 8];
                uint32_t w7 = Su[(r + 8) * S_STRIDE + e0 + 9];
                uint32_t aH[4] = {__byte_perm(w0, w1, 0x5410), __byte_perm(w4, w5, 0x5410),
                                  __byte_perm(w2, w3, 0x5410), __byte_perm(w6, w7, 0x5410)};
                uint32_t aL[4] = {__byte_perm(w0, w1, 0x7632), __byte_perm(w4, w5, 0x7632),
                                  __byte_perm(w2, w3, 0x7632), __byte_perm(w6, w7, 0x7632)};
                mma16816(o[am], aH, bh);
                mma16816(o[am], aL, bh);
                mma16816(o[am], aH, bl);
            }
        }
        __syncthreads();
        if (ch + 2 < 8) load_v((ch + 2) * 128, ch & 1);
    }

    // ---- O epilogue: bf16 hi/lo for Wo gemm ----
    #pragma unroll
    for (int am = 0; am < 2; am++) {
        int row = q0 + am * 16 + g;
        int col = hd * HD + warp * 8 + 2 * tig;
        #pragma unroll
        for (int h = 0; h < 2; h++) {
            size_t off = (tokbase + row + h * 8) * CDIM + col;
            __nv_bfloat16 h0, l0, h1, l1;
            split_bf16(o[am][h * 2 + 0], h0, l0);
            split_bf16(o[am][h * 2 + 1], h1, l1);
            __nv_bfloat162 hp; hp.x = h0; hp.y = h1;
            __nv_bfloat162 lp; lp.x = l0; lp.y = l1;
            *(__nv_bfloat162*)(g_oh + off) = hp;
            *(__nv_bfloat162*)(g_ol + off) = lp;
        }
    }
}

// ---------------- launcher ----------------
extern "C" void kernel_launch(void* const* d_in, const int* in_sizes, int n_in,
                              void* d_out, int out_size)
{
    const float* x     = (const float*)d_in[0];
    const float* Wq    = (const float*)d_in[1];
    const float* Wk    = (const float*)d_in[2];
    const float* Wv    = (const float*)d_in[3];
    const float* Wo    = (const float*)d_in[4];
    const float* ln1_g = (const float*)d_in[5];
    const float* ln1_b = (const float*)d_in[6];
    const float* fc1_w = (const float*)d_in[7];
    const float* fc1_b = (const float*)d_in[8];
    const float* fc2_w = (const float*)d_in[9];
    const float* fc2_b = (const float*)d_in[10];
    const float* ln2_g = (const float*)d_in[11];
    const float* ln2_b = (const float*)d_in[12];

    float* out   = (float*)d_out;
    float* probs = out + (size_t)NTOK * CDIM;

    float *p_xn, *p_attn, *p_yn;
    __nv_bfloat16 *p_xnh, *p_xnl, *p_ynh, *p_ynl, *p_oh, *p_ol, *p_h1h, *p_h1l;
    __nv_bfloat16 *p_qh, *p_ql, *p_kh, *p_kl, *p_vth, *p_vtl;
    __nv_bfloat16 *p_wqth, *p_wqtl, *p_wkth, *p_wktl, *p_wvth, *p_wvtl;
    __nv_bfloat16 *p_woth, *p_wotl, *p_f1th, *p_f1tl, *p_f2th, *p_f2tl;
    cudaGetSymbolAddress((void**)&p_xn,   g_xn);
    cudaGetSymbolAddress((void**)&p_attn, g_attn);
    cudaGetSymbolAddress((void**)&p_yn,   g_yn);
    cudaGetSymbolAddress((void**)&p_xnh,  g_xnh);
    cudaGetSymbolAddress((void**)&p_xnl,  g_xnl);
    cudaGetSymbolAddress((void**)&p_ynh,  g_ynh);
    cudaGetSymbolAddress((void**)&p_ynl,  g_ynl);
    cudaGetSymbolAddress((void**)&p_oh,   g_oh);
    cudaGetSymbolAddress((void**)&p_ol,   g_ol);
    cudaGetSymbolAddress((void**)&p_h1h,  g_h1h);
    cudaGetSymbolAddress((void**)&p_h1l,  g_h1l);
    cudaGetSymbolAddress((void**)&p_qh,   g_qh);
    cudaGetSymbolAddress((void**)&p_ql,   g_ql);
    cudaGetSymbolAddress((void**)&p_kh,   g_kh);
    cudaGetSymbolAddress((void**)&p_kl,   g_kl);
    cudaGetSymbolAddress((void**)&p_vth,  g_vth);
    cudaGetSymbolAddress((void**)&p_vtl,  g_vtl);
    cudaGetSymbolAddress((void**)&p_wqth, g_wqth);
    cudaGetSymbolAddress((void**)&p_wqtl, g_wqtl);
    cudaGetSymbolAddress((void**)&p_wkth, g_wkth);
    cudaGetSymbolAddress((void**)&p_wktl, g_wktl);
    cudaGetSymbolAddress((void**)&p_wvth, g_wvth);
    cudaGetSymbolAddress((void**)&p_wvtl, g_wvtl);
    cudaGetSymbolAddress((void**)&p_woth, g_woth);
    cudaGetSymbolAddress((void**)&p_wotl, g_wotl);
    cudaGetSymbolAddress((void**)&p_f1th, g_f1th);
    cudaGetSymbolAddress((void**)&p_f1tl, g_f1tl);
    cudaGetSymbolAddress((void**)&p_f2th, g_f2th);
    cudaGetSymbolAddress((void**)&p_f2tl, g_f2tl);

    cudaFuncSetAttribute(attn_mma,
                         cudaFuncAttributeMaxDynamicSharedMemorySize, ATTN_SMEM);
    cudaFuncSetAttribute(gemm_mma<false, false, false, true, false>,
                         cudaFuncAttributeMaxDynamicSharedMemorySize, GT_SMEM);
    cudaFuncSetAttribute(gemm_mma<false, false, false, false, true>,
                         cudaFuncAttributeMaxDynamicSharedMemorySize, GT_SMEM);
    cudaFuncSetAttribute(gemm_mma<false, true, false, false, false>,
                         cudaFuncAttributeMaxDynamicSharedMemorySize, GT_SMEM);
    cudaFuncSetAttribute(gemm_mma<true, false, true, true, false>,
                         cudaFuncAttributeMaxDynamicSharedMemorySize, GT_SMEM);
    cudaFuncSetAttribute(gemm_mma<true, true, false, false, false>,
                         cudaFuncAttributeMaxDynamicSharedMemorySize, GT_SMEM);

    // LN1
    ln_kernel<<<NTOK, 128>>>(x, ln1_g, ln1_b, p_xn, p_xnh, p_xnl);

    // weight transpose + split (Wq folded with 1/8 score scale)
    transconv<<<dim3(16, 16), 256>>>(Wq, p_wqth, p_wqtl, CDIM, CDIM, 0.125f);
    transconv<<<dim3(16, 16), 256>>>(Wk, p_wkth, p_wktl, CDIM, CDIM, 1.0f);
    transconv<<<dim3(16, 16), 256>>>(Wv, p_wvth, p_wvtl, CDIM, CDIM, 1.0f);
    transconv<<<dim3(16, 16), 256>>>(Wo, p_woth, p_wotl, CDIM, CDIM, 1.0f);
    transconv<<<dim3(64, 16), 256>>>(fc1_w, p_f1th, p_f1tl, CDIM, FFDIM, 1.0f);
    transconv<<<dim3(16, 64), 256>>>(fc2_w, p_f2th, p_f2tl, FFDIM, CDIM, 1.0f);

    dim3 g512(CDIM / BN, NTOK / BM);
    // Q, K -> bf16 hi/lo
    gemm_mma<false, false, false, true, false><<<g512, 256, GT_SMEM>>>(
        p_xnh, p_xnl, p_wqth, p_wqtl, nullptr, nullptr, nullptr, p_qh, p_ql,
        NTOK, CDIM, CDIM);
    gemm_mma<false, false, false, true, false><<<g512, 256, GT_SMEM>>>(
        p_xnh, p_xnl, p_wkth, p_wktl, nullptr, nullptr, nullptr, p_kh, p_kl,
        NTOK, CDIM, CDIM);
    // V -> transposed bf16 hi/lo [b*8+h][d][kv]
    gemm_mma<false, false, false, false, true><<<g512, 256, GT_SMEM>>>(
        p_xnh, p_xnl, p_wvth, p_wvtl, nullptr, nullptr, nullptr, p_vth, p_vtl,
        NTOK, CDIM, CDIM);

    // attention (mma): probs + O hi/lo
    attn_mma<<<dim3(32, NHEAD, NBATCH), 256, ATTN_SMEM>>>(probs);

    // attn_out = O @ Wo + xn
    gemm_mma<false, true, false, false, false><<<g512, 256, GT_SMEM>>>(
        p_oh, p_ol, p_woth, p_wotl, nullptr, p_xn, p_attn, nullptr, nullptr,
        NTOK, CDIM, CDIM);

    // LN2
    ln_kernel<<<NTOK, 128>>>(p_attn, ln2_g, ln2_b, p_yn, p_ynh, p_ynl);

    // h1 = relu(yn @ fc1 + b1) -> bf16 hi/lo
    dim3 gff(FFDIM / BN, NTOK / BM);
    gemm_mma<true, false, true, true, false><<<gff, 256, GT_SMEM>>>(
        p_ynh, p_ynl, p_f1th, p_f1tl, fc1_b, nullptr, nullptr, p_h1h, p_h1l,
        NTOK, FFDIM, CDIM);

    // out = h1 @ fc2 + b2 + yn
    gemm_mma<true, true, false, false, false><<<g512, 256, GT_SMEM>>>(
        p_h1h, p_h1l, p_f2th, p_f2tl, fc2_b, p_yn, out, nullptr, nullptr,
        NTOK, CDIM, FFDIM);
}

// round 8
// speedup vs baseline: 2.8628x; 1.0906x over previous
#include <cuda_runtime.h>
#include <cuda_bf16.h>
#include <math.h>
#include <stdint.h>

// ---------------- problem constants ----------------
#define NTOK   8192
#define CDIM   512
#define FFDIM  2048
#define NHEAD  8
#define HD     64
#define SEQ    1024
#define NBATCH 8

// ---------------- scratch ----------------
__device__ float g_xn  [NTOK * CDIM];
__device__ float g_attn[NTOK * CDIM];
__device__ float g_yn  [NTOK * CDIM];

__device__ __nv_bfloat16 g_xnh[NTOK * CDIM], g_xnl[NTOK * CDIM];
__device__ __nv_bfloat16 g_ynh[NTOK * CDIM], g_ynl[NTOK * CDIM];
__device__ __nv_bfloat16 g_qh [NTOK * CDIM], g_ql [NTOK * CDIM];
__device__ __nv_bfloat16 g_kh [NTOK * CDIM], g_kl [NTOK * CDIM];
__device__ __nv_bfloat16 g_vth[NTOK * CDIM], g_vtl[NTOK * CDIM];  // [b*8+h][d][kv]
__device__ __nv_bfloat16 g_oh [NTOK * CDIM], g_ol [NTOK * CDIM];
__device__ __nv_bfloat16 g_h1h[NTOK * FFDIM], g_h1l[NTOK * FFDIM];

__device__ __nv_bfloat16 g_wqth[CDIM * CDIM], g_wqtl[CDIM * CDIM];
__device__ __nv_bfloat16 g_wkth[CDIM * CDIM], g_wktl[CDIM * CDIM];
__device__ __nv_bfloat16 g_wvth[CDIM * CDIM], g_wvtl[CDIM * CDIM];
__device__ __nv_bfloat16 g_woth[CDIM * CDIM], g_wotl[CDIM * CDIM];
__device__ __nv_bfloat16 g_f1th[CDIM * FFDIM], g_f1tl[CDIM * FFDIM];
__device__ __nv_bfloat16 g_f2th[FFDIM * CDIM], g_f2tl[FFDIM * CDIM];

// ---------------- helpers ----------------
__device__ __forceinline__ void split_bf16(float x, __nv_bfloat16& h, __nv_bfloat16& l) {
    h = __float2bfloat16(x);
    l = __float2bfloat16(x - __bfloat162float(h));
}
__device__ __forceinline__ uint32_t smem_u32(const void* p) {
    uint32_t a;
    asm("{ .reg .u64 t; cvta.to.shared.u64 t, %1; cvt.u32.u64 %0, t; }" : "=r"(a) : "l"(p));
    return a;
}
__device__ __forceinline__ void cpa16(uint32_t s, const void* g) {
    asm volatile("cp.async.cg.shared.global [%0], [%1], 16;" :: "r"(s), "l"(g) : "memory");
}
#define CP_COMMIT() asm volatile("cp.async.commit_group;" ::: "memory")

__device__ __forceinline__ void mma16816(float* c, const uint32_t* a, const uint32_t* b) {
    asm volatile("mma.sync.aligned.m16n8k16.row.col.f32.bf16.bf16.f32 "
        "{%0,%1,%2,%3}, {%4,%5,%6,%7}, {%8,%9}, {%0,%1,%2,%3};"
        : "+f"(c[0]), "+f"(c[1]), "+f"(c[2]), "+f"(c[3])
        : "r"(a[0]), "r"(a[1]), "r"(a[2]), "r"(a[3]), "r"(b[0]), "r"(b[1]));
}
__device__ __forceinline__ void ldm_x4(uint32_t* r, uint32_t addr) {
    asm volatile("ldmatrix.sync.aligned.m8n8.x4.shared.b16 {%0,%1,%2,%3}, [%4];"
        : "=r"(r[0]), "=r"(r[1]), "=r"(r[2]), "=r"(r[3]) : "r"(addr));
}

// ---------------- LayerNorm (fp32 out + bf16 hi/lo) ----------------
__global__ __launch_bounds__(128) void ln_kernel(
    const float* __restrict__ in, const float* __restrict__ gam,
    const float* __restrict__ bet, float* __restrict__ out,
    __nv_bfloat16* __restrict__ oh, __nv_bfloat16* __restrict__ ol)
{
    const int row = blockIdx.x;
    const int t = threadIdx.x;
    const float4* x4 = (const float4*)(in + (size_t)row * CDIM);
    float4 v = x4[t];
    float s  = v.x + v.y + v.z + v.w;
    float ss = fmaf(v.x, v.x, fmaf(v.y, v.y, fmaf(v.z, v.z, v.w * v.w)));
    #pragma unroll
    for (int o = 16; o > 0; o >>= 1) {
        s  += __shfl_xor_sync(0xffffffffu, s,  o);
        ss += __shfl_xor_sync(0xffffffffu, ss, o);
    }
    __shared__ float sh[4], shh[4];
    const int wid = t >> 5, lane = t & 31;
    if (lane == 0) { sh[wid] = s; shh[wid] = ss; }
    __syncthreads();
    float tot  = sh[0] + sh[1] + sh[2] + sh[3];
    float tot2 = shh[0] + shh[1] + shh[2] + shh[3];
    const float mean = tot * (1.0f / CDIM);
    const float var  = tot2 * (1.0f / CDIM) - mean * mean;
    const float r    = rsqrtf(var + 1e-5f);
    float4 g = ((const float4*)gam)[t];
    float4 b = ((const float4*)bet)[t];
    float o4[4];
    o4[0] = (v.x - mean) * r * g.x + b.x;
    o4[1] = (v.y - mean) * r * g.y + b.y;
    o4[2] = (v.z - mean) * r * g.z + b.z;
    o4[3] = (v.w - mean) * r * g.w + b.w;
    ((float4*)(out + (size_t)row * CDIM))[t] = make_float4(o4[0], o4[1], o4[2], o4[3]);
    size_t base = (size_t)row * CDIM + t * 4;
    #pragma unroll
    for (int e = 0; e < 4; e++) {
        __nv_bfloat16 h, l;
        split_bf16(o4[e], h, l);
        oh[base + e] = h; ol[base + e] = l;
    }
}

// ------------- all weight transposes + hi/lo split in ONE launch ----------
__global__ __launch_bounds__(256) void transconv_all(
    const float* __restrict__ Wq, const float* __restrict__ Wk,
    const float* __restrict__ Wv, const float* __restrict__ Wo,
    const float* __restrict__ F1, const float* __restrict__ F2)
{
    const int bid = blockIdx.x;
    const float* W; __nv_bfloat16 *Th, *Tl;
    int K, N, nb, idx; float scale = 1.0f;
    if (bid < 1024) {
        int which = bid >> 8; idx = bid & 255; K = 512; N = 512; nb = 16;
        if (which == 0)      { W = Wq; Th = g_wqth; Tl = g_wqtl; scale = 0.125f; }
        else if (which == 1) { W = Wk; Th = g_wkth; Tl = g_wktl; }
        else if (which == 2) { W = Wv; Th = g_wvth; Tl = g_wvtl; }
        else                 { W = Wo; Th = g_woth; Tl = g_wotl; }
    } else if (bid < 2048) {
        idx = bid - 1024; W = F1; Th = g_f1th; Tl = g_f1tl; K = 512; N = 2048; nb = 64;
    } else {
        idx = bid - 2048; W = F2; Th = g_f2th; Tl = g_f2tl; K = 2048; N = 512; nb = 16;
    }
    const int n0 = (idx % nb) * 32, k0 = (idx / nb) * 32;
    __shared__ float t[32][33];
    const int tx = threadIdx.x & 31, ty = threadIdx.x >> 5;
    #pragma unroll
    for (int i = 0; i < 4; i++)
        t[ty + i * 8][tx] = W[(size_t)(k0 + ty + i * 8) * N + n0 + tx];
    __syncthreads();
    #pragma unroll
    for (int i = 0; i < 4; i++) {
        int r = ty + i * 8;
        float v = t[tx][r] * scale;
        __nv_bfloat16 h, l;
        split_bf16(v, h, l);
        Th[(size_t)(n0 + r) * K + k0 + tx] = h;
        Tl[(size_t)(n0 + r) * K + k0 + tx] = l;
    }
}

// ---------------- mma.sync split-bf16 GEMM (ldmatrix fragments) -----------
#define BM 128
#define BN 128
#define KC 32
#define ROWB 80
#define MAT_BYTES (128 * ROWB)
#define AH_OFF 0
#define AL_OFF MAT_BYTES
#define BH_OFF (2 * MAT_BYTES)
#define BL_OFF (3 * MAT_BYTES)
#define STAGE_BYTES (4 * MAT_BYTES)
#define GT_SMEM (2 * STAGE_BYTES)

template <bool BIAS, bool RES, bool RELU, bool OUTBF, bool OUTT>
__global__ __launch_bounds__(256, 2) void gemm_mma(
    const __nv_bfloat16* __restrict__ Ah, const __nv_bfloat16* __restrict__ Al,
    const __nv_bfloat16* __restrict__ Bh, const __nv_bfloat16* __restrict__ Bl,
    const float* __restrict__ bias, const float* __restrict__ res,
    float* __restrict__ Cf, __nv_bfloat16* __restrict__ Ch,
    __nv_bfloat16* __restrict__ Cl, int M, int N, int K)
{
    extern __shared__ char sm[];
    const uint32_t sbase = smem_u32(sm);
    const int tid  = threadIdx.x;
    const int lane = tid & 31;
    const int warp = tid >> 5;
    const int wm0  = (warp & 3) * 32;
    const int wn0  = (warp >> 2) * 64;
    const int g    = lane >> 2;
    const int tig  = lane & 3;
    const int t8   = lane >> 3;       // ldmatrix tile select
    const int r8   = lane & 7;        // ldmatrix row-in-tile
    const int bm0  = blockIdx.y * BM;
    const int bn0  = blockIdx.x * BN;

    float acc[2][8][4];
    #pragma unroll
    for (int i = 0; i < 2; i++)
        #pragma unroll
        for (int j = 0; j < 8; j++)
            #pragma unroll
            for (int e = 0; e < 4; e++) acc[i][j][e] = 0.0f;

    const __nv_bfloat16* gsrc[4] = {Ah, Al, Bh, Bl};

    auto load_stage = [&](int kt, int buf) {
        const uint32_t st = sbase + buf * STAGE_BYTES;
        #pragma unroll
        for (int i = 0; i < 8; i++) {
            int idx = tid + i * 256;
            int mat = idx >> 9;
            int rix = idx & 511;
            int r   = rix >> 2;
            int cb  = (rix & 3) * 16;
            int grow = (mat < 2) ? (bm0 + r) : (bn0 + r);
            const char* src = (const char*)(gsrc[mat] + (size_t)grow * K + kt) + cb;
            cpa16(st + mat * MAT_BYTES + r * ROWB + cb, src);
        }
        CP_COMMIT();
    };

    const int S = K / KC;
    load_stage(0, 0);
    load_stage(KC, 1);

    for (int s = 0; s < S; s++) {
        if (s + 1 < S) asm volatile("cp.async.wait_group 1;" ::: "memory");
        else           asm volatile("cp.async.wait_group 0;" ::: "memory");
        __syncthreads();

        const uint32_t sb32 = sbase + (s & 1) * STAGE_BYTES;
        #pragma unroll
        for (int kk = 0; kk < 2; kk++) {
            const int kbyte = kk * 32;
            uint32_t aH[2][4], aL[2][4];
            #pragma unroll
            for (int am = 0; am < 2; am++) {
                uint32_t arow = wm0 + am * 16 + (t8 & 1) * 8 + r8;
                uint32_t acol = kbyte + (t8 >> 1) * 16;
                ldm_x4(aH[am], sb32 + AH_OFF + arow * ROWB + acol);
                ldm_x4(aL[am], sb32 + AL_OFF + arow * ROWB + acol);
            }
            #pragma unroll
            for (int bn2 = 0; bn2 < 4; bn2++) {
                uint32_t brow = wn0 + (2 * bn2 + (t8 >> 1)) * 8 + r8;
                uint32_t bcol = kbyte + (t8 & 1) * 16;
                uint32_t bh4[4], bl4[4];
                ldm_x4(bh4, sb32 + BH_OFF + brow * ROWB + bcol);
                ldm_x4(bl4, sb32 + BL_OFF + brow * ROWB + bcol);
                #pragma unroll
                for (int half = 0; half < 2; half++) {
                    const int bn = 2 * bn2 + half;
                    const uint32_t* bh = bh4 + 2 * half;
                    const uint32_t* bl = bl4 + 2 * half;
                    mma16816(acc[0][bn], aH[0], bh);
                    mma16816(acc[0][bn], aL[0], bh);
                    mma16816(acc[0][bn], aH[0], bl);
                    mma16816(acc[1][bn], aH[1], bh);
                    mma16816(acc[1][bn], aL[1], bh);
                    mma16816(acc[1][bn], aH[1], bl);
                }
            }
        }
        __syncthreads();
        if (s + 2 < S) load_stage((s + 2) * KC, s & 1);
    }

    // epilogue
    #pragma unroll
    for (int am = 0; am < 2; am++) {
        #pragma unroll
        for (int bn = 0; bn < 8; bn++) {
            const int row = bm0 + wm0 + am * 16 + g;
            const int col = bn0 + wn0 + bn * 8 + 2 * tig;
            float* c = acc[am][bn];
            #pragma unroll
            for (int h = 0; h < 2; h++) {
                const int r = row + h * 8;
                float v0 = c[h * 2 + 0];
                float v1 = c[h * 2 + 1];
                if (BIAS) { v0 += bias[col]; v1 += bias[col + 1]; }
                if (RES) {
                    float2 rr = *(const float2*)&res[(size_t)r * N + col];
                    v0 += rr.x; v1 += rr.y;
                }
                if (RELU) { v0 = fmaxf(v0, 0.f); v1 = fmaxf(v1, 0.f); }
                if (OUTT) {
                    int bb = r >> 10, kv = r & 1023;
                    int head = col >> 6, d = col & 63;
                    size_t tb = ((size_t)(bb * 8 + head) * 64 + d) * 1024 + kv;
                    __nv_bfloat16 h0, l0, h1, l1;
                    split_bf16(v0, h0, l0);
                    split_bf16(v1, h1, l1);
                    Ch[tb] = h0;        Cl[tb] = l0;
                    Ch[tb + 1024] = h1; Cl[tb + 1024] = l1;
                } else if (OUTBF) {
                    __nv_bfloat16 h0, l0, h1, l1;
                    split_bf16(v0, h0, l0);
                    split_bf16(v1, h1, l1);
                    __nv_bfloat162 hp; hp.x = h0; hp.y = h1;
                    __nv_bfloat162 lp; lp.x = l0; lp.y = l1;
                    *(__nv_bfloat162*)(Ch + (size_t)r * N + col) = hp;
                    *(__nv_bfloat162*)(Cl + (size_t)r * N + col) = lp;
                } else {
                    *(float2*)&Cf[(size_t)r * N + col] = make_float2(v0, v1);
                }
            }
        }
    }
}

// ---------------- mma attention (ldmatrix + permuted packed P) ------------
#define PSTR    1040                         // floats; 4160 B, ≡64 mod 128
#define S_BYTES (32 * PSTR * 4)              // 133120
#define Q_OFF   S_BYTES
#define QROW    144
#define Q_BYTES (2 * 32 * QROW)              // 9216
#define KV_OFF  (Q_OFF + Q_BYTES)            // 142336
#define KROW 144
#define KMAT (128 * KROW)
#define KSTG (2 * KMAT)                      // 36864
#define VROW 272
#define VMAT (64 * VROW)
#define VSTG (2 * VMAT)                      // 34816
#define ATTN_SMEM (KV_OFF + 2 * KSTG)        // 216064

__global__ __launch_bounds__(256, 1) void attn_mma(float* __restrict__ probs)
{
    extern __shared__ char sm[];
    float* S = (float*)sm;
    uint32_t* Su = (uint32_t*)sm;
    const uint32_t sb = smem_u32(sm);
    const int tid = threadIdx.x, lane = tid & 31, warp = tid >> 5;
    const int g = lane >> 2, tig = lane & 3;
    const int t8 = lane >> 3, r8 = lane & 7;
    const int qb = blockIdx.x, hd = blockIdx.y, b = blockIdx.z;
    const int q0 = qb * 32;
    const size_t tokbase = (size_t)b * SEQ;

    // Q tile (hi/lo) -> smem
    #pragma unroll
    for (int i = 0; i < 2; i++) {
        int idx = tid + i * 256;
        int mat = idx >> 8;
        int rix = idx & 255;
        int r = rix >> 3, v = (rix & 7) * 16;
        const __nv_bfloat16* src = mat ? g_ql : g_qh;
        const char* sp = (const char*)(src + (tokbase + q0 + r) * CDIM + hd * HD) + v;
        *(uint4*)(sm + Q_OFF + mat * 32 * QROW + r * QROW + v) = *(const uint4*)sp;
    }

    auto load_k = [&](int kv0, int buf) {
        const uint32_t st = sb + KV_OFF + buf * KSTG;
        #pragma unroll
        for (int i = 0; i < 8; i++) {
            int idx = tid + i * 256;
            int mat = idx >> 10;
            int rix = idx & 1023;
            int r = rix >> 3, v = (rix & 7) * 16;
            const __nv_bfloat16* src = mat ? g_kl : g_kh;
            const char* sp = (const char*)(src + (tokbase + kv0 + r) * CDIM + hd * HD) + v;
            cpa16(st + mat * KMAT + r * KROW + v, sp);
        }
        CP_COMMIT();
    };
    auto load_v = [&](int kv0, int buf) {
        const uint32_t st = sb + KV_OFF + buf * VSTG;
        #pragma unroll
        for (int i = 0; i < 8; i++) {
            int idx = tid + i * 256;
            int mat = idx >> 10;
            int rix = idx & 1023;
            int r = rix >> 4, v = (rix & 15) * 16;
            const __nv_bfloat16* src = mat ? g_vtl : g_vth;
            const char* sp = (const char*)(src + ((size_t)(b * 8 + hd) * 64 + r) * SEQ + kv0) + v;
            cpa16(st + mat * VMAT + r * VROW + v, sp);
        }
        CP_COMMIT();
    };

    load_k(0, 0);
    load_k(128, 1);

    const uint32_t sbQ = sb + Q_OFF;

    // ---- scores S = Q @ K^T (Wq pre-scaled by 1/8) ----
    for (int ch = 0; ch < 8; ch++) {
        if (ch < 7) asm volatile("cp.async.wait_group 1;" ::: "memory");
        else        asm volatile("cp.async.wait_group 0;" ::: "memory");
        __syncthreads();
        const uint32_t kb32 = sb + KV_OFF + (ch & 1) * KSTG;
        float c[2][2][4];
        #pragma unroll
        for (int am = 0; am < 2; am++)
            #pragma unroll
            for (int nt = 0; nt < 2; nt++)
                #pragma unroll
                for (int e = 0; e < 4; e++) c[am][nt][e] = 0.0f;

        #pragma unroll
        for (int kk = 0; kk < 4; kk++) {
            const int kbyte = kk * 32;
            uint32_t aH[2][4], aL[2][4];
            #pragma unroll
            for (int am = 0; am < 2; am++) {
                uint32_t arow = am * 16 + (t8 & 1) * 8 + r8;
                uint32_t acol = kbyte + (t8 >> 1) * 16;
                ldm_x4(aH[am], sbQ + arow * QROW + acol);
                ldm_x4(aL[am], sbQ + 32 * QROW + arow * QROW + acol);
            }
            #pragma unroll
            for (int nt = 0; nt < 2; nt++) {
                // tiles: t8=0 -> H khalf0, 1 -> H khalf1, 2 -> L khalf0, 3 -> L khalf1
                uint32_t krow = warp * 16 + nt * 8 + r8;
                uint32_t kaddr = kb32 + krow * KROW + ((t8 >> 1) ? KMAT : 0u)
                               + kbyte + (t8 & 1) * 16;
                uint32_t kf[4];
                ldm_x4(kf, kaddr);
                #pragma unroll
                for (int am = 0; am < 2; am++) {
                    mma16816(c[am][nt], aH[am], kf);       // H*H
                    mma16816(c[am][nt], aL[am], kf);       // L*H
                    mma16816(c[am][nt], aH[am], kf + 2);   // H*L
                }
            }
        }
        __syncthreads();
        if (ch + 2 < 8) load_k((ch + 2) * 128, ch & 1);
        #pragma unroll
        for (int am = 0; am < 2; am++)
            #pragma unroll
            for (int nt = 0; nt < 2; nt++) {
                int row = am * 16 + g;
                int col = ch * 128 + warp * 16 + nt * 8 + 2 * tig;
                *(float2*)&S[row * PSTR + col] =
                    make_float2(c[am][nt][0], c[am][nt][1]);
                *(float2*)&S[(row + 8) * PSTR + col] =
                    make_float2(c[am][nt][2], c[am][nt][3]);
            }
    }

    // preload V chunks (K reads all completed at final in-loop barrier)
    load_v(0, 0);
    load_v(128, 1);
    __syncthreads();

    // ---- softmax; write probs; write permuted packed P (hi|lo) ----
    #pragma unroll
    for (int rr = 0; rr < 4; rr++) {
        int row = warp * 4 + rr;
        float4 vals[8];
        float mx = -1e30f;
        #pragma unroll
        for (int v = 0; v < 8; v++) {
            vals[v] = *(float4*)&S[row * PSTR + (v * 32 + lane) * 4];
            mx = fmaxf(mx, fmaxf(fmaxf(vals[v].x, vals[v].y), fmaxf(vals[v].z, vals[v].w)));
        }
        #pragma unroll
        for (int o = 16; o > 0; o >>= 1) mx = fmaxf(mx, __shfl_xor_sync(0xffffffffu, mx, o));
        float sum = 0.f;
        #pragma unroll
        for (int v = 0; v < 8; v++) {
            vals[v].x = __expf(vals[v].x - mx);
            vals[v].y = __expf(vals[v].y - mx);
            vals[v].z = __expf(vals[v].z - mx);
            vals[v].w = __expf(vals[v].w - mx);
            sum += vals[v].x + vals[v].y + vals[v].z + vals[v].w;
        }
        #pragma unroll
        for (int o = 16; o > 0; o >>= 1) sum += __shfl_xor_sync(0xffffffffu, sum, o);
        float inv = 1.0f / sum;
        size_t pbase = ((tokbase + q0 + row) * NHEAD + hd) * SEQ;
        #pragma unroll
        for (int v = 0; v < 8; v++) {
            int cc = (v * 32 + lane) * 4;
            float p[4] = {vals[v].x * inv, vals[v].y * inv, vals[v].z * inv, vals[v].w * inv};
            *(float4*)&probs[pbase + cc] = make_float4(p[0], p[1], p[2], p[3]);
            uint32_t w[4];
            #pragma unroll
            for (int e = 0; e < 4; e++) {
                __nv_bfloat16 h, l;
                split_bf16(p[e], h, l);
                w[e] = (uint32_t)__bfloat16_as_ushort(h) |
                       ((uint32_t)__bfloat16_as_ushort(l) << 16);
            }
            // permuted group layout: group of 16 cols stored as
            // [0,1,8,9, 2,3,10,11, 4,5,12,13, 6,7,14,15]
            int j  = cc & 15;
            int cg = cc >> 4;
            int p0 = ((j & 4) << 1) | ((j & 8) >> 2);
            int iw = row * PSTR + cg * 16 + p0;
            *(uint2*)&Su[iw]     = make_uint2(w[0], w[1]);
            *(uint2*)&Su[iw + 4] = make_uint2(w[2], w[3]);
        }
    }
    __syncthreads();

    // ---- O = P @ V ----
    float o[2][4];
    #pragma unroll
    for (int am = 0; am < 2; am++)
        #pragma unroll
        for (int e = 0; e < 4; e++) o[am][e] = 0.0f;

    for (int ch = 0; ch < 8; ch++) {
        if (ch < 7) asm volatile("cp.async.wait_group 1;" ::: "memory");
        else        asm volatile("cp.async.wait_group 0;" ::: "memory");
        __syncthreads();
        const uint32_t vb32 = sb + KV_OFF + (ch & 1) * VSTG;
        #pragma unroll
        for (int kk = 0; kk < 8; kk++) {
            const int kbyte = kk * 32;
            // V fragments: one x4 = {vh k0, vh k1, vl k0, vl k1}
            uint32_t vaddr = vb32 + (warp * 8 + r8) * VROW + ((t8 >> 1) ? VMAT : 0u)
                           + kbyte + (t8 & 1) * 16;
            uint32_t vf[4];
            ldm_x4(vf, vaddr);
            const int cg = ch * 8 + kk;
            #pragma unroll
            for (int am = 0; am < 2; am++) {
                int r = am * 16 + g;
                uint4 U  = *(const uint4*)&Su[r * PSTR + cg * 16 + tig * 4];
                uint4 U2 = *(const uint4*)&Su[(r + 8) * PSTR + cg * 16 + tig * 4];
                uint32_t aH[4] = {__byte_perm(U.x,  U.y,  0x5410), __byte_perm(U2.x, U2.y, 0x5410),
                                  __byte_perm(U.z,  U.w,  0x5410), __byte_perm(U2.z, U2.w, 0x5410)};
                uint32_t aL[4] = {__byte_perm(U.x,  U.y,  0x7632), __byte_perm(U2.x, U2.y, 0x7632),
                                  __byte_perm(U.z,  U.w,  0x7632), __byte_perm(U2.z, U2.w, 0x7632)};
                mma16816(o[am], aH, vf);       // P_h * V_h
                mma16816(o[am], aL, vf);       // P_l * V_h
                mma16816(o[am], aH, vf + 2);   // P_h * V_l
            }
        }
        __syncthreads();
        if (ch + 2 < 8) load_v((ch + 2) * 128, ch & 1);
    }

    // ---- O epilogue: bf16 hi/lo for Wo gemm ----
    #pragma unroll
    for (int am = 0; am < 2; am++) {
        int row = q0 + am * 16 + g;
        int col = hd * HD + warp * 8 + 2 * tig;
        #pragma unroll
        for (int h = 0; h < 2; h++) {
            size_t off = (tokbase + row + h * 8) * CDIM + col;
            __nv_bfloat16 h0, l0, h1, l1;
            split_bf16(o[am][h * 2 + 0], h0, l0);
            split_bf16(o[am][h * 2 + 1], h1, l1);
            __nv_bfloat162 hp; hp.x = h0; hp.y = h1;
            __nv_bfloat162 lp; lp.x = l0; lp.y = l1;
            *(__nv_bfloat162*)(g_oh + off) = hp;
            *(__nv_bfloat162*)(g_ol + off) = lp;
        }
    }
}

// ---------------- launcher ----------------
extern "C" void kernel_launch(void* const* d_in, const int* in_sizes, int n_in,
                              void* d_out, int out_size)
{
    const float* x     = (const float*)d_in[0];
    const float* Wq    = (const float*)d_in[1];
    const float* Wk    = (const float*)d_in[2];
    const float* Wv    = (const float*)d_in[3];
    const float* Wo    = (const float*)d_in[4];
    const float* ln1_g = (const float*)d_in[5];
    const float* ln1_b = (const float*)d_in[6];
    const float* fc1_w = (const float*)d_in[7];
    const float* fc1_b = (const float*)d_in[8];
    const float* fc2_w = (const float*)d_in[9];
    const float* fc2_b = (const float*)d_in[10];
    const float* ln2_g = (const float*)d_in[11];
    const float* ln2_b = (const float*)d_in[12];

    float* out   = (float*)d_out;
    float* probs = out + (size_t)NTOK * CDIM;

    float *p_xn, *p_attn, *p_yn;
    __nv_bfloat16 *p_xnh, *p_xnl, *p_ynh, *p_ynl, *p_oh, *p_ol, *p_h1h, *p_h1l;
    __nv_bfloat16 *p_qh, *p_ql, *p_kh, *p_kl, *p_vth, *p_vtl;
    __nv_bfloat16 *p_wqth, *p_wqtl, *p_wkth, *p_wktl, *p_wvth, *p_wvtl;
    __nv_bfloat16 *p_woth, *p_wotl, *p_f1th, *p_f1tl, *p_f2th, *p_f2tl;
    cudaGetSymbolAddress((void**)&p_xn,   g_xn);
    cudaGetSymbolAddress((void**)&p_attn, g_attn);
    cudaGetSymbolAddress((void**)&p_yn,   g_yn);
    cudaGetSymbolAddress((void**)&p_xnh,  g_xnh);
    cudaGetSymbolAddress((void**)&p_xnl,  g_xnl);
    cudaGetSymbolAddress((void**)&p_ynh,  g_ynh);
    cudaGetSymbolAddress((void**)&p_ynl,  g_ynl);
    cudaGetSymbolAddress((void**)&p_oh,   g_oh);
    cudaGetSymbolAddress((void**)&p_ol,   g_ol);
    cudaGetSymbolAddress((void**)&p_h1h,  g_h1h);
    cudaGetSymbolAddress((void**)&p_h1l,  g_h1l);
    cudaGetSymbolAddress((void**)&p_qh,   g_qh);
    cudaGetSymbolAddress((void**)&p_ql,   g_ql);
    cudaGetSymbolAddress((void**)&p_kh,   g_kh);
    cudaGetSymbolAddress((void**)&p_kl,   g_kl);
    cudaGetSymbolAddress((void**)&p_vth,  g_vth);
    cudaGetSymbolAddress((void**)&p_vtl,  g_vtl);
    cudaGetSymbolAddress((void**)&p_wqth, g_wqth);
    cudaGetSymbolAddress((void**)&p_wqtl, g_wqtl);
    cudaGetSymbolAddress((void**)&p_wkth, g_wkth);
    cudaGetSymbolAddress((void**)&p_wktl, g_wktl);
    cudaGetSymbolAddress((void**)&p_wvth, g_wvth);
    cudaGetSymbolAddress((void**)&p_wvtl, g_wvtl);
    cudaGetSymbolAddress((void**)&p_woth, g_woth);
    cudaGetSymbolAddress((void**)&p_wotl, g_wotl);
    cudaGetSymbolAddress((void**)&p_f1th, g_f1th);
    cudaGetSymbolAddress((void**)&p_f1tl, g_f1tl);
    cudaGetSymbolAddress((void**)&p_f2th, g_f2th);
    cudaGetSymbolAddress((void**)&p_f2tl, g_f2tl);

    cudaFuncSetAttribute(attn_mma,
                         cudaFuncAttributeMaxDynamicSharedMemorySize, ATTN_SMEM);
    cudaFuncSetAttribute(gemm_mma<false, false, false, true, false>,
                         cudaFuncAttributeMaxDynamicSharedMemorySize, GT_SMEM);
    cudaFuncSetAttribute(gemm_mma<false, false, false, false, true>,
                         cudaFuncAttributeMaxDynamicSharedMemorySize, GT_SMEM);
    cudaFuncSetAttribute(gemm_mma<false, true, false, false, false>,
                         cudaFuncAttributeMaxDynamicSharedMemorySize, GT_SMEM);
    cudaFuncSetAttribute(gemm_mma<true, false, true, true, false>,
                         cudaFuncAttributeMaxDynamicSharedMemorySize, GT_SMEM);
    cudaFuncSetAttribute(gemm_mma<true, true, false, false, false>,
                         cudaFuncAttributeMaxDynamicSharedMemorySize, GT_SMEM);

    // launch 0: LN1
    ln_kernel<<<NTOK, 128>>>(x, ln1_g, ln1_b, p_xn, p_xnh, p_xnl);

    // launch 1: all weight transposes (Wq folded with 1/8)
    transconv_all<<<3072, 256>>>(Wq, Wk, Wv, Wo, fc1_w, fc2_w);

    dim3 g512(CDIM / BN, NTOK / BM);
    // launches 2-4: Q, K -> bf16 hi/lo; V -> transposed hi/lo
    gemm_mma<false, false, false, true, false><<<g512, 256, GT_SMEM>>>(
        p_xnh, p_xnl, p_wqth, p_wqtl, nullptr, nullptr, nullptr, p_qh, p_ql,
        NTOK, CDIM, CDIM);
    gemm_mma<false, false, false, true, false><<<g512, 256, GT_SMEM>>>(
        p_xnh, p_xnl, p_wkth, p_wktl, nullptr, nullptr, nullptr, p_kh, p_kl,
        NTOK, CDIM, CDIM);
    gemm_mma<false, false, false, false, true><<<g512, 256, GT_SMEM>>>(
        p_xnh, p_xnl, p_wvth, p_wvtl, nullptr, nullptr, nullptr, p_vth, p_vtl,
        NTOK, CDIM, CDIM);

    // launch 5 (ncu-profiled): attention
    attn_mma<<<dim3(32, NHEAD, NBATCH), 256, ATTN_SMEM>>>(probs);

    // launch 6: attn_out = O @ Wo + xn
    gemm_mma<false, true, false, false, false><<<g512, 256, GT_SMEM>>>(
        p_oh, p_ol, p_woth, p_wotl, nullptr, p_xn, p_attn, nullptr, nullptr,
        NTOK, CDIM, CDIM);

    // launch 7: LN2
    ln_kernel<<<NTOK, 128>>>(p_attn, ln2_g, ln2_b, p_yn, p_ynh, p_ynl);

    // launch 8: h1 = relu(yn @ fc1 + b1) -> bf16 hi/lo
    dim3 gff(FFDIM / BN, NTOK / BM);
    gemm_mma<true, false, true, true, false><<<gff, 256, GT_SMEM>>>(
        p_ynh, p_ynl, p_f1th, p_f1tl, fc1_b, nullptr, nullptr, p_h1h, p_h1l,
        NTOK, FFDIM, CDIM);

    // launch 9: out = h1 @ fc2 + b2 + yn
    gemm_mma<true, true, false, false, false><<<g512, 256, GT_SMEM>>>(
        p_h1h, p_h1l, p_f2th, p_f2tl, fc2_b, p_yn, out, nullptr, nullptr,
        NTOK, CDIM, FFDIM);
}

// round 10
// speedup vs baseline: 3.6780x; 1.2848x over previous
#include <cuda_runtime.h>
#include <cuda_fp16.h>
#include <math.h>
#include <stdint.h>

// ---------------- problem constants ----------------
#define NTOK   8192
#define CDIM   512
#define FFDIM  2048
#define NHEAD  8
#define HD     64
#define SEQ    1024
#define NBATCH 8

// ---------------- scratch ----------------
__device__ float g_xn  [NTOK * CDIM];
__device__ float g_attn[NTOK * CDIM];
__device__ float g_yn  [NTOK * CDIM];

__device__ __half g_xnh[NTOK * CDIM], g_xnl[NTOK * CDIM];
__device__ __half g_ynh[NTOK * CDIM], g_ynl[NTOK * CDIM];
__device__ __half g_qh [NTOK * CDIM], g_ql [NTOK * CDIM];
__device__ __half g_kk [NTOK * CDIM];                       // K single fp16
__device__ __half g_vt [NTOK * CDIM];                       // V^T single [b*8+h][d][kv]
__device__ __half g_oh [NTOK * CDIM], g_ol [NTOK * CDIM];
__device__ __half g_h1h[NTOK * FFDIM], g_h1l[NTOK * FFDIM];

__device__ __half g_wqt[CDIM * CDIM];
__device__ __half g_wkt[CDIM * CDIM];
__device__ __half g_wvt[CDIM * CDIM];
__device__ __half g_wot[CDIM * CDIM];
__device__ __half g_f1t[CDIM * FFDIM];
__device__ __half g_f2t[FFDIM * CDIM];

// ---------------- helpers ----------------
__device__ __forceinline__ void split_f16(float x, __half& h, __half& l) {
    h = __float2half_rn(x);
    l = __float2half_rn(x - __half2float(h));
}
__device__ __forceinline__ uint32_t smem_u32(const void* p) {
    uint32_t a;
    asm("{ .reg .u64 t; cvta.to.shared.u64 t, %1; cvt.u32.u64 %0, t; }" : "=r"(a) : "l"(p));
    return a;
}
__device__ __forceinline__ void cpa16(uint32_t s, const void* g) {
    asm volatile("cp.async.cg.shared.global [%0], [%1], 16;" :: "r"(s), "l"(g) : "memory");
}
#define CP_COMMIT() asm volatile("cp.async.commit_group;" ::: "memory")

__device__ __forceinline__ void mma16816(float* c, const uint32_t* a, const uint32_t* b) {
    asm volatile("mma.sync.aligned.m16n8k16.row.col.f32.f16.f16.f32 "
        "{%0,%1,%2,%3}, {%4,%5,%6,%7}, {%8,%9}, {%0,%1,%2,%3};"
        : "+f"(c[0]), "+f"(c[1]), "+f"(c[2]), "+f"(c[3])
        : "r"(a[0]), "r"(a[1]), "r"(a[2]), "r"(a[3]), "r"(b[0]), "r"(b[1]));
}
__device__ __forceinline__ void ldm_x4(uint32_t* r, uint32_t addr) {
    asm volatile("ldmatrix.sync.aligned.m8n8.x4.shared.b16 {%0,%1,%2,%3}, [%4];"
        : "=r"(r[0]), "=r"(r[1]), "=r"(r[2]), "=r"(r[3]) : "r"(addr));
}

// ---------------- LayerNorm (fp32 out + fp16 hi/lo) ----------------
__global__ __launch_bounds__(128) void ln_kernel(
    const float* __restrict__ in, const float* __restrict__ gam,
    const float* __restrict__ bet, float* __restrict__ out,
    __half* __restrict__ oh, __half* __restrict__ ol)
{
    const int row = blockIdx.x;
    const int t = threadIdx.x;
    const float4* x4 = (const float4*)(in + (size_t)row * CDIM);
    float4 v = x4[t];
    float s  = v.x + v.y + v.z + v.w;
    float ss = fmaf(v.x, v.x, fmaf(v.y, v.y, fmaf(v.z, v.z, v.w * v.w)));
    #pragma unroll
    for (int o = 16; o > 0; o >>= 1) {
        s  += __shfl_xor_sync(0xffffffffu, s,  o);
        ss += __shfl_xor_sync(0xffffffffu, ss, o);
    }
    __shared__ float sh[4], shh[4];
    const int wid = t >> 5, lane = t & 31;
    if (lane == 0) { sh[wid] = s; shh[wid] = ss; }
    __syncthreads();
    float tot  = sh[0] + sh[1] + sh[2] + sh[3];
    float tot2 = shh[0] + shh[1] + shh[2] + shh[3];
    const float mean = tot * (1.0f / CDIM);
    const float var  = tot2 * (1.0f / CDIM) - mean * mean;
    const float r    = rsqrtf(var + 1e-5f);
    float4 g = ((const float4*)gam)[t];
    float4 b = ((const float4*)bet)[t];
    float o4[4];
    o4[0] = (v.x - mean) * r * g.x + b.x;
    o4[1] = (v.y - mean) * r * g.y + b.y;
    o4[2] = (v.z - mean) * r * g.z + b.z;
    o4[3] = (v.w - mean) * r * g.w + b.w;
    ((float4*)(out + (size_t)row * CDIM))[t] = make_float4(o4[0], o4[1], o4[2], o4[3]);
    size_t base = (size_t)row * CDIM + t * 4;
    #pragma unroll
    for (int e = 0; e < 4; e++) {
        __half h, l;
        split_f16(o4[e], h, l);
        oh[base + e] = h; ol[base + e] = l;
    }
}

// ------------- all weight transposes (single fp16) in ONE launch ----------
__global__ __launch_bounds__(256) void transconv_all(
    const float* __restrict__ Wq, const float* __restrict__ Wk,
    const float* __restrict__ Wv, const float* __restrict__ Wo,
    const float* __restrict__ F1, const float* __restrict__ F2)
{
    const int bid = blockIdx.x;
    const float* W; __half* Th;
    int K, N, nb, idx; float scale = 1.0f;
    if (bid < 1024) {
        int which = bid >> 8; idx = bid & 255; K = 512; N = 512; nb = 16;
        if (which == 0)      { W = Wq; Th = g_wqt; scale = 0.125f; }
        else if (which == 1) { W = Wk; Th = g_wkt; }
        else if (which == 2) { W = Wv; Th = g_wvt; }
        else                 { W = Wo; Th = g_wot; }
    } else if (bid < 2048) {
        idx = bid - 1024; W = F1; Th = g_f1t; K = 512; N = 2048; nb = 64;
    } else {
        idx = bid - 2048; W = F2; Th = g_f2t; K = 2048; N = 512; nb = 16;
    }
    const int n0 = (idx % nb) * 32, k0 = (idx / nb) * 32;
    __shared__ float t[32][33];
    const int tx = threadIdx.x & 31, ty = threadIdx.x >> 5;
    #pragma unroll
    for (int i = 0; i < 4; i++)
        t[ty + i * 8][tx] = W[(size_t)(k0 + ty + i * 8) * N + n0 + tx];
    __syncthreads();
    #pragma unroll
    for (int i = 0; i < 4; i++) {
        int r = ty + i * 8;
        Th[(size_t)(n0 + r) * K + k0 + tx] = __float2half_rn(t[tx][r] * scale);
    }
}

// -------- mma.sync fp16 2-term GEMM: C = (Ah+Al) @ B16^T ------------------
#define BM 128
#define BN 128
#define KC 32
#define ROWB 80
#define MAT_BYTES (128 * ROWB)
#define AH_OFF 0
#define AL_OFF MAT_BYTES
#define B_OFF  (2 * MAT_BYTES)
#define STAGE_BYTES (3 * MAT_BYTES)          // 30720
#define GT_SMEM (2 * STAGE_BYTES)            // 61440

// OM: 0 = fp32 Cf; 1 = split fp16 Ch/Cl; 2 = single fp16 Ch; 3 = transposed single fp16
template <bool BIAS, bool RES, bool RELU, int OM>
__global__ __launch_bounds__(256, 2) void gemm_mma(
    const __half* __restrict__ Ah, const __half* __restrict__ Al,
    const __half* __restrict__ B,
    const float* __restrict__ bias, const float* __restrict__ res,
    float* __restrict__ Cf, __half* __restrict__ Ch,
    __half* __restrict__ Cl, int M, int N, int K)
{
    extern __shared__ char sm[];
    const uint32_t sbase = smem_u32(sm);
    const int tid  = threadIdx.x;
    const int lane = tid & 31;
    const int warp = tid >> 5;
    const int wm0  = (warp & 3) * 32;
    const int wn0  = (warp >> 2) * 64;
    const int g    = lane >> 2;
    const int tig  = lane & 3;
    const int t8   = lane >> 3;
    const int r8   = lane & 7;
    const int bm0  = blockIdx.y * BM;
    const int bn0  = blockIdx.x * BN;

    float acc[2][8][4];
    #pragma unroll
    for (int i = 0; i < 2; i++)
        #pragma unroll
        for (int j = 0; j < 8; j++)
            #pragma unroll
            for (int e = 0; e < 4; e++) acc[i][j][e] = 0.0f;

    const __half* gsrc[3] = {Ah, Al, B};

    auto load_stage = [&](int kt, int buf) {
        const uint32_t st = sbase + buf * STAGE_BYTES;
        #pragma unroll
        for (int i = 0; i < 6; i++) {
            int idx = tid + i * 256;              // 0..1535
            int mat = idx >> 9;                   // 0..2
            int rix = idx & 511;
            int r   = rix >> 2;
            int cb  = (rix & 3) * 16;
            int grow = (mat < 2) ? (bm0 + r) : (bn0 + r);
            const char* src = (const char*)(gsrc[mat] + (size_t)grow * K + kt) + cb;
            cpa16(st + mat * MAT_BYTES + r * ROWB + cb, src);
        }
        CP_COMMIT();
    };

    const int S = K / KC;
    load_stage(0, 0);
    load_stage(KC, 1);

    for (int s = 0; s < S; s++) {
        if (s + 1 < S) asm volatile("cp.async.wait_group 1;" ::: "memory");
        else           asm volatile("cp.async.wait_group 0;" ::: "memory");
        __syncthreads();

        const uint32_t sb32 = sbase + (s & 1) * STAGE_BYTES;
        #pragma unroll
        for (int kk = 0; kk < 2; kk++) {
            const int kbyte = kk * 32;
            uint32_t aH[2][4], aL[2][4];
            #pragma unroll
            for (int am = 0; am < 2; am++) {
                uint32_t arow = wm0 + am * 16 + (t8 & 1) * 8 + r8;
                uint32_t acol = kbyte + (t8 >> 1) * 16;
                ldm_x4(aH[am], sb32 + AH_OFF + arow * ROWB + acol);
                ldm_x4(aL[am], sb32 + AL_OFF + arow * ROWB + acol);
            }
            #pragma unroll
            for (int bn2 = 0; bn2 < 4; bn2++) {
                uint32_t brow = wn0 + (2 * bn2 + (t8 >> 1)) * 8 + r8;
                uint32_t bcol = kbyte + (t8 & 1) * 16;
                uint32_t b4[4];
                ldm_x4(b4, sb32 + B_OFF + brow * ROWB + bcol);
                #pragma unroll
                for (int half = 0; half < 2; half++) {
                    const int bn = 2 * bn2 + half;
                    const uint32_t* b = b4 + 2 * half;
                    mma16816(acc[0][bn], aH[0], b);
                    mma16816(acc[0][bn], aL[0], b);
                    mma16816(acc[1][bn], aH[1], b);
                    mma16816(acc[1][bn], aL[1], b);
                }
            }
        }
        __syncthreads();
        if (s + 2 < S) load_stage((s + 2) * KC, s & 1);
    }

    // epilogue
    #pragma unroll
    for (int am = 0; am < 2; am++) {
        #pragma unroll
        for (int bn = 0; bn < 8; bn++) {
            const int row = bm0 + wm0 + am * 16 + g;
            const int col = bn0 + wn0 + bn * 8 + 2 * tig;
            float* c = acc[am][bn];
            #pragma unroll
            for (int h = 0; h < 2; h++) {
                const int r = row + h * 8;
                float v0 = c[h * 2 + 0];
                float v1 = c[h * 2 + 1];
                if (BIAS) { v0 += bias[col]; v1 += bias[col + 1]; }
                if (RES) {
                    float2 rr = *(const float2*)&res[(size_t)r * N + col];
                    v0 += rr.x; v1 += rr.y;
                }
                if (RELU) { v0 = fmaxf(v0, 0.f); v1 = fmaxf(v1, 0.f); }
                if (OM == 3) {
                    int bb = r >> 10, kv = r & 1023;
                    int head = col >> 6, d = col & 63;
                    size_t tb = ((size_t)(bb * 8 + head) * 64 + d) * 1024 + kv;
                    Ch[tb]        = __float2half_rn(v0);
                    Ch[tb + 1024] = __float2half_rn(v1);
                } else if (OM == 2) {
                    __half2 hp; hp.x = __float2half_rn(v0); hp.y = __float2half_rn(v1);
                    *(__half2*)(Ch + (size_t)r * N + col) = hp;
                } else if (OM == 1) {
                    __half h0, l0, h1, l1;
                    split_f16(v0, h0, l0);
                    split_f16(v1, h1, l1);
                    __half2 hp; hp.x = h0; hp.y = h1;
                    __half2 lp; lp.x = l0; lp.y = l1;
                    *(__half2*)(Ch + (size_t)r * N + col) = hp;
                    *(__half2*)(Cl + (size_t)r * N + col) = lp;
                } else {
                    *(float2*)&Cf[(size_t)r * N + col] = make_float2(v0, v1);
                }
            }
        }
    }
}

// ---------------- mma attention (fp16; Q split, K/V single) ---------------
#define PSTR    1040
#define S_BYTES (32 * PSTR * 4)              // 133120
#define Q_OFF   S_BYTES
#define QROW    144
#define Q_BYTES (2 * 32 * QROW)              // 9216
#define KV_OFF  (Q_OFF + Q_BYTES)            // 142336
#define KROW 144
#define KMAT (128 * KROW)                    // 18432 (single matrix = one buffer)
#define VROW 272
#define VMAT (64 * VROW)                     // 17408
#define ATTN_SMEM (KV_OFF + 2 * KMAT)        // 179200

__global__ __launch_bounds__(256, 1) void attn_mma(float* __restrict__ probs)
{
    extern __shared__ char sm[];
    float* S = (float*)sm;
    uint32_t* Su = (uint32_t*)sm;
    const uint32_t sb = smem_u32(sm);
    const int tid = threadIdx.x, lane = tid & 31, warp = tid >> 5;
    const int g = lane >> 2, tig = lane & 3;
    const int t8 = lane >> 3, r8 = lane & 7;
    const int qb = blockIdx.x, hd = blockIdx.y, b = blockIdx.z;
    const int q0 = qb * 32;
    const size_t tokbase = (size_t)b * SEQ;

    // Q tile (hi/lo) -> smem
    #pragma unroll
    for (int i = 0; i < 2; i++) {
        int idx = tid + i * 256;
        int mat = idx >> 8;
        int rix = idx & 255;
        int r = rix >> 3, v = (rix & 7) * 16;
        const __half* src = mat ? g_ql : g_qh;
        const char* sp = (const char*)(src + (tokbase + q0 + r) * CDIM + hd * HD) + v;
        *(uint4*)(sm + Q_OFF + mat * 32 * QROW + r * QROW + v) = *(const uint4*)sp;
    }

    auto load_k = [&](int kv0, int buf) {
        const uint32_t st = sb + KV_OFF + buf * KMAT;
        #pragma unroll
        for (int i = 0; i < 4; i++) {
            int idx = tid + i * 256;              // 0..1023
            int r = idx >> 3, v = (idx & 7) * 16;
            const char* sp = (const char*)(g_kk + (tokbase + kv0 + r) * CDIM + hd * HD) + v;
            cpa16(st + r * KROW + v, sp);
        }
        CP_COMMIT();
    };
    auto load_v = [&](int kv0, int buf) {
        const uint32_t st = sb + KV_OFF + buf * VMAT;
        #pragma unroll
        for (int i = 0; i < 4; i++) {
            int idx = tid + i * 256;              // 0..1023
            int r = idx >> 4, v = (idx & 15) * 16;
            const char* sp = (const char*)(g_vt + ((size_t)(b * 8 + hd) * 64 + r) * SEQ + kv0) + v;
            cpa16(st + r * VROW + v, sp);
        }
        CP_COMMIT();
    };

    load_k(0, 0);
    load_k(128, 1);

    const uint32_t sbQ = sb + Q_OFF;

    // ---- scores S = Q @ K^T (Wq pre-scaled by 1/8) ----
    for (int ch = 0; ch < 8; ch++) {
        if (ch < 7) asm volatile("cp.async.wait_group 1;" ::: "memory");
        else        asm volatile("cp.async.wait_group 0;" ::: "memory");
        __syncthreads();
        const uint32_t kb32 = sb + KV_OFF + (ch & 1) * KMAT;
        float c[2][2][4];
        #pragma unroll
        for (int am = 0; am < 2; am++)
            #pragma unroll
            for (int nt = 0; nt < 2; nt++)
                #pragma unroll
                for (int e = 0; e < 4; e++) c[am][nt][e] = 0.0f;

        #pragma unroll
        for (int kk = 0; kk < 4; kk++) {
            const int kbyte = kk * 32;
            uint32_t aH[2][4], aL[2][4];
            #pragma unroll
            for (int am = 0; am < 2; am++) {
                uint32_t arow = am * 16 + (t8 & 1) * 8 + r8;
                uint32_t acol = kbyte + (t8 >> 1) * 16;
                ldm_x4(aH[am], sbQ + arow * QROW + acol);
                ldm_x4(aL[am], sbQ + 32 * QROW + arow * QROW + acol);
            }
            // K fragments: tiles = {nt0 k0, nt0 k1, nt1 k0, nt1 k1}
            uint32_t krow = warp * 16 + (t8 >> 1) * 8 + r8;
            uint32_t kaddr = kb32 + krow * KROW + kbyte + (t8 & 1) * 16;
            uint32_t kf[4];
            ldm_x4(kf, kaddr);
            #pragma unroll
            for (int nt = 0; nt < 2; nt++) {
                #pragma unroll
                for (int am = 0; am < 2; am++) {
                    mma16816(c[am][nt], aH[am], kf + 2 * nt);
                    mma16816(c[am][nt], aL[am], kf + 2 * nt);
                }
            }
        }
        __syncthreads();
        if (ch + 2 < 8) load_k((ch + 2) * 128, ch & 1);
        #pragma unroll
        for (int am = 0; am < 2; am++)
            #pragma unroll
            for (int nt = 0; nt < 2; nt++) {
                int row = am * 16 + g;
                int col = ch * 128 + warp * 16 + nt * 8 + 2 * tig;
                *(float2*)&S[row * PSTR + col] =
                    make_float2(c[am][nt][0], c[am][nt][1]);
                *(float2*)&S[(row + 8) * PSTR + col] =
                    make_float2(c[am][nt][2], c[am][nt][3]);
            }
    }

    // preload V chunks (K reads all completed at final in-loop barrier)
    load_v(0, 0);
    load_v(128, 1);
    __syncthreads();

    // ---- softmax; write probs; write permuted packed P (hi|lo fp16) ----
    #pragma unroll
    for (int rr = 0; rr < 4; rr++) {
        int row = warp * 4 + rr;
        float4 vals[8];
        float mx = -1e30f;
        #pragma unroll
        for (int v = 0; v < 8; v++) {
            vals[v] = *(float4*)&S[row * PSTR + (v * 32 + lane) * 4];
            mx = fmaxf(mx, fmaxf(fmaxf(vals[v].x, vals[v].y), fmaxf(vals[v].z, vals[v].w)));
        }
        #pragma unroll
        for (int o = 16; o > 0; o >>= 1) mx = fmaxf(mx, __shfl_xor_sync(0xffffffffu, mx, o));
        float sum = 0.f;
        #pragma unroll
        for (int v = 0; v < 8; v++) {
            vals[v].x = __expf(vals[v].x - mx);
            vals[v].y = __expf(vals[v].y - mx);
            vals[v].z = __expf(vals[v].z - mx);
            vals[v].w = __expf(vals[v].w - mx);
            sum += vals[v].x + vals[v].y + vals[v].z + vals[v].w;
        }
        #pragma unroll
        for (int o = 16; o > 0; o >>= 1) sum += __shfl_xor_sync(0xffffffffu, sum, o);
        float inv = 1.0f / sum;
        size_t pbase = ((tokbase + q0 + row) * NHEAD + hd) * SEQ;
        #pragma unroll
        for (int v = 0; v < 8; v++) {
            int cc = (v * 32 + lane) * 4;
            float p[4] = {vals[v].x * inv, vals[v].y * inv, vals[v].z * inv, vals[v].w * inv};
            *(float4*)&probs[pbase + cc] = make_float4(p[0], p[1], p[2], p[3]);
            uint32_t w[4];
            #pragma unroll
            for (int e = 0; e < 4; e++) {
                __half h, l;
                split_f16(p[e], h, l);
                w[e] = (uint32_t)__half_as_ushort(h) |
                       ((uint32_t)__half_as_ushort(l) << 16);
            }
            int j  = cc & 15;
            int cg = cc >> 4;
            int p0 = ((j & 4) << 1) | ((j & 8) >> 2);
            int iw = row * PSTR + cg * 16 + p0;
            *(uint2*)&Su[iw]     = make_uint2(w[0], w[1]);
            *(uint2*)&Su[iw + 4] = make_uint2(w[2], w[3]);
        }
    }
    __syncthreads();

    // ---- O = P @ V ----
    float o[2][4];
    #pragma unroll
    for (int am = 0; am < 2; am++)
        #pragma unroll
        for (int e = 0; e < 4; e++) o[am][e] = 0.0f;

    for (int ch = 0; ch < 8; ch++) {
        if (ch < 7) asm volatile("cp.async.wait_group 1;" ::: "memory");
        else        asm volatile("cp.async.wait_group 0;" ::: "memory");
        __syncthreads();
        const uint32_t vb32 = sb + KV_OFF + (ch & 1) * VMAT;
        uint32_t vf[4];
        #pragma unroll
        for (int kk = 0; kk < 8; kk++) {
            if ((kk & 1) == 0) {
                // one ldm.x4 covers 64 k-bytes = 2 kk iterations
                uint32_t vaddr = vb32 + (warp * 8 + r8) * VROW + (kk >> 1) * 64 + t8 * 16;
                ldm_x4(vf, vaddr);
            }
            const uint32_t* vb = vf + 2 * (kk & 1);
            const int cg = ch * 8 + kk;
            #pragma unroll
            for (int am = 0; am < 2; am++) {
                int r = am * 16 + g;
                uint4 U  = *(const uint4*)&Su[r * PSTR + cg * 16 + tig * 4];
                uint4 U2 = *(const uint4*)&Su[(r + 8) * PSTR + cg * 16 + tig * 4];
                uint32_t aH[4] = {__byte_perm(U.x,  U.y,  0x5410), __byte_perm(U2.x, U2.y, 0x5410),
                                  __byte_perm(U.z,  U.w,  0x5410), __byte_perm(U2.z, U2.w, 0x5410)};
                uint32_t aL[4] = {__byte_perm(U.x,  U.y,  0x7632), __byte_perm(U2.x, U2.y, 0x7632),
                                  __byte_perm(U.z,  U.w,  0x7632), __byte_perm(U2.z, U2.w, 0x7632)};
                mma16816(o[am], aH, vb);
                mma16816(o[am], aL, vb);
            }
        }
        __syncthreads();
        if (ch + 2 < 8) load_v((ch + 2) * 128, ch & 1);
    }

    // ---- O epilogue: fp16 hi/lo for Wo gemm ----
    #pragma unroll
    for (int am = 0; am < 2; am++) {
        int row = q0 + am * 16 + g;
        int col = hd * HD + warp * 8 + 2 * tig;
        #pragma unroll
        for (int h = 0; h < 2; h++) {
            size_t off = (tokbase + row + h * 8) * CDIM + col;
            __half h0, l0, h1, l1;
            split_f16(o[am][h * 2 + 0], h0, l0);
            split_f16(o[am][h * 2 + 1], h1, l1);
            __half2 hp; hp.x = h0; hp.y = h1;
            __half2 lp; lp.x = l0; lp.y = l1;
            *(__half2*)(g_oh + off) = hp;
            *(__half2*)(g_ol + off) = lp;
        }
    }
}

// ---------------- launcher ----------------
extern "C" void kernel_launch(void* const* d_in, const int* in_sizes, int n_in,
                              void* d_out, int out_size)
{
    const float* x     = (const float*)d_in[0];
    const float* Wq    = (const float*)d_in[1];
    const float* Wk    = (const float*)d_in[2];
    const float* Wv    = (const float*)d_in[3];
    const float* Wo    = (const float*)d_in[4];
    const float* ln1_g = (const float*)d_in[5];
    const float* ln1_b = (const float*)d_in[6];
    const float* fc1_w = (const float*)d_in[7];
    const float* fc1_b = (const float*)d_in[8];
    const float* fc2_w = (const float*)d_in[9];
    const float* fc2_b = (const float*)d_in[10];
    const float* ln2_g = (const float*)d_in[11];
    const float* ln2_b = (const float*)d_in[12];

    float* out   = (float*)d_out;
    float* probs = out + (size_t)NTOK * CDIM;

    float *p_xn, *p_attn, *p_yn;
    __half *p_xnh, *p_xnl, *p_ynh, *p_ynl, *p_oh, *p_ol, *p_h1h, *p_h1l;
    __half *p_qh, *p_ql, *p_kk, *p_vt;
    __half *p_wqt, *p_wkt, *p_wvt, *p_wot, *p_f1t, *p_f2t;
    cudaGetSymbolAddress((void**)&p_xn,   g_xn);
    cudaGetSymbolAddress((void**)&p_attn, g_attn);
    cudaGetSymbolAddress((void**)&p_yn,   g_yn);
    cudaGetSymbolAddress((void**)&p_xnh,  g_xnh);
    cudaGetSymbolAddress((void**)&p_xnl,  g_xnl);
    cudaGetSymbolAddress((void**)&p_ynh,  g_ynh);
    cudaGetSymbolAddress((void**)&p_ynl,  g_ynl);
    cudaGetSymbolAddress((void**)&p_oh,   g_oh);
    cudaGetSymbolAddress((void**)&p_ol,   g_ol);
    cudaGetSymbolAddress((void**)&p_h1h,  g_h1h);
    cudaGetSymbolAddress((void**)&p_h1l,  g_h1l);
    cudaGetSymbolAddress((void**)&p_qh,   g_qh);
    cudaGetSymbolAddress((void**)&p_ql,   g_ql);
    cudaGetSymbolAddress((void**)&p_kk,   g_kk);
    cudaGetSymbolAddress((void**)&p_vt,   g_vt);
    cudaGetSymbolAddress((void**)&p_wqt,  g_wqt);
    cudaGetSymbolAddress((void**)&p_wkt,  g_wkt);
    cudaGetSymbolAddress((void**)&p_wvt,  g_wvt);
    cudaGetSymbolAddress((void**)&p_wot,  g_wot);
    cudaGetSymbolAddress((void**)&p_f1t,  g_f1t);
    cudaGetSymbolAddress((void**)&p_f2t,  g_f2t);

    cudaFuncSetAttribute(attn_mma,
                         cudaFuncAttributeMaxDynamicSharedMemorySize, ATTN_SMEM);
    cudaFuncSetAttribute(gemm_mma<false, false, false, 1>,
                         cudaFuncAttributeMaxDynamicSharedMemorySize, GT_SMEM);
    cudaFuncSetAttribute(gemm_mma<false, false, false, 2>,
                         cudaFuncAttributeMaxDynamicSharedMemorySize, GT_SMEM);
    cudaFuncSetAttribute(gemm_mma<false, false, false, 3>,
                         cudaFuncAttributeMaxDynamicSharedMemorySize, GT_SMEM);
    cudaFuncSetAttribute(gemm_mma<false, true, false, 0>,
                         cudaFuncAttributeMaxDynamicSharedMemorySize, GT_SMEM);
    cudaFuncSetAttribute(gemm_mma<true, false, true, 1>,
                         cudaFuncAttributeMaxDynamicSharedMemorySize, GT_SMEM);
    cudaFuncSetAttribute(gemm_mma<true, true, false, 0>,
                         cudaFuncAttributeMaxDynamicSharedMemorySize, GT_SMEM);

    // launch 0: LN1
    ln_kernel<<<NTOK, 128>>>(x, ln1_g, ln1_b, p_xn, p_xnh, p_xnl);

    // launch 1: all weight transposes (Wq folded with 1/8)
    transconv_all<<<3072, 256>>>(Wq, Wk, Wv, Wo, fc1_w, fc2_w);

    dim3 g512(CDIM / BN, NTOK / BM);
    // launch 2: Q -> fp16 hi/lo
    gemm_mma<false, false, false, 1><<<g512, 256, GT_SMEM>>>(
        p_xnh, p_xnl, p_wqt, nullptr, nullptr, nullptr, p_qh, p_ql,
        NTOK, CDIM, CDIM);
    // launch 3: K -> single fp16
    gemm_mma<false, false, false, 2><<<g512, 256, GT_SMEM>>>(
        p_xnh, p_xnl, p_wkt, nullptr, nullptr, nullptr, p_kk, nullptr,
        NTOK, CDIM, CDIM);
    // launch 4: V -> transposed single fp16
    gemm_mma<false, false, false, 3><<<g512, 256, GT_SMEM>>>(
        p_xnh, p_xnl, p_wvt, nullptr, nullptr, nullptr, p_vt, nullptr,
        NTOK, CDIM, CDIM);

    // launch 5 (ncu-profiled): attention
    attn_mma<<<dim3(32, NHEAD, NBATCH), 256, ATTN_SMEM>>>(probs);

    // launch 6: attn_out = O @ Wo + xn
    gemm_mma<false, true, false, 0><<<g512, 256, GT_SMEM>>>(
        p_oh, p_ol, p_wot, nullptr, p_xn, p_attn, nullptr, nullptr,
        NTOK, CDIM, CDIM);

    // launch 7: LN2
    ln_kernel<<<NTOK, 128>>>(p_attn, ln2_g, ln2_b, p_yn, p_ynh, p_ynl);

    // launch 8: h1 = relu(yn @ fc1 + b1) -> fp16 hi/lo
    dim3 gff(FFDIM / BN, NTOK / BM);
    gemm_mma<true, false, true, 1><<<gff, 256, GT_SMEM>>>(
        p_ynh, p_ynl, p_f1t, fc1_b, nullptr, nullptr, p_h1h, p_h1l,
        NTOK, FFDIM, CDIM);

    // launch 9: out = h1 @ fc2 + b2 + yn
    gemm_mma<true, true, false, 0><<<g512, 256, GT_SMEM>>>(
        p_h1h, p_h1l, p_f2t, fc2_b, p_yn, out, nullptr, nullptr,
        NTOK, CDIM, FFDIM);
}

// round 11
// speedup vs baseline: 3.7643x; 1.0235x over previous
#include <cuda_runtime.h>
#include <cuda_fp16.h>
#include <math.h>
#include <stdint.h>

// ---------------- problem constants ----------------
#define NTOK   8192
#define CDIM   512
#define FFDIM  2048
#define NHEAD  8
#define HD     64
#define SEQ    1024
#define NBATCH 8

// ---------------- scratch ----------------
__device__ float g_xn  [NTOK * CDIM];
__device__ float g_attn[NTOK * CDIM];
__device__ float g_yn  [NTOK * CDIM];

__device__ __half g_xnh[NTOK * CDIM], g_xnl[NTOK * CDIM];
__device__ __half g_ynh[NTOK * CDIM], g_ynl[NTOK * CDIM];
__device__ __half g_qh [NTOK * CDIM], g_ql [NTOK * CDIM];
__device__ __half g_kk [NTOK * CDIM];                       // K single fp16
__device__ __half g_vt [NTOK * CDIM];                       // V^T single [b*8+h][d][kv]
__device__ __half g_oh [NTOK * CDIM], g_ol [NTOK * CDIM];
__device__ __half g_h1h[NTOK * FFDIM], g_h1l[NTOK * FFDIM];

__device__ __half g_wqt[CDIM * CDIM];
__device__ __half g_wkt[CDIM * CDIM];
__device__ __half g_wvt[CDIM * CDIM];
__device__ __half g_wot[CDIM * CDIM];
__device__ __half g_f1t[CDIM * FFDIM];
__device__ __half g_f2t[FFDIM * CDIM];

// ---------------- helpers ----------------
__device__ __forceinline__ void split_f16(float x, __half& h, __half& l) {
    h = __float2half_rn(x);
    l = __float2half_rn(x - __half2float(h));
}
__device__ __forceinline__ uint32_t smem_u32(const void* p) {
    uint32_t a;
    asm("{ .reg .u64 t; cvta.to.shared.u64 t, %1; cvt.u32.u64 %0, t; }" : "=r"(a) : "l"(p));
    return a;
}
__device__ __forceinline__ void cpa16(uint32_t s, const void* g) {
    asm volatile("cp.async.cg.shared.global [%0], [%1], 16;" :: "r"(s), "l"(g) : "memory");
}
#define CP_COMMIT() asm volatile("cp.async.commit_group;" ::: "memory")

__device__ __forceinline__ void mma16816(float* c, const uint32_t* a, const uint32_t* b) {
    asm volatile("mma.sync.aligned.m16n8k16.row.col.f32.f16.f16.f32 "
        "{%0,%1,%2,%3}, {%4,%5,%6,%7}, {%8,%9}, {%0,%1,%2,%3};"
        : "+f"(c[0]), "+f"(c[1]), "+f"(c[2]), "+f"(c[3])
        : "r"(a[0]), "r"(a[1]), "r"(a[2]), "r"(a[3]), "r"(b[0]), "r"(b[1]));
}
__device__ __forceinline__ void ldm_x4(uint32_t* r, uint32_t addr) {
    asm volatile("ldmatrix.sync.aligned.m8n8.x4.shared.b16 {%0,%1,%2,%3}, [%4];"
        : "=r"(r[0]), "=r"(r[1]), "=r"(r[2]), "=r"(r[3]) : "r"(addr));
}

// ---------------- LayerNorm (fp32 out + fp16 hi/lo) ----------------
__global__ __launch_bounds__(128) void ln_kernel(
    const float* __restrict__ in, const float* __restrict__ gam,
    const float* __restrict__ bet, float* __restrict__ out,
    __half* __restrict__ oh, __half* __restrict__ ol)
{
    const int row = blockIdx.x;
    const int t = threadIdx.x;
    const float4* x4 = (const float4*)(in + (size_t)row * CDIM);
    float4 v = x4[t];
    float s  = v.x + v.y + v.z + v.w;
    float ss = fmaf(v.x, v.x, fmaf(v.y, v.y, fmaf(v.z, v.z, v.w * v.w)));
    #pragma unroll
    for (int o = 16; o > 0; o >>= 1) {
        s  += __shfl_xor_sync(0xffffffffu, s,  o);
        ss += __shfl_xor_sync(0xffffffffu, ss, o);
    }
    __shared__ float sh[4], shh[4];
    const int wid = t >> 5, lane = t & 31;
    if (lane == 0) { sh[wid] = s; shh[wid] = ss; }
    __syncthreads();
    float tot  = sh[0] + sh[1] + sh[2] + sh[3];
    float tot2 = shh[0] + shh[1] + shh[2] + shh[3];
    const float mean = tot * (1.0f / CDIM);
    const float var  = tot2 * (1.0f / CDIM) - mean * mean;
    const float r    = rsqrtf(var + 1e-5f);
    float4 g = ((const float4*)gam)[t];
    float4 b = ((const float4*)bet)[t];
    float o4[4];
    o4[0] = (v.x - mean) * r * g.x + b.x;
    o4[1] = (v.y - mean) * r * g.y + b.y;
    o4[2] = (v.z - mean) * r * g.z + b.z;
    o4[3] = (v.w - mean) * r * g.w + b.w;
    ((float4*)(out + (size_t)row * CDIM))[t] = make_float4(o4[0], o4[1], o4[2], o4[3]);
    size_t base = (size_t)row * CDIM + t * 4;
    #pragma unroll
    for (int e = 0; e < 4; e++) {
        __half h, l;
        split_f16(o4[e], h, l);
        oh[base + e] = h; ol[base + e] = l;
    }
}

// ------------- all weight transposes (single fp16) in ONE launch ----------
__global__ __launch_bounds__(256) void transconv_all(
    const float* __restrict__ Wq, const float* __restrict__ Wk,
    const float* __restrict__ Wv, const float* __restrict__ Wo,
    const float* __restrict__ F1, const float* __restrict__ F2)
{
    const int bid = blockIdx.x;
    const float* W; __half* Th;
    int K, N, nb, idx; float scale = 1.0f;
    if (bid < 1024) {
        int which = bid >> 8; idx = bid & 255; K = 512; N = 512; nb = 16;
        if (which == 0)      { W = Wq; Th = g_wqt; scale = 0.125f; }
        else if (which == 1) { W = Wk; Th = g_wkt; }
        else if (which == 2) { W = Wv; Th = g_wvt; }
        else                 { W = Wo; Th = g_wot; }
    } else if (bid < 2048) {
        idx = bid - 1024; W = F1; Th = g_f1t; K = 512; N = 2048; nb = 64;
    } else {
        idx = bid - 2048; W = F2; Th = g_f2t; K = 2048; N = 512; nb = 16;
    }
    const int n0 = (idx % nb) * 32, k0 = (idx / nb) * 32;
    __shared__ float t[32][33];
    const int tx = threadIdx.x & 31, ty = threadIdx.x >> 5;
    #pragma unroll
    for (int i = 0; i < 4; i++)
        t[ty + i * 8][tx] = W[(size_t)(k0 + ty + i * 8) * N + n0 + tx];
    __syncthreads();
    #pragma unroll
    for (int i = 0; i < 4; i++) {
        int r = ty + i * 8;
        Th[(size_t)(n0 + r) * K + k0 + tx] = __float2half_rn(t[tx][r] * scale);
    }
}

// -------- mma.sync fp16 2-term GEMM, 3-stage single-sync pipeline ---------
#define BM 128
#define BN 128
#define KC 32
#define ROWB 80
#define MAT_BYTES (128 * ROWB)
#define AH_OFF 0
#define AL_OFF MAT_BYTES
#define B_OFF  (2 * MAT_BYTES)
#define STAGE_BYTES (3 * MAT_BYTES)          // 30720
#define GT_SMEM (3 * STAGE_BYTES)            // 92160

// OM: 0 = fp32 Cf; 1 = split fp16 Ch/Cl; 2 = single fp16 Ch; 3 = transposed single fp16
template <bool BIAS, bool RES, bool RELU, int OM>
__global__ __launch_bounds__(256, 2) void gemm_mma(
    const __half* __restrict__ Ah, const __half* __restrict__ Al,
    const __half* __restrict__ B,
    const float* __restrict__ bias, const float* __restrict__ res,
    float* __restrict__ Cf, __half* __restrict__ Ch,
    __half* __restrict__ Cl, int M, int N, int K)
{
    extern __shared__ char sm[];
    const uint32_t sbase = smem_u32(sm);
    const int tid  = threadIdx.x;
    const int lane = tid & 31;
    const int warp = tid >> 5;
    const int wm0  = (warp & 3) * 32;
    const int wn0  = (warp >> 2) * 64;
    const int g    = lane >> 2;
    const int tig  = lane & 3;
    const int t8   = lane >> 3;
    const int r8   = lane & 7;
    const int bm0  = blockIdx.y * BM;
    const int bn0  = blockIdx.x * BN;

    float acc[2][8][4];
    #pragma unroll
    for (int i = 0; i < 2; i++)
        #pragma unroll
        for (int j = 0; j < 8; j++)
            #pragma unroll
            for (int e = 0; e < 4; e++) acc[i][j][e] = 0.0f;

    const __half* gsrc[3] = {Ah, Al, B};

    auto load_stage = [&](int kt, int buf) {
        const uint32_t st = sbase + buf * STAGE_BYTES;
        #pragma unroll
        for (int i = 0; i < 6; i++) {
            int idx = tid + i * 256;              // 0..1535
            int mat = idx >> 9;                   // 0..2
            int rix = idx & 511;
            int r   = rix >> 2;
            int cb  = (rix & 3) * 16;
            int grow = (mat < 2) ? (bm0 + r) : (bn0 + r);
            const char* src = (const char*)(gsrc[mat] + (size_t)grow * K + kt) + cb;
            cpa16(st + mat * MAT_BYTES + r * ROWB + cb, src);
        }
        CP_COMMIT();
    };

    const int S = K / KC;
    load_stage(0, 0);
    load_stage(KC, 1);

    int buf = 0;
    for (int s = 0; s < S; s++) {
        if (s + 1 < S) asm volatile("cp.async.wait_group 1;" ::: "memory");
        else           asm volatile("cp.async.wait_group 0;" ::: "memory");
        __syncthreads();
        // issue next load into the idle buffer (read last at stage s-1;
        // all warps finished s-1 because they passed this barrier)
        if (s + 2 < S) {
            int nb = buf + 2; if (nb >= 3) nb -= 3;
            load_stage((s + 2) * KC, nb);
        }

        const uint32_t sb32 = sbase + buf * STAGE_BYTES;
        #pragma unroll
        for (int kk = 0; kk < 2; kk++) {
            const int kbyte = kk * 32;
            uint32_t aH[2][4], aL[2][4];
            #pragma unroll
            for (int am = 0; am < 2; am++) {
                uint32_t arow = wm0 + am * 16 + (t8 & 1) * 8 + r8;
                uint32_t acol = kbyte + (t8 >> 1) * 16;
                ldm_x4(aH[am], sb32 + AH_OFF + arow * ROWB + acol);
                ldm_x4(aL[am], sb32 + AL_OFF + arow * ROWB + acol);
            }
            #pragma unroll
            for (int bn2 = 0; bn2 < 4; bn2++) {
                uint32_t brow = wn0 + (2 * bn2 + (t8 >> 1)) * 8 + r8;
                uint32_t bcol = kbyte + (t8 & 1) * 16;
                uint32_t b4[4];
                ldm_x4(b4, sb32 + B_OFF + brow * ROWB + bcol);
                #pragma unroll
                for (int half = 0; half < 2; half++) {
                    const int bn = 2 * bn2 + half;
                    const uint32_t* b = b4 + 2 * half;
                    mma16816(acc[0][bn], aH[0], b);
                    mma16816(acc[0][bn], aL[0], b);
                    mma16816(acc[1][bn], aH[1], b);
                    mma16816(acc[1][bn], aL[1], b);
                }
            }
        }
        if (++buf == 3) buf = 0;
    }

    // epilogue
    #pragma unroll
    for (int am = 0; am < 2; am++) {
        #pragma unroll
        for (int bn = 0; bn < 8; bn++) {
            const int row = bm0 + wm0 + am * 16 + g;
            const int col = bn0 + wn0 + bn * 8 + 2 * tig;
            float* c = acc[am][bn];
            #pragma unroll
            for (int h = 0; h < 2; h++) {
                const int r = row + h * 8;
                float v0 = c[h * 2 + 0];
                float v1 = c[h * 2 + 1];
                if (BIAS) { v0 += bias[col]; v1 += bias[col + 1]; }
                if (RES) {
                    float2 rr = *(const float2*)&res[(size_t)r * N + col];
                    v0 += rr.x; v1 += rr.y;
                }
                if (RELU) { v0 = fmaxf(v0, 0.f); v1 = fmaxf(v1, 0.f); }
                if (OM == 3) {
                    int bb = r >> 10, kv = r & 1023;
                    int head = col >> 6, d = col & 63;
                    size_t tb = ((size_t)(bb * 8 + head) * 64 + d) * 1024 + kv;
                    Ch[tb]        = __float2half_rn(v0);
                    Ch[tb + 1024] = __float2half_rn(v1);
                } else if (OM == 2) {
                    __half2 hp; hp.x = __float2half_rn(v0); hp.y = __float2half_rn(v1);
                    *(__half2*)(Ch + (size_t)r * N + col) = hp;
                } else if (OM == 1) {
                    __half h0, l0, h1, l1;
                    split_f16(v0, h0, l0);
                    split_f16(v1, h1, l1);
                    __half2 hp; hp.x = h0; hp.y = h1;
                    __half2 lp; lp.x = l0; lp.y = l1;
                    *(__half2*)(Ch + (size_t)r * N + col) = hp;
                    *(__half2*)(Cl + (size_t)r * N + col) = lp;
                } else {
                    *(float2*)&Cf[(size_t)r * N + col] = make_float2(v0, v1);
                }
            }
        }
    }
}

// -------- mma attention (fp16; 3-stage single-sync K/V pipelines) ---------
#define PSTR    1040
#define S_BYTES (32 * PSTR * 4)              // 133120
#define Q_OFF   S_BYTES
#define QROW    144
#define Q_BYTES (2 * 32 * QROW)              // 9216
#define KV_OFF  (Q_OFF + Q_BYTES)            // 142336
#define KROW 144
#define KMAT (128 * KROW)                    // 18432
#define VROW 272
#define VMAT (64 * VROW)                     // 17408
#define ATTN_SMEM (KV_OFF + 3 * KMAT)        // 197632

__global__ __launch_bounds__(256, 1) void attn_mma(float* __restrict__ probs)
{
    extern __shared__ char sm[];
    float* S = (float*)sm;
    uint32_t* Su = (uint32_t*)sm;
    const uint32_t sb = smem_u32(sm);
    const int tid = threadIdx.x, lane = tid & 31, warp = tid >> 5;
    const int g = lane >> 2, tig = lane & 3;
    const int t8 = lane >> 3, r8 = lane & 7;
    const int qb = blockIdx.x, hd = blockIdx.y, b = blockIdx.z;
    const int q0 = qb * 32;
    const size_t tokbase = (size_t)b * SEQ;

    // Q tile (hi/lo) -> smem
    #pragma unroll
    for (int i = 0; i < 2; i++) {
        int idx = tid + i * 256;
        int mat = idx >> 8;
        int rix = idx & 255;
        int r = rix >> 3, v = (rix & 7) * 16;
        const __half* src = mat ? g_ql : g_qh;
        const char* sp = (const char*)(src + (tokbase + q0 + r) * CDIM + hd * HD) + v;
        *(uint4*)(sm + Q_OFF + mat * 32 * QROW + r * QROW + v) = *(const uint4*)sp;
    }

    auto load_k = [&](int kv0, int buf) {
        const uint32_t st = sb + KV_OFF + buf * KMAT;
        #pragma unroll
        for (int i = 0; i < 4; i++) {
            int idx = tid + i * 256;              // 0..1023
            int r = idx >> 3, v = (idx & 7) * 16;
            const char* sp = (const char*)(g_kk + (tokbase + kv0 + r) * CDIM + hd * HD) + v;
            cpa16(st + r * KROW + v, sp);
        }
        CP_COMMIT();
    };
    auto load_v = [&](int kv0, int buf) {
        const uint32_t st = sb + KV_OFF + buf * VMAT;
        #pragma unroll
        for (int i = 0; i < 4; i++) {
            int idx = tid + i * 256;              // 0..1023
            int r = idx >> 4, v = (idx & 15) * 16;
            const char* sp = (const char*)(g_vt + ((size_t)(b * 8 + hd) * 64 + r) * SEQ + kv0) + v;
            cpa16(st + r * VROW + v, sp);
        }
        CP_COMMIT();
    };

    load_k(0, 0);
    load_k(128, 1);

    const uint32_t sbQ = sb + Q_OFF;

    // ---- scores S = Q @ K^T (Wq pre-scaled by 1/8) ----
    int kbuf = 0;
    for (int ch = 0; ch < 8; ch++) {
        if (ch < 7) asm volatile("cp.async.wait_group 1;" ::: "memory");
        else        asm volatile("cp.async.wait_group 0;" ::: "memory");
        __syncthreads();
        if (ch + 2 < 8) {
            int nb = kbuf + 2; if (nb >= 3) nb -= 3;
            load_k((ch + 2) * 128, nb);
        }
        const uint32_t kb32 = sb + KV_OFF + kbuf * KMAT;
        float c[2][2][4];
        #pragma unroll
        for (int am = 0; am < 2; am++)
            #pragma unroll
            for (int nt = 0; nt < 2; nt++)
                #pragma unroll
                for (int e = 0; e < 4; e++) c[am][nt][e] = 0.0f;

        #pragma unroll
        for (int kk = 0; kk < 4; kk++) {
            const int kbyte = kk * 32;
            uint32_t aH[2][4], aL[2][4];
            #pragma unroll
            for (int am = 0; am < 2; am++) {
                uint32_t arow = am * 16 + (t8 & 1) * 8 + r8;
                uint32_t acol = kbyte + (t8 >> 1) * 16;
                ldm_x4(aH[am], sbQ + arow * QROW + acol);
                ldm_x4(aL[am], sbQ + 32 * QROW + arow * QROW + acol);
            }
            uint32_t krow = warp * 16 + (t8 >> 1) * 8 + r8;
            uint32_t kaddr = kb32 + krow * KROW + kbyte + (t8 & 1) * 16;
            uint32_t kf[4];
            ldm_x4(kf, kaddr);
            #pragma unroll
            for (int nt = 0; nt < 2; nt++) {
                #pragma unroll
                for (int am = 0; am < 2; am++) {
                    mma16816(c[am][nt], aH[am], kf + 2 * nt);
                    mma16816(c[am][nt], aL[am], kf + 2 * nt);
                }
            }
        }
        #pragma unroll
        for (int am = 0; am < 2; am++)
            #pragma unroll
            for (int nt = 0; nt < 2; nt++) {
                int row = am * 16 + g;
                int col = ch * 128 + warp * 16 + nt * 8 + 2 * tig;
                *(float2*)&S[row * PSTR + col] =
                    make_float2(c[am][nt][0], c[am][nt][1]);
                *(float2*)&S[(row + 8) * PSTR + col] =
                    make_float2(c[am][nt][2], c[am][nt][3]);
            }
        if (++kbuf == 3) kbuf = 0;
    }

    // all K reads + S writes complete before V loads overwrite KV region /
    // softmax reads S rows written by other warps
    __syncthreads();
    load_v(0, 0);
    load_v(128, 1);

    // ---- softmax; write probs; write permuted packed P (hi|lo fp16) ----
    #pragma unroll
    for (int rr = 0; rr < 4; rr++) {
        int row = warp * 4 + rr;
        float4 vals[8];
        float mx = -1e30f;
        #pragma unroll
        for (int v = 0; v < 8; v++) {
            vals[v] = *(float4*)&S[row * PSTR + (v * 32 + lane) * 4];
            mx = fmaxf(mx, fmaxf(fmaxf(vals[v].x, vals[v].y), fmaxf(vals[v].z, vals[v].w)));
        }
        #pragma unroll
        for (int o = 16; o > 0; o >>= 1) mx = fmaxf(mx, __shfl_xor_sync(0xffffffffu, mx, o));
        float sum = 0.f;
        #pragma unroll
        for (int v = 0; v < 8; v++) {
            vals[v].x = __expf(vals[v].x - mx);
            vals[v].y = __expf(vals[v].y - mx);
            vals[v].z = __expf(vals[v].z - mx);
            vals[v].w = __expf(vals[v].w - mx);
            sum += vals[v].x + vals[v].y + vals[v].z + vals[v].w;
        }
        #pragma unroll
        for (int o = 16; o > 0; o >>= 1) sum += __shfl_xor_sync(0xffffffffu, sum, o);
        float inv = 1.0f / sum;
        size_t pbase = ((tokbase + q0 + row) * NHEAD + hd) * SEQ;
        #pragma unroll
        for (int v = 0; v < 8; v++) {
            int cc = (v * 32 + lane) * 4;
            float p[4] = {vals[v].x * inv, vals[v].y * inv, vals[v].z * inv, vals[v].w * inv};
            *(float4*)&probs[pbase + cc] = make_float4(p[0], p[1], p[2], p[3]);
            uint32_t w[4];
            #pragma unroll
            for (int e = 0; e < 4; e++) {
                __half h, l;
                split_f16(p[e], h, l);
                w[e] = (uint32_t)__half_as_ushort(h) |
                       ((uint32_t)__half_as_ushort(l) << 16);
            }
            int j  = cc & 15;
            int cg = cc >> 4;
            int p0 = ((j & 4) << 1) | ((j & 8) >> 2);
            int iw = row * PSTR + cg * 16 + p0;
            *(uint2*)&Su[iw]     = make_uint2(w[0], w[1]);
            *(uint2*)&Su[iw + 4] = make_uint2(w[2], w[3]);
        }
    }
    __syncthreads();

    // ---- O = P @ V ----
    float o[2][4];
    #pragma unroll
    for (int am = 0; am < 2; am++)
        #pragma unroll
        for (int e = 0; e < 4; e++) o[am][e] = 0.0f;

    int vbuf = 0;
    for (int ch = 0; ch < 8; ch++) {
        if (ch < 7) asm volatile("cp.async.wait_group 1;" ::: "memory");
        else        asm volatile("cp.async.wait_group 0;" ::: "memory");
        __syncthreads();
        if (ch + 2 < 8) {
            int nb = vbuf + 2; if (nb >= 3) nb -= 3;
            load_v((ch + 2) * 128, nb);
        }
        const uint32_t vb32 = sb + KV_OFF + vbuf * VMAT;
        uint32_t vf[4];
        #pragma unroll
        for (int kk = 0; kk < 8; kk++) {
            if ((kk & 1) == 0) {
                uint32_t vaddr = vb32 + (warp * 8 + r8) * VROW + (kk >> 1) * 64 + t8 * 16;
                ldm_x4(vf, vaddr);
            }
            const uint32_t* vb = vf + 2 * (kk & 1);
            const int cg = ch * 8 + kk;
            #pragma unroll
            for (int am = 0; am < 2; am++) {
                int r = am * 16 + g;
                uint4 U  = *(const uint4*)&Su[r * PSTR + cg * 16 + tig * 4];
                uint4 U2 = *(const uint4*)&Su[(r + 8) * PSTR + cg * 16 + tig * 4];
                uint32_t aH[4] = {__byte_perm(U.x,  U.y,  0x5410), __byte_perm(U2.x, U2.y, 0x5410),
                                  __byte_perm(U.z,  U.w,  0x5410), __byte_perm(U2.z, U2.w, 0x5410)};
                uint32_t aL[4] = {__byte_perm(U.x,  U.y,  0x7632), __byte_perm(U2.x, U2.y, 0x7632),
                                  __byte_perm(U.z,  U.w,  0x7632), __byte_perm(U2.z, U2.w, 0x7632)};
                mma16816(o[am], aH, vb);
                mma16816(o[am], aL, vb);
            }
        }
        if (++vbuf == 3) vbuf = 0;
    }

    // ---- O epilogue: fp16 hi/lo for Wo gemm ----
    #pragma unroll
    for (int am = 0; am < 2; am++) {
        int row = q0 + am * 16 + g;
        int col = hd * HD + warp * 8 + 2 * tig;
        #pragma unroll
        for (int h = 0; h < 2; h++) {
            size_t off = (tokbase + row + h * 8) * CDIM + col;
            __half h0, l0, h1, l1;
            split_f16(o[am][h * 2 + 0], h0, l0);
            split_f16(o[am][h * 2 + 1], h1, l1);
            __half2 hp; hp.x = h0; hp.y = h1;
            __half2 lp; lp.x = l0; lp.y = l1;
            *(__half2*)(g_oh + off) = hp;
            *(__half2*)(g_ol + off) = lp;
        }
    }
}

// ---------------- launcher ----------------
extern "C" void kernel_launch(void* const* d_in, const int* in_sizes, int n_in,
                              void* d_out, int out_size)
{
    const float* x     = (const float*)d_in[0];
    const float* Wq    = (const float*)d_in[1];
    const float* Wk    = (const float*)d_in[2];
    const float* Wv    = (const float*)d_in[3];
    const float* Wo    = (const float*)d_in[4];
    const float* ln1_g = (const float*)d_in[5];
    const float* ln1_b = (const float*)d_in[6];
    const float* fc1_w = (const float*)d_in[7];
    const float* fc1_b = (const float*)d_in[8];
    const float* fc2_w = (const float*)d_in[9];
    const float* fc2_b = (const float*)d_in[10];
    const float* ln2_g = (const float*)d_in[11];
    const float* ln2_b = (const float*)d_in[12];

    float* out   = (float*)d_out;
    float* probs = out + (size_t)NTOK * CDIM;

    float *p_xn, *p_attn, *p_yn;
    __half *p_xnh, *p_xnl, *p_ynh, *p_ynl, *p_oh, *p_ol, *p_h1h, *p_h1l;
    __half *p_qh, *p_ql, *p_kk, *p_vt;
    __half *p_wqt, *p_wkt, *p_wvt, *p_wot, *p_f1t, *p_f2t;
    cudaGetSymbolAddress((void**)&p_xn,   g_xn);
    cudaGetSymbolAddress((void**)&p_attn, g_attn);
    cudaGetSymbolAddress((void**)&p_yn,   g_yn);
    cudaGetSymbolAddress((void**)&p_xnh,  g_xnh);
    cudaGetSymbolAddress((void**)&p_xnl,  g_xnl);
    cudaGetSymbolAddress((void**)&p_ynh,  g_ynh);
    cudaGetSymbolAddress((void**)&p_ynl,  g_ynl);
    cudaGetSymbolAddress((void**)&p_oh,   g_oh);
    cudaGetSymbolAddress((void**)&p_ol,   g_ol);
    cudaGetSymbolAddress((void**)&p_h1h,  g_h1h);
    cudaGetSymbolAddress((void**)&p_h1l,  g_h1l);
    cudaGetSymbolAddress((void**)&p_qh,   g_qh);
    cudaGetSymbolAddress((void**)&p_ql,   g_ql);
    cudaGetSymbolAddress((void**)&p_kk,   g_kk);
    cudaGetSymbolAddress((void**)&p_vt,   g_vt);
    cudaGetSymbolAddress((void**)&p_wqt,  g_wqt);
    cudaGetSymbolAddress((void**)&p_wkt,  g_wkt);
    cudaGetSymbolAddress((void**)&p_wvt,  g_wvt);
    cudaGetSymbolAddress((void**)&p_wot,  g_wot);
    cudaGetSymbolAddress((void**)&p_f1t,  g_f1t);
    cudaGetSymbolAddress((void**)&p_f2t,  g_f2t);

    cudaFuncSetAttribute(attn_mma,
                         cudaFuncAttributeMaxDynamicSharedMemorySize, ATTN_SMEM);
    cudaFuncSetAttribute(gemm_mma<false, false, false, 1>,
                         cudaFuncAttributeMaxDynamicSharedMemorySize, GT_SMEM);
    cudaFuncSetAttribute(gemm_mma<false, false, false, 2>,
                         cudaFuncAttributeMaxDynamicSharedMemorySize, GT_SMEM);
    cudaFuncSetAttribute(gemm_mma<false, false, false, 3>,
                         cudaFuncAttributeMaxDynamicSharedMemorySize, GT_SMEM);
    cudaFuncSetAttribute(gemm_mma<false, true, false, 0>,
                         cudaFuncAttributeMaxDynamicSharedMemorySize, GT_SMEM);
    cudaFuncSetAttribute(gemm_mma<true, false, true, 1>,
                         cudaFuncAttributeMaxDynamicSharedMemorySize, GT_SMEM);
    cudaFuncSetAttribute(gemm_mma<true, true, false, 0>,
                         cudaFuncAttributeMaxDynamicSharedMemorySize, GT_SMEM);

    // launch 0: LN1
    ln_kernel<<<NTOK, 128>>>(x, ln1_g, ln1_b, p_xn, p_xnh, p_xnl);

    // launch 1: all weight transposes (Wq folded with 1/8)
    transconv_all<<<3072, 256>>>(Wq, Wk, Wv, Wo, fc1_w, fc2_w);

    dim3 g512(CDIM / BN, NTOK / BM);
    // launch 2: Q -> fp16 hi/lo
    gemm_mma<false, false, false, 1><<<g512, 256, GT_SMEM>>>(
        p_xnh, p_xnl, p_wqt, nullptr, nullptr, nullptr, p_qh, p_ql,
        NTOK, CDIM, CDIM);
    // launch 3: K -> single fp16
    gemm_mma<false, false, false, 2><<<g512, 256, GT_SMEM>>>(
        p_xnh, p_xnl, p_wkt, nullptr, nullptr, nullptr, p_kk, nullptr,
        NTOK, CDIM, CDIM);
    // launch 4: V -> transposed single fp16
    gemm_mma<false, false, false, 3><<<g512, 256, GT_SMEM>>>(
        p_xnh, p_xnl, p_wvt, nullptr, nullptr, nullptr, p_vt, nullptr,
        NTOK, CDIM, CDIM);

    // launch 5 (ncu-profiled): attention
    attn_mma<<<dim3(32, NHEAD, NBATCH), 256, ATTN_SMEM>>>(probs);

    // launch 6: attn_out = O @ Wo + xn
    gemm_mma<false, true, false, 0><<<g512, 256, GT_SMEM>>>(
        p_oh, p_ol, p_wot, nullptr, p_xn, p_attn, nullptr, nullptr,
        NTOK, CDIM, CDIM);

    // launch 7: LN2
    ln_kernel<<<NTOK, 128>>>(p_attn, ln2_g, ln2_b, p_yn, p_ynh, p_ynl);

    // launch 8: h1 = relu(yn @ fc1 + b1) -> fp16 hi/lo
    dim3 gff(FFDIM / BN, NTOK / BM);
    gemm_mma<true, false, true, 1><<<gff, 256, GT_SMEM>>>(
        p_ynh, p_ynl, p_f1t, fc1_b, nullptr, nullptr, p_h1h, p_h1l,
        NTOK, FFDIM, CDIM);

    // launch 9: out = h1 @ fc2 + b2 + yn
    gemm_mma<true, true, false, 0><<<g512, 256, GT_SMEM>>>(
        p_h1h, p_h1l, p_f2t, fc2_b, p_yn, out, nullptr, nullptr,
        NTOK, CDIM, FFDIM);
}

// round 12
// speedup vs baseline: 5.4726x; 1.4538x over previous
#include <cuda_runtime.h>
#include <cuda_fp16.h>
#include <math.h>
#include <stdint.h>

// ---------------- problem constants ----------------
#define NTOK   8192
#define CDIM   512
#define FFDIM  2048
#define NHEAD  8
#define HD     64
#define SEQ    1024
#define NBATCH 8

// ---------------- scratch ----------------
__device__ float g_xn  [NTOK * CDIM];
__device__ float g_attn[NTOK * CDIM];
__device__ float g_yn  [NTOK * CDIM];

__device__ __half g_xnf[NTOK * CDIM];
__device__ __half g_ynf[NTOK * CDIM];
__device__ __half g_q  [NTOK * CDIM];
__device__ __half g_k  [NTOK * CDIM];
__device__ __half g_vt [NTOK * CDIM];     // V^T [b*8+h][d][kv]
__device__ __half g_o  [NTOK * CDIM];
__device__ __half g_h1 [NTOK * FFDIM];

__device__ __half g_wqt[CDIM * CDIM];
__device__ __half g_wkt[CDIM * CDIM];
__device__ __half g_wvt[CDIM * CDIM];
__device__ __half g_wot[CDIM * CDIM];
__device__ __half g_f1t[CDIM * FFDIM];
__device__ __half g_f2t[FFDIM * CDIM];

// ---------------- helpers ----------------
__device__ __forceinline__ uint32_t smem_u32(const void* p) {
    uint32_t a;
    asm("{ .reg .u64 t; cvta.to.shared.u64 t, %1; cvt.u32.u64 %0, t; }" : "=r"(a) : "l"(p));
    return a;
}
__device__ __forceinline__ void cpa16(uint32_t s, const void* g) {
    asm volatile("cp.async.cg.shared.global [%0], [%1], 16;" :: "r"(s), "l"(g) : "memory");
}
#define CP_COMMIT() asm volatile("cp.async.commit_group;" ::: "memory")

__device__ __forceinline__ void mma16816(float* c, const uint32_t* a, const uint32_t* b) {
    asm volatile("mma.sync.aligned.m16n8k16.row.col.f32.f16.f16.f32 "
        "{%0,%1,%2,%3}, {%4,%5,%6,%7}, {%8,%9}, {%0,%1,%2,%3};"
        : "+f"(c[0]), "+f"(c[1]), "+f"(c[2]), "+f"(c[3])
        : "r"(a[0]), "r"(a[1]), "r"(a[2]), "r"(a[3]), "r"(b[0]), "r"(b[1]));
}
__device__ __forceinline__ void ldm_x4(uint32_t* r, uint32_t addr) {
    asm volatile("ldmatrix.sync.aligned.m8n8.x4.shared.b16 {%0,%1,%2,%3}, [%4];"
        : "=r"(r[0]), "=r"(r[1]), "=r"(r[2]), "=r"(r[3]) : "r"(addr));
}

// ---------------- LayerNorm (fp32 out + fp16) ----------------
__global__ __launch_bounds__(128) void ln_kernel(
    const float* __restrict__ in, const float* __restrict__ gam,
    const float* __restrict__ bet, float* __restrict__ out,
    __half* __restrict__ oh)
{
    const int row = blockIdx.x;
    const int t = threadIdx.x;
    const float4* x4 = (const float4*)(in + (size_t)row * CDIM);
    float4 v = x4[t];
    float s  = v.x + v.y + v.z + v.w;
    float ss = fmaf(v.x, v.x, fmaf(v.y, v.y, fmaf(v.z, v.z, v.w * v.w)));
    #pragma unroll
    for (int o = 16; o > 0; o >>= 1) {
        s  += __shfl_xor_sync(0xffffffffu, s,  o);
        ss += __shfl_xor_sync(0xffffffffu, ss, o);
    }
    __shared__ float sh[4], shh[4];
    const int wid = t >> 5, lane = t & 31;
    if (lane == 0) { sh[wid] = s; shh[wid] = ss; }
    __syncthreads();
    float tot  = sh[0] + sh[1] + sh[2] + sh[3];
    float tot2 = shh[0] + shh[1] + shh[2] + shh[3];
    const float mean = tot * (1.0f / CDIM);
    const float var  = tot2 * (1.0f / CDIM) - mean * mean;
    const float r    = rsqrtf(var + 1e-5f);
    float4 g = ((const float4*)gam)[t];
    float4 b = ((const float4*)bet)[t];
    float o4[4];
    o4[0] = (v.x - mean) * r * g.x + b.x;
    o4[1] = (v.y - mean) * r * g.y + b.y;
    o4[2] = (v.z - mean) * r * g.z + b.z;
    o4[3] = (v.w - mean) * r * g.w + b.w;
    ((float4*)(out + (size_t)row * CDIM))[t] = make_float4(o4[0], o4[1], o4[2], o4[3]);
    size_t base = (size_t)row * CDIM + t * 4;
    __half2 p0; p0.x = __float2half_rn(o4[0]); p0.y = __float2half_rn(o4[1]);
    __half2 p1; p1.x = __float2half_rn(o4[2]); p1.y = __float2half_rn(o4[3]);
    *(__half2*)(oh + base)     = p0;
    *(__half2*)(oh + base + 2) = p1;
}

// ------------- all weight transposes (fp16) in ONE launch ----------
__global__ __launch_bounds__(256) void transconv_all(
    const float* __restrict__ Wq, const float* __restrict__ Wk,
    const float* __restrict__ Wv, const float* __restrict__ Wo,
    const float* __restrict__ F1, const float* __restrict__ F2)
{
    const int bid = blockIdx.x;
    const float* W; __half* Th;
    int K, N, nb, idx; float scale = 1.0f;
    if (bid < 1024) {
        int which = bid >> 8; idx = bid & 255; K = 512; N = 512; nb = 16;
        if (which == 0)      { W = Wq; Th = g_wqt; scale = 0.125f; }
        else if (which == 1) { W = Wk; Th = g_wkt; }
        else if (which == 2) { W = Wv; Th = g_wvt; }
        else                 { W = Wo; Th = g_wot; }
    } else if (bid < 2048) {
        idx = bid - 1024; W = F1; Th = g_f1t; K = 512; N = 2048; nb = 64;
    } else {
        idx = bid - 2048; W = F2; Th = g_f2t; K = 2048; N = 512; nb = 16;
    }
    const int n0 = (idx % nb) * 32, k0 = (idx / nb) * 32;
    __shared__ float t[32][33];
    const int tx = threadIdx.x & 31, ty = threadIdx.x >> 5;
    #pragma unroll
    for (int i = 0; i < 4; i++)
        t[ty + i * 8][tx] = W[(size_t)(k0 + ty + i * 8) * N + n0 + tx];
    __syncthreads();
    #pragma unroll
    for (int i = 0; i < 4; i++) {
        int r = ty + i * 8;
        Th[(size_t)(n0 + r) * K + k0 + tx] = __float2half_rn(t[tx][r] * scale);
    }
}

// -------- mma.sync fp16 GEMM: C = A16 @ B16^T, 3-stage pipeline -----------
#define BM 128
#define BN 128
#define KC 32
#define ROWB 80
#define MAT_BYTES (128 * ROWB)
#define A_OFF 0
#define B_OFF MAT_BYTES
#define STAGE_BYTES (2 * MAT_BYTES)          // 20480
#define GT_SMEM (3 * STAGE_BYTES)            // 61440

// OM: 0 = fp32 Cf; 2 = fp16 Ch; 3 = transposed fp16 Ch
template <bool BIAS, bool RES, bool RELU, int OM>
__global__ __launch_bounds__(256, 2) void gemm_mma(
    const __half* __restrict__ A, const __half* __restrict__ B,
    const float* __restrict__ bias, const float* __restrict__ res,
    float* __restrict__ Cf, __half* __restrict__ Ch, int M, int N, int K)
{
    extern __shared__ char sm[];
    const uint32_t sbase = smem_u32(sm);
    const int tid  = threadIdx.x;
    const int lane = tid & 31;
    const int warp = tid >> 5;
    const int wm0  = (warp & 3) * 32;
    const int wn0  = (warp >> 2) * 64;
    const int g    = lane >> 2;
    const int tig  = lane & 3;
    const int t8   = lane >> 3;
    const int r8   = lane & 7;
    const int bm0  = blockIdx.y * BM;
    const int bn0  = blockIdx.x * BN;

    float acc[2][8][4];
    #pragma unroll
    for (int i = 0; i < 2; i++)
        #pragma unroll
        for (int j = 0; j < 8; j++)
            #pragma unroll
            for (int e = 0; e < 4; e++) acc[i][j][e] = 0.0f;

    auto load_stage = [&](int kt, int buf) {
        const uint32_t st = sbase + buf * STAGE_BYTES;
        #pragma unroll
        for (int i = 0; i < 4; i++) {
            int idx = tid + i * 256;              // 0..1023
            int mat = idx >> 9;                   // 0..1
            int rix = idx & 511;
            int r   = rix >> 2;
            int cb  = (rix & 3) * 16;
            const __half* gs = mat ? B : A;
            int grow = mat ? (bn0 + r) : (bm0 + r);
            const char* src = (const char*)(gs + (size_t)grow * K + kt) + cb;
            cpa16(st + mat * MAT_BYTES + r * ROWB + cb, src);
        }
        CP_COMMIT();
    };

    const int S = K / KC;
    load_stage(0, 0);
    load_stage(KC, 1);

    int buf = 0;
    for (int s = 0; s < S; s++) {
        if (s + 1 < S) asm volatile("cp.async.wait_group 1;" ::: "memory");
        else           asm volatile("cp.async.wait_group 0;" ::: "memory");
        __syncthreads();
        if (s + 2 < S) {
            int nb = buf + 2; if (nb >= 3) nb -= 3;
            load_stage((s + 2) * KC, nb);
        }

        const uint32_t sb32 = sbase + buf * STAGE_BYTES;
        #pragma unroll
        for (int kk = 0; kk < 2; kk++) {
            const int kbyte = kk * 32;
            uint32_t aF[2][4];
            #pragma unroll
            for (int am = 0; am < 2; am++) {
                uint32_t arow = wm0 + am * 16 + (t8 & 1) * 8 + r8;
                uint32_t acol = kbyte + (t8 >> 1) * 16;
                ldm_x4(aF[am], sb32 + A_OFF + arow * ROWB + acol);
            }
            #pragma unroll
            for (int bn2 = 0; bn2 < 4; bn2++) {
                uint32_t brow = wn0 + (2 * bn2 + (t8 >> 1)) * 8 + r8;
                uint32_t bcol = kbyte + (t8 & 1) * 16;
                uint32_t b4[4];
                ldm_x4(b4, sb32 + B_OFF + brow * ROWB + bcol);
                #pragma unroll
                for (int half = 0; half < 2; half++) {
                    const int bn = 2 * bn2 + half;
                    const uint32_t* b = b4 + 2 * half;
                    mma16816(acc[0][bn], aF[0], b);
                    mma16816(acc[1][bn], aF[1], b);
                }
            }
        }
        if (++buf == 3) buf = 0;
    }

    // epilogue
    #pragma unroll
    for (int am = 0; am < 2; am++) {
        #pragma unroll
        for (int bn = 0; bn < 8; bn++) {
            const int row = bm0 + wm0 + am * 16 + g;
            const int col = bn0 + wn0 + bn * 8 + 2 * tig;
            float* c = acc[am][bn];
            #pragma unroll
            for (int h = 0; h < 2; h++) {
                const int r = row + h * 8;
                float v0 = c[h * 2 + 0];
                float v1 = c[h * 2 + 1];
                if (BIAS) { v0 += bias[col]; v1 += bias[col + 1]; }
                if (RES) {
                    float2 rr = *(const float2*)&res[(size_t)r * N + col];
                    v0 += rr.x; v1 += rr.y;
                }
                if (RELU) { v0 = fmaxf(v0, 0.f); v1 = fmaxf(v1, 0.f); }
                if (OM == 3) {
                    int bb = r >> 10, kv = r & 1023;
                    int head = col >> 6, d = col & 63;
                    size_t tb = ((size_t)(bb * 8 + head) * 64 + d) * 1024 + kv;
                    Ch[tb]        = __float2half_rn(v0);
                    Ch[tb + 1024] = __float2half_rn(v1);
                } else if (OM == 2) {
                    __half2 hp; hp.x = __float2half_rn(v0); hp.y = __float2half_rn(v1);
                    *(__half2*)(Ch + (size_t)r * N + col) = hp;
                } else {
                    *(float2*)&Cf[(size_t)r * N + col] = make_float2(v0, v1);
                }
            }
        }
    }
}

// -------- mma attention (single fp16 Q/K/V/P) -----------------------------
#define PSTR    1040                         // float/word stride per row
#define S_BYTES (32 * PSTR * 4)              // 133120
#define Q_OFF   S_BYTES
#define QROW    144
#define Q_BYTES (32 * QROW)                  // 4608
#define KV_OFF  (Q_OFF + Q_BYTES)            // 137728
#define KROW 144
#define KMAT (128 * KROW)                    // 18432
#define VROW 272
#define VMAT (64 * VROW)                     // 17408
#define ATTN_SMEM (KV_OFF + 3 * KMAT)        // 193024

__global__ __launch_bounds__(256, 1) void attn_mma(float* __restrict__ probs)
{
    extern __shared__ char sm[];
    float* S = (float*)sm;
    uint32_t* Su = (uint32_t*)sm;
    const uint32_t sb = smem_u32(sm);
    const int tid = threadIdx.x, lane = tid & 31, warp = tid >> 5;
    const int g = lane >> 2, tig = lane & 3;
    const int t8 = lane >> 3, r8 = lane & 7;
    const int qb = blockIdx.x, hd = blockIdx.y, b = blockIdx.z;
    const int q0 = qb * 32;
    const size_t tokbase = (size_t)b * SEQ;

    // Q tile -> smem (32 rows x 128 B)
    {
        int r = tid >> 3, v = (tid & 7) * 16;
        const char* sp = (const char*)(g_q + (tokbase + q0 + r) * CDIM + hd * HD) + v;
        *(uint4*)(sm + Q_OFF + r * QROW + v) = *(const uint4*)sp;
    }

    auto load_k = [&](int kv0, int buf) {
        const uint32_t st = sb + KV_OFF + buf * KMAT;
        #pragma unroll
        for (int i = 0; i < 4; i++) {
            int idx = tid + i * 256;
            int r = idx >> 3, v = (idx & 7) * 16;
            const char* sp = (const char*)(g_k + (tokbase + kv0 + r) * CDIM + hd * HD) + v;
            cpa16(st + r * KROW + v, sp);
        }
        CP_COMMIT();
    };
    auto load_v = [&](int kv0, int buf) {
        const uint32_t st = sb + KV_OFF + buf * VMAT;
        #pragma unroll
        for (int i = 0; i < 4; i++) {
            int idx = tid + i * 256;
            int r = idx >> 4, v = (idx & 15) * 16;
            const char* sp = (const char*)(g_vt + ((size_t)(b * 8 + hd) * 64 + r) * SEQ + kv0) + v;
            cpa16(st + r * VROW + v, sp);
        }
        CP_COMMIT();
    };

    load_k(0, 0);
    load_k(128, 1);

    const uint32_t sbQ = sb + Q_OFF;

    // ---- scores S = Q @ K^T (Wq pre-scaled by 1/8) ----
    int kbuf = 0;
    for (int ch = 0; ch < 8; ch++) {
        if (ch < 7) asm volatile("cp.async.wait_group 1;" ::: "memory");
        else        asm volatile("cp.async.wait_group 0;" ::: "memory");
        __syncthreads();
        if (ch + 2 < 8) {
            int nb = kbuf + 2; if (nb >= 3) nb -= 3;
            load_k((ch + 2) * 128, nb);
        }
        const uint32_t kb32 = sb + KV_OFF + kbuf * KMAT;
        float c[2][2][4];
        #pragma unroll
        for (int am = 0; am < 2; am++)
            #pragma unroll
            for (int nt = 0; nt < 2; nt++)
                #pragma unroll
                for (int e = 0; e < 4; e++) c[am][nt][e] = 0.0f;

        #pragma unroll
        for (int kk = 0; kk < 4; kk++) {
            const int kbyte = kk * 32;
            uint32_t aF[2][4];
            #pragma unroll
            for (int am = 0; am < 2; am++) {
                uint32_t arow = am * 16 + (t8 & 1) * 8 + r8;
                uint32_t acol = kbyte + (t8 >> 1) * 16;
                ldm_x4(aF[am], sbQ + arow * QROW + acol);
            }
            uint32_t krow = warp * 16 + (t8 >> 1) * 8 + r8;
            uint32_t kf[4];
            ldm_x4(kf, kb32 + krow * KROW + kbyte + (t8 & 1) * 16);
            #pragma unroll
            for (int nt = 0; nt < 2; nt++)
                #pragma unroll
                for (int am = 0; am < 2; am++)
                    mma16816(c[am][nt], aF[am], kf + 2 * nt);
        }
        #pragma unroll
        for (int am = 0; am < 2; am++)
            #pragma unroll
            for (int nt = 0; nt < 2; nt++) {
                int row = am * 16 + g;
                int col = ch * 128 + warp * 16 + nt * 8 + 2 * tig;
                *(float2*)&S[row * PSTR + col] =
                    make_float2(c[am][nt][0], c[am][nt][1]);
                *(float2*)&S[(row + 8) * PSTR + col] =
                    make_float2(c[am][nt][2], c[am][nt][3]);
            }
        if (++kbuf == 3) kbuf = 0;
    }

    __syncthreads();
    load_v(0, 0);
    load_v(128, 1);

    // ---- softmax; write probs; pack P fp16 in fragment-interleaved order --
    // word j (cols 2j,2j+1) of each 16-col group stored at pos(j)=2*(j&3)+(j>>2)
    #pragma unroll
    for (int rr = 0; rr < 4; rr++) {
        int row = warp * 4 + rr;
        float4 vals[8];
        float mx = -1e30f;
        #pragma unroll
        for (int v = 0; v < 8; v++) {
            vals[v] = *(float4*)&S[row * PSTR + (v * 32 + lane) * 4];
            mx = fmaxf(mx, fmaxf(fmaxf(vals[v].x, vals[v].y), fmaxf(vals[v].z, vals[v].w)));
        }
        #pragma unroll
        for (int o = 16; o > 0; o >>= 1) mx = fmaxf(mx, __shfl_xor_sync(0xffffffffu, mx, o));
        float sum = 0.f;
        #pragma unroll
        for (int v = 0; v < 8; v++) {
            vals[v].x = __expf(vals[v].x - mx);
            vals[v].y = __expf(vals[v].y - mx);
            vals[v].z = __expf(vals[v].z - mx);
            vals[v].w = __expf(vals[v].w - mx);
            sum += vals[v].x + vals[v].y + vals[v].z + vals[v].w;
        }
        #pragma unroll
        for (int o = 16; o > 0; o >>= 1) sum += __shfl_xor_sync(0xffffffffu, sum, o);
        float inv = 1.0f / sum;
        size_t pbase = ((tokbase + q0 + row) * NHEAD + hd) * SEQ;
        #pragma unroll
        for (int v = 0; v < 8; v++) {
            int cc = (v * 32 + lane) * 4;
            float p[4] = {vals[v].x * inv, vals[v].y * inv, vals[v].z * inv, vals[v].w * inv};
            *(float4*)&probs[pbase + cc] = make_float4(p[0], p[1], p[2], p[3]);
            __half2 w0; w0.x = __float2half_rn(p[0]); w0.y = __float2half_rn(p[1]);
            __half2 w1; w1.x = __float2half_rn(p[2]); w1.y = __float2half_rn(p[3]);
            int cg = cc >> 4;
            int j0 = (cc & 15) >> 1;                 // even: 0,2,4,6
            int base = row * PSTR + cg * 8;
            Su[base + 2 * (j0 & 3) + (j0 >> 2)]             = *(uint32_t*)&w0;
            Su[base + 2 * ((j0 + 1) & 3) + ((j0 + 1) >> 2)] = *(uint32_t*)&w1;
        }
    }
    __syncthreads();

    // ---- O = P @ V ----
    float o[2][4];
    #pragma unroll
    for (int am = 0; am < 2; am++)
        #pragma unroll
        for (int e = 0; e < 4; e++) o[am][e] = 0.0f;

    int vbuf = 0;
    for (int ch = 0; ch < 8; ch++) {
        if (ch < 7) asm volatile("cp.async.wait_group 1;" ::: "memory");
        else        asm volatile("cp.async.wait_group 0;" ::: "memory");
        __syncthreads();
        if (ch + 2 < 8) {
            int nb = vbuf + 2; if (nb >= 3) nb -= 3;
            load_v((ch + 2) * 128, nb);
        }
        const uint32_t vb32 = sb + KV_OFF + vbuf * VMAT;
        uint32_t vf[4];
        #pragma unroll
        for (int kk = 0; kk < 8; kk++) {
            if ((kk & 1) == 0) {
                uint32_t vaddr = vb32 + (warp * 8 + r8) * VROW + (kk >> 1) * 64 + t8 * 16;
                ldm_x4(vf, vaddr);
            }
            const uint32_t* vb = vf + 2 * (kk & 1);
            const int cg = ch * 8 + kk;
            #pragma unroll
            for (int am = 0; am < 2; am++) {
                int r = am * 16 + g;
                uint2 Ua = *(const uint2*)&Su[r * PSTR + cg * 8 + 2 * tig];
                uint2 Ub = *(const uint2*)&Su[(r + 8) * PSTR + cg * 8 + 2 * tig];
                uint32_t a[4] = {Ua.x, Ub.x, Ua.y, Ub.y};
                mma16816(o[am], a, vb);
            }
        }
        if (++vbuf == 3) vbuf = 0;
    }

    // ---- O epilogue: fp16 for Wo gemm ----
    #pragma unroll
    for (int am = 0; am < 2; am++) {
        int row = q0 + am * 16 + g;
        int col = hd * HD + warp * 8 + 2 * tig;
        #pragma unroll
        for (int h = 0; h < 2; h++) {
            size_t off = (tokbase + row + h * 8) * CDIM + col;
            __half2 hp;
            hp.x = __float2half_rn(o[am][h * 2 + 0]);
            hp.y = __float2half_rn(o[am][h * 2 + 1]);
            *(__half2*)(g_o + off) = hp;
        }
    }
}

// ---------------- launcher ----------------
extern "C" void kernel_launch(void* const* d_in, const int* in_sizes, int n_in,
                              void* d_out, int out_size)
{
    const float* x     = (const float*)d_in[0];
    const float* Wq    = (const float*)d_in[1];
    const float* Wk    = (const float*)d_in[2];
    const float* Wv    = (const float*)d_in[3];
    const float* Wo    = (const float*)d_in[4];
    const float* ln1_g = (const float*)d_in[5];
    const float* ln1_b = (const float*)d_in[6];
    const float* fc1_w = (const float*)d_in[7];
    const float* fc1_b = (const float*)d_in[8];
    const float* fc2_w = (const float*)d_in[9];
    const float* fc2_b = (const float*)d_in[10];
    const float* ln2_g = (const float*)d_in[11];
    const float* ln2_b = (const float*)d_in[12];

    float* out   = (float*)d_out;
    float* probs = out + (size_t)NTOK * CDIM;

    float *p_xn, *p_attn, *p_yn;
    __half *p_xnf, *p_ynf, *p_q, *p_k, *p_vt, *p_o, *p_h1;
    __half *p_wqt, *p_wkt, *p_wvt, *p_wot, *p_f1t, *p_f2t;
    cudaGetSymbolAddress((void**)&p_xn,   g_xn);
    cudaGetSymbolAddress((void**)&p_attn, g_attn);
    cudaGetSymbolAddress((void**)&p_yn,   g_yn);
    cudaGetSymbolAddress((void**)&p_xnf,  g_xnf);
    cudaGetSymbolAddress((void**)&p_ynf,  g_ynf);
    cudaGetSymbolAddress((void**)&p_q,    g_q);
    cudaGetSymbolAddress((void**)&p_k,    g_k);
    cudaGetSymbolAddress((void**)&p_vt,   g_vt);
    cudaGetSymbolAddress((void**)&p_o,    g_o);
    cudaGetSymbolAddress((void**)&p_h1,   g_h1);
    cudaGetSymbolAddress((void**)&p_wqt,  g_wqt);
    cudaGetSymbolAddress((void**)&p_wkt,  g_wkt);
    cudaGetSymbolAddress((void**)&p_wvt,  g_wvt);
    cudaGetSymbolAddress((void**)&p_wot,  g_wot);
    cudaGetSymbolAddress((void**)&p_f1t,  g_f1t);
    cudaGetSymbolAddress((void**)&p_f2t,  g_f2t);

    cudaFuncSetAttribute(attn_mma,
                         cudaFuncAttributeMaxDynamicSharedMemorySize, ATTN_SMEM);
    cudaFuncSetAttribute(gemm_mma<false, false, false, 2>,
                         cudaFuncAttributeMaxDynamicSharedMemorySize, GT_SMEM);
    cudaFuncSetAttribute(gemm_mma<false, false, false, 3>,
                         cudaFuncAttributeMaxDynamicSharedMemorySize, GT_SMEM);
    cudaFuncSetAttribute(gemm_mma<false, true, false, 0>,
                         cudaFuncAttributeMaxDynamicSharedMemorySize, GT_SMEM);
    cudaFuncSetAttribute(gemm_mma<true, false, true, 2>,
                         cudaFuncAttributeMaxDynamicSharedMemorySize, GT_SMEM);
    cudaFuncSetAttribute(gemm_mma<true, true, false, 0>,
                         cudaFuncAttributeMaxDynamicSharedMemorySize, GT_SMEM);

    // launch 0: LN1
    ln_kernel<<<NTOK, 128>>>(x, ln1_g, ln1_b, p_xn, p_xnf);

    // launch 1: all weight transposes (Wq folded with 1/8)
    transconv_all<<<3072, 256>>>(Wq, Wk, Wv, Wo, fc1_w, fc2_w);

    dim3 g512(CDIM / BN, NTOK / BM);
    // launches 2-4: Q, K fp16; V transposed fp16
    gemm_mma<false, false, false, 2><<<g512, 256, GT_SMEM>>>(
        p_xnf, p_wqt, nullptr, nullptr, nullptr, p_q, NTOK, CDIM, CDIM);
    gemm_mma<false, false, false, 2><<<g512, 256, GT_SMEM>>>(
        p_xnf, p_wkt, nullptr, nullptr, nullptr, p_k, NTOK, CDIM, CDIM);
    gemm_mma<false, false, false, 3><<<g512, 256, GT_SMEM>>>(
        p_xnf, p_wvt, nullptr, nullptr, nullptr, p_vt, NTOK, CDIM, CDIM);

    // launch 5 (ncu-profiled): attention
    attn_mma<<<dim3(32, NHEAD, NBATCH), 256, ATTN_SMEM>>>(probs);

    // launch 6: attn_out = O @ Wo + xn
    gemm_mma<false, true, false, 0><<<g512, 256, GT_SMEM>>>(
        p_o, p_wot, nullptr, p_xn, p_attn, nullptr, NTOK, CDIM, CDIM);

    // launch 7: LN2
    ln_kernel<<<NTOK, 128>>>(p_attn, ln2_g, ln2_b, p_yn, p_ynf);

    // launch 8: h1 = relu(yn @ fc1 + b1) -> fp16
    dim3 gff(FFDIM / BN, NTOK / BM);
    gemm_mma<true, false, true, 2><<<gff, 256, GT_SMEM>>>(
        p_ynf, p_f1t, fc1_b, nullptr, nullptr, p_h1, NTOK, FFDIM, CDIM);

    // launch 9: out = h1 @ fc2 + b2 + yn
    gemm_mma<true, true, false, 0><<<g512, 256, GT_SMEM>>>(
        p_h1, p_f2t, fc2_b, p_yn, out, nullptr, NTOK, CDIM, FFDIM);
}

// round 13
// speedup vs baseline: 5.6158x; 1.0262x over previous
#include <cuda_runtime.h>
#include <cuda_fp16.h>
#include <math.h>
#include <stdint.h>

// ---------------- problem constants ----------------
#define NTOK   8192
#define CDIM   512
#define FFDIM  2048
#define NHEAD  8
#define HD     64
#define SEQ    1024
#define NBATCH 8

// ---------------- scratch ----------------
__device__ float g_xn  [NTOK * CDIM];
__device__ float g_attn[NTOK * CDIM];
__device__ float g_yn  [NTOK * CDIM];

__device__ __half g_xnf[NTOK * CDIM];
__device__ __half g_ynf[NTOK * CDIM];
__device__ __half g_q  [NTOK * CDIM];
__device__ __half g_k  [NTOK * CDIM];
__device__ __half g_vt [NTOK * CDIM];     // V^T [b*8+h][d][kv]
__device__ __half g_o  [NTOK * CDIM];
__device__ __half g_h1 [NTOK * FFDIM];

__device__ __half g_wqt[CDIM * CDIM];
__device__ __half g_wkt[CDIM * CDIM];
__device__ __half g_wvt[CDIM * CDIM];
__device__ __half g_wot[CDIM * CDIM];
__device__ __half g_f1t[CDIM * FFDIM];
__device__ __half g_f2t[FFDIM * CDIM];

// ---------------- helpers ----------------
__device__ __forceinline__ uint32_t smem_u32(const void* p) {
    uint32_t a;
    asm("{ .reg .u64 t; cvta.to.shared.u64 t, %1; cvt.u32.u64 %0, t; }" : "=r"(a) : "l"(p));
    return a;
}
__device__ __forceinline__ void cpa16(uint32_t s, const void* g) {
    asm volatile("cp.async.cg.shared.global [%0], [%1], 16;" :: "r"(s), "l"(g) : "memory");
}
#define CP_COMMIT() asm volatile("cp.async.commit_group;" ::: "memory")

__device__ __forceinline__ void mma16816(float* c, const uint32_t* a, const uint32_t* b) {
    asm volatile("mma.sync.aligned.m16n8k16.row.col.f32.f16.f16.f32 "
        "{%0,%1,%2,%3}, {%4,%5,%6,%7}, {%8,%9}, {%0,%1,%2,%3};"
        : "+f"(c[0]), "+f"(c[1]), "+f"(c[2]), "+f"(c[3])
        : "r"(a[0]), "r"(a[1]), "r"(a[2]), "r"(a[3]), "r"(b[0]), "r"(b[1]));
}
__device__ __forceinline__ void ldm_x4(uint32_t* r, uint32_t addr) {
    asm volatile("ldmatrix.sync.aligned.m8n8.x4.shared.b16 {%0,%1,%2,%3}, [%4];"
        : "=r"(r[0]), "=r"(r[1]), "=r"(r[2]), "=r"(r[3]) : "r"(addr));
}

// ---------------- LayerNorm (fp32 out + fp16) ----------------
__global__ __launch_bounds__(128) void ln_kernel(
    const float* __restrict__ in, const float* __restrict__ gam,
    const float* __restrict__ bet, float* __restrict__ out,
    __half* __restrict__ oh)
{
    const int row = blockIdx.x;
    const int t = threadIdx.x;
    const float4* x4 = (const float4*)(in + (size_t)row * CDIM);
    float4 v = x4[t];
    float s  = v.x + v.y + v.z + v.w;
    float ss = fmaf(v.x, v.x, fmaf(v.y, v.y, fmaf(v.z, v.z, v.w * v.w)));
    #pragma unroll
    for (int o = 16; o > 0; o >>= 1) {
        s  += __shfl_xor_sync(0xffffffffu, s,  o);
        ss += __shfl_xor_sync(0xffffffffu, ss, o);
    }
    __shared__ float sh[4], shh[4];
    const int wid = t >> 5, lane = t & 31;
    if (lane == 0) { sh[wid] = s; shh[wid] = ss; }
    __syncthreads();
    float tot  = sh[0] + sh[1] + sh[2] + sh[3];
    float tot2 = shh[0] + shh[1] + shh[2] + shh[3];
    const float mean = tot * (1.0f / CDIM);
    const float var  = tot2 * (1.0f / CDIM) - mean * mean;
    const float r    = rsqrtf(var + 1e-5f);
    float4 g = ((const float4*)gam)[t];
    float4 b = ((const float4*)bet)[t];
    float o4[4];
    o4[0] = (v.x - mean) * r * g.x + b.x;
    o4[1] = (v.y - mean) * r * g.y + b.y;
    o4[2] = (v.z - mean) * r * g.z + b.z;
    o4[3] = (v.w - mean) * r * g.w + b.w;
    ((float4*)(out + (size_t)row * CDIM))[t] = make_float4(o4[0], o4[1], o4[2], o4[3]);
    size_t base = (size_t)row * CDIM + t * 4;
    __half2 p0; p0.x = __float2half_rn(o4[0]); p0.y = __float2half_rn(o4[1]);
    __half2 p1; p1.x = __float2half_rn(o4[2]); p1.y = __float2half_rn(o4[3]);
    *(__half2*)(oh + base)     = p0;
    *(__half2*)(oh + base + 2) = p1;
}

// ------------- all weight transposes (fp16) in ONE launch ----------
__global__ __launch_bounds__(256) void transconv_all(
    const float* __restrict__ Wq, const float* __restrict__ Wk,
    const float* __restrict__ Wv, const float* __restrict__ Wo,
    const float* __restrict__ F1, const float* __restrict__ F2)
{
    const int bid = blockIdx.x;
    const float* W; __half* Th;
    int K, N, nb, idx; float scale = 1.0f;
    if (bid < 1024) {
        int which = bid >> 8; idx = bid & 255; K = 512; N = 512; nb = 16;
        if (which == 0)      { W = Wq; Th = g_wqt; scale = 0.125f; }
        else if (which == 1) { W = Wk; Th = g_wkt; }
        else if (which == 2) { W = Wv; Th = g_wvt; }
        else                 { W = Wo; Th = g_wot; }
    } else if (bid < 2048) {
        idx = bid - 1024; W = F1; Th = g_f1t; K = 512; N = 2048; nb = 64;
    } else {
        idx = bid - 2048; W = F2; Th = g_f2t; K = 2048; N = 512; nb = 16;
    }
    const int n0 = (idx % nb) * 32, k0 = (idx / nb) * 32;
    __shared__ float t[32][33];
    const int tx = threadIdx.x & 31, ty = threadIdx.x >> 5;
    #pragma unroll
    for (int i = 0; i < 4; i++)
        t[ty + i * 8][tx] = W[(size_t)(k0 + ty + i * 8) * N + n0 + tx];
    __syncthreads();
    #pragma unroll
    for (int i = 0; i < 4; i++) {
        int r = ty + i * 8;
        Th[(size_t)(n0 + r) * K + k0 + tx] = __float2half_rn(t[tx][r] * scale);
    }
}

// -------- mma.sync fp16 GEMM: KC=64, 3-stage single-sync pipeline ---------
#define BM 128
#define BN 128
#define KC 64
#define ROWB 144
#define MAT_BYTES (128 * ROWB)               // 18432
#define A_OFF 0
#define B_OFF MAT_BYTES
#define STAGE_BYTES (2 * MAT_BYTES)          // 36864
#define GT_SMEM (3 * STAGE_BYTES)            // 110592

// OM: 0 = fp32 Cf; 2 = fp16 Ch; 3 = transposed fp16 Ch
template <bool BIAS, bool RES, bool RELU, int OM>
__global__ __launch_bounds__(256, 2) void gemm_mma(
    const __half* __restrict__ A, const __half* __restrict__ B,
    const float* __restrict__ bias, const float* __restrict__ res,
    float* __restrict__ Cf, __half* __restrict__ Ch, int M, int N, int K)
{
    extern __shared__ char sm[];
    const uint32_t sbase = smem_u32(sm);
    const int tid  = threadIdx.x;
    const int lane = tid & 31;
    const int warp = tid >> 5;
    const int wm0  = (warp & 3) * 32;
    const int wn0  = (warp >> 2) * 64;
    const int g    = lane >> 2;
    const int tig  = lane & 3;
    const int t8   = lane >> 3;
    const int r8   = lane & 7;
    const int bm0  = blockIdx.y * BM;
    const int bn0  = blockIdx.x * BN;

    float acc[2][8][4];
    #pragma unroll
    for (int i = 0; i < 2; i++)
        #pragma unroll
        for (int j = 0; j < 8; j++)
            #pragma unroll
            for (int e = 0; e < 4; e++) acc[i][j][e] = 0.0f;

    auto load_stage = [&](int kt, int buf) {
        const uint32_t st = sbase + buf * STAGE_BYTES;
        #pragma unroll
        for (int i = 0; i < 8; i++) {
            int idx = tid + i * 256;              // 0..2047
            int mat = idx >> 10;                  // 0..1
            int rix = idx & 1023;
            int r   = rix >> 3;                   // 0..127
            int cb  = (rix & 7) * 16;             // 0..112
            const __half* gs = mat ? B : A;
            int grow = mat ? (bn0 + r) : (bm0 + r);
            const char* src = (const char*)(gs + (size_t)grow * K + kt) + cb;
            cpa16(st + mat * MAT_BYTES + r * ROWB + cb, src);
        }
        CP_COMMIT();
    };

    const int S = K / KC;
    load_stage(0, 0);
    load_stage(KC, 1);

    int buf = 0;
    for (int s = 0; s < S; s++) {
        if (s + 1 < S) asm volatile("cp.async.wait_group 1;" ::: "memory");
        else           asm volatile("cp.async.wait_group 0;" ::: "memory");
        __syncthreads();
        if (s + 2 < S) {
            int nb = buf + 2; if (nb >= 3) nb -= 3;
            load_stage((s + 2) * KC, nb);
        }

        const uint32_t sb32 = sbase + buf * STAGE_BYTES;
        #pragma unroll
        for (int kk = 0; kk < 4; kk++) {
            const int kbyte = kk * 32;
            uint32_t aF[2][4];
            #pragma unroll
            for (int am = 0; am < 2; am++) {
                uint32_t arow = wm0 + am * 16 + (t8 & 1) * 8 + r8;
                uint32_t acol = kbyte + (t8 >> 1) * 16;
                ldm_x4(aF[am], sb32 + A_OFF + arow * ROWB + acol);
            }
            #pragma unroll
            for (int bn2 = 0; bn2 < 4; bn2++) {
                uint32_t brow = wn0 + (2 * bn2 + (t8 >> 1)) * 8 + r8;
                uint32_t bcol = kbyte + (t8 & 1) * 16;
                uint32_t b4[4];
                ldm_x4(b4, sb32 + B_OFF + brow * ROWB + bcol);
                #pragma unroll
                for (int half = 0; half < 2; half++) {
                    const int bn = 2 * bn2 + half;
                    const uint32_t* b = b4 + 2 * half;
                    mma16816(acc[0][bn], aF[0], b);
                    mma16816(acc[1][bn], aF[1], b);
                }
            }
        }
        if (++buf == 3) buf = 0;
    }

    // epilogue
    #pragma unroll
    for (int am = 0; am < 2; am++) {
        #pragma unroll
        for (int bn = 0; bn < 8; bn++) {
            const int row = bm0 + wm0 + am * 16 + g;
            const int col = bn0 + wn0 + bn * 8 + 2 * tig;
            float* c = acc[am][bn];
            #pragma unroll
            for (int h = 0; h < 2; h++) {
                const int r = row + h * 8;
                float v0 = c[h * 2 + 0];
                float v1 = c[h * 2 + 1];
                if (BIAS) { v0 += bias[col]; v1 += bias[col + 1]; }
                if (RES) {
                    float2 rr = *(const float2*)&res[(size_t)r * N + col];
                    v0 += rr.x; v1 += rr.y;
                }
                if (RELU) { v0 = fmaxf(v0, 0.f); v1 = fmaxf(v1, 0.f); }
                if (OM == 3) {
                    int bb = r >> 10, kv = r & 1023;
                    int head = col >> 6, d = col & 63;
                    size_t tb = ((size_t)(bb * 8 + head) * 64 + d) * 1024 + kv;
                    Ch[tb]        = __float2half_rn(v0);
                    Ch[tb + 1024] = __float2half_rn(v1);
                } else if (OM == 2) {
                    __half2 hp; hp.x = __float2half_rn(v0); hp.y = __float2half_rn(v1);
                    *(__half2*)(Ch + (size_t)r * N + col) = hp;
                } else {
                    *(float2*)&Cf[(size_t)r * N + col] = make_float2(v0, v1);
                }
            }
        }
    }
}

// -------- mma attention: 512 threads, 16 warps, q-split work --------------
#define PSTR    1040
#define S_BYTES (32 * PSTR * 4)              // 133120
#define Q_OFF   S_BYTES
#define QROW    144
#define Q_BYTES (32 * QROW)                  // 4608
#define KV_OFF  (Q_OFF + Q_BYTES)            // 137728
#define KROW 144
#define KMAT (128 * KROW)                    // 18432
#define VROW 272
#define VMAT (64 * VROW)                     // 17408
#define ATTN_SMEM (KV_OFF + 3 * KMAT)        // 193024

__global__ __launch_bounds__(512, 1) void attn_mma(float* __restrict__ probs)
{
    extern __shared__ char sm[];
    float* S = (float*)sm;
    uint32_t* Su = (uint32_t*)sm;
    const uint32_t sb = smem_u32(sm);
    const int tid = threadIdx.x, lane = tid & 31, warp = tid >> 5;
    const int wq = warp >> 3;            // 0..1 : q half (16 rows)
    const int wv = warp & 7;             // 0..7 : kv-tile / d-group
    const int g = lane >> 2, tig = lane & 3;
    const int t8 = lane >> 3, r8 = lane & 7;
    const int qb = blockIdx.x, hd = blockIdx.y, b = blockIdx.z;
    const int q0 = qb * 32;
    const size_t tokbase = (size_t)b * SEQ;

    // Q tile -> smem (32 rows x 128 B), first 256 threads
    if (tid < 256) {
        int r = tid >> 3, v = (tid & 7) * 16;
        const char* sp = (const char*)(g_q + (tokbase + q0 + r) * CDIM + hd * HD) + v;
        *(uint4*)(sm + Q_OFF + r * QROW + v) = *(const uint4*)sp;
    }

    auto load_k = [&](int kv0, int buf) {
        const uint32_t st = sb + KV_OFF + buf * KMAT;
        #pragma unroll
        for (int i = 0; i < 2; i++) {
            int idx = tid + i * 512;             // 0..1023
            int r = idx >> 3, v = (idx & 7) * 16;
            const char* sp = (const char*)(g_k + (tokbase + kv0 + r) * CDIM + hd * HD) + v;
            cpa16(st + r * KROW + v, sp);
        }
        CP_COMMIT();
    };
    auto load_v = [&](int kv0, int buf) {
        const uint32_t st = sb + KV_OFF + buf * VMAT;
        #pragma unroll
        for (int i = 0; i < 2; i++) {
            int idx = tid + i * 512;             // 0..1023
            int r = idx >> 4, v = (idx & 15) * 16;
            const char* sp = (const char*)(g_vt + ((size_t)(b * 8 + hd) * 64 + r) * SEQ + kv0) + v;
            cpa16(st + r * VROW + v, sp);
        }
        CP_COMMIT();
    };

    load_k(0, 0);
    load_k(128, 1);

    const uint32_t sbQ = sb + Q_OFF;

    // ---- scores S = Q @ K^T (Wq pre-scaled by 1/8) ----
    // warp (wq, wv): 16 q rows x 16 kv cols of each 128-kv chunk
    int kbuf = 0;
    for (int ch = 0; ch < 8; ch++) {
        if (ch < 7) asm volatile("cp.async.wait_group 1;" ::: "memory");
        else        asm volatile("cp.async.wait_group 0;" ::: "memory");
        __syncthreads();
        if (ch + 2 < 8) {
            int nb = kbuf + 2; if (nb >= 3) nb -= 3;
            load_k((ch + 2) * 128, nb);
        }
        const uint32_t kb32 = sb + KV_OFF + kbuf * KMAT;
        float c[2][4];
        #pragma unroll
        for (int nt = 0; nt < 2; nt++)
            #pragma unroll
            for (int e = 0; e < 4; e++) c[nt][e] = 0.0f;

        #pragma unroll
        for (int kk = 0; kk < 4; kk++) {
            const int kbyte = kk * 32;
            uint32_t aF[4];
            uint32_t arow = wq * 16 + (t8 & 1) * 8 + r8;
            uint32_t acol = kbyte + (t8 >> 1) * 16;
            ldm_x4(aF, sbQ + arow * QROW + acol);
            uint32_t krow = wv * 16 + (t8 >> 1) * 8 + r8;
            uint32_t kf[4];
            ldm_x4(kf, kb32 + krow * KROW + kbyte + (t8 & 1) * 16);
            mma16816(c[0], aF, kf);
            mma16816(c[1], aF, kf + 2);
        }
        #pragma unroll
        for (int nt = 0; nt < 2; nt++) {
            int row = wq * 16 + g;
            int col = ch * 128 + wv * 16 + nt * 8 + 2 * tig;
            *(float2*)&S[row * PSTR + col] = make_float2(c[nt][0], c[nt][1]);
            *(float2*)&S[(row + 8) * PSTR + col] = make_float2(c[nt][2], c[nt][3]);
        }
        if (++kbuf == 3) kbuf = 0;
    }

    __syncthreads();          // K reads + S writes complete
    load_v(0, 0);
    load_v(128, 1);

    // ---- softmax (2 rows per warp); probs out; packed fp16 P in S --------
    #pragma unroll
    for (int rr = 0; rr < 2; rr++) {
        int row = warp * 2 + rr;
        float4 vals[8];
        float mx = -1e30f;
        #pragma unroll
        for (int v = 0; v < 8; v++) {
            vals[v] = *(float4*)&S[row * PSTR + (v * 32 + lane) * 4];
            mx = fmaxf(mx, fmaxf(fmaxf(vals[v].x, vals[v].y), fmaxf(vals[v].z, vals[v].w)));
        }
        #pragma unroll
        for (int o = 16; o > 0; o >>= 1) mx = fmaxf(mx, __shfl_xor_sync(0xffffffffu, mx, o));
        float sum = 0.f;
        #pragma unroll
        for (int v = 0; v < 8; v++) {
            vals[v].x = __expf(vals[v].x - mx);
            vals[v].y = __expf(vals[v].y - mx);
            vals[v].z = __expf(vals[v].z - mx);
            vals[v].w = __expf(vals[v].w - mx);
            sum += vals[v].x + vals[v].y + vals[v].z + vals[v].w;
        }
        #pragma unroll
        for (int o = 16; o > 0; o >>= 1) sum += __shfl_xor_sync(0xffffffffu, sum, o);
        float inv = 1.0f / sum;
        size_t pbase = ((tokbase + q0 + row) * NHEAD + hd) * SEQ;
        #pragma unroll
        for (int v = 0; v < 8; v++) {
            int cc = (v * 32 + lane) * 4;
            float p[4] = {vals[v].x * inv, vals[v].y * inv, vals[v].z * inv, vals[v].w * inv};
            *(float4*)&probs[pbase + cc] = make_float4(p[0], p[1], p[2], p[3]);
            __half2 w0; w0.x = __float2half_rn(p[0]); w0.y = __float2half_rn(p[1]);
            __half2 w1; w1.x = __float2half_rn(p[2]); w1.y = __float2half_rn(p[3]);
            int cg = cc >> 4;
            int j0 = (cc & 15) >> 1;
            int base = row * PSTR + cg * 8;
            Su[base + 2 * (j0 & 3) + (j0 >> 2)]             = *(uint32_t*)&w0;
            Su[base + 2 * ((j0 + 1) & 3) + ((j0 + 1) >> 2)] = *(uint32_t*)&w1;
        }
    }
    __syncthreads();

    // ---- O = P @ V ----  warp (wq, wd=wv): 16 q rows x 8 d cols
    float o[4];
    #pragma unroll
    for (int e = 0; e < 4; e++) o[e] = 0.0f;

    int vbuf = 0;
    for (int ch = 0; ch < 8; ch++) {
        if (ch < 7) asm volatile("cp.async.wait_group 1;" ::: "memory");
        else        asm volatile("cp.async.wait_group 0;" ::: "memory");
        __syncthreads();
        if (ch + 2 < 8) {
            int nb = vbuf + 2; if (nb >= 3) nb -= 3;
            load_v((ch + 2) * 128, nb);
        }
        const uint32_t vb32 = sb + KV_OFF + vbuf * VMAT;
        uint32_t vf[4];
        #pragma unroll
        for (int kk = 0; kk < 8; kk++) {
            if ((kk & 1) == 0) {
                uint32_t vaddr = vb32 + (wv * 8 + r8) * VROW + (kk >> 1) * 64 + t8 * 16;
                ldm_x4(vf, vaddr);
            }
            const uint32_t* vb = vf + 2 * (kk & 1);
            const int cg = ch * 8 + kk;
            int r = wq * 16 + g;
            uint2 Ua = *(const uint2*)&Su[r * PSTR + cg * 8 + 2 * tig];
            uint2 Ub = *(const uint2*)&Su[(r + 8) * PSTR + cg * 8 + 2 * tig];
            uint32_t a[4] = {Ua.x, Ub.x, Ua.y, Ub.y};
            mma16816(o, a, vb);
        }
        if (++vbuf == 3) vbuf = 0;
    }

    // ---- O epilogue: fp16 for Wo gemm ----
    {
        int row = q0 + wq * 16 + g;
        int col = hd * HD + wv * 8 + 2 * tig;
        #pragma unroll
        for (int h = 0; h < 2; h++) {
            size_t off = (tokbase + row + h * 8) * CDIM + col;
            __half2 hp;
            hp.x = __float2half_rn(o[h * 2 + 0]);
            hp.y = __float2half_rn(o[h * 2 + 1]);
            *(__half2*)(g_o + off) = hp;
        }
    }
}

// ---------------- launcher ----------------
extern "C" void kernel_launch(void* const* d_in, const int* in_sizes, int n_in,
                              void* d_out, int out_size)
{
    const float* x     = (const float*)d_in[0];
    const float* Wq    = (const float*)d_in[1];
    const float* Wk    = (const float*)d_in[2];
    const float* Wv    = (const float*)d_in[3];
    const float* Wo    = (const float*)d_in[4];
    const float* ln1_g = (const float*)d_in[5];
    const float* ln1_b = (const float*)d_in[6];
    const float* fc1_w = (const float*)d_in[7];
    const float* fc1_b = (const float*)d_in[8];
    const float* fc2_w = (const float*)d_in[9];
    const float* fc2_b = (const float*)d_in[10];
    const float* ln2_g = (const float*)d_in[11];
    const float* ln2_b = (const float*)d_in[12];

    float* out   = (float*)d_out;
    float* probs = out + (size_t)NTOK * CDIM;

    float *p_xn, *p_attn, *p_yn;
    __half *p_xnf, *p_ynf, *p_q, *p_k, *p_vt, *p_o, *p_h1;
    __half *p_wqt, *p_wkt, *p_wvt, *p_wot, *p_f1t, *p_f2t;
    cudaGetSymbolAddress((void**)&p_xn,   g_xn);
    cudaGetSymbolAddress((void**)&p_attn, g_attn);
    cudaGetSymbolAddress((void**)&p_yn,   g_yn);
    cudaGetSymbolAddress((void**)&p_xnf,  g_xnf);
    cudaGetSymbolAddress((void**)&p_ynf,  g_ynf);
    cudaGetSymbolAddress((void**)&p_q,    g_q);
    cudaGetSymbolAddress((void**)&p_k,    g_k);
    cudaGetSymbolAddress((void**)&p_vt,   g_vt);
    cudaGetSymbolAddress((void**)&p_o,    g_o);
    cudaGetSymbolAddress((void**)&p_h1,   g_h1);
    cudaGetSymbolAddress((void**)&p_wqt,  g_wqt);
    cudaGetSymbolAddress((void**)&p_wkt,  g_wkt);
    cudaGetSymbolAddress((void**)&p_wvt,  g_wvt);
    cudaGetSymbolAddress((void**)&p_wot,  g_wot);
    cudaGetSymbolAddress((void**)&p_f1t,  g_f1t);
    cudaGetSymbolAddress((void**)&p_f2t,  g_f2t);

    cudaFuncSetAttribute(attn_mma,
                         cudaFuncAttributeMaxDynamicSharedMemorySize, ATTN_SMEM);
    cudaFuncSetAttribute(gemm_mma<false, false, false, 2>,
                         cudaFuncAttributeMaxDynamicSharedMemorySize, GT_SMEM);
    cudaFuncSetAttribute(gemm_mma<false, false, false, 3>,
                         cudaFuncAttributeMaxDynamicSharedMemorySize, GT_SMEM);
    cudaFuncSetAttribute(gemm_mma<false, true, false, 0>,
                         cudaFuncAttributeMaxDynamicSharedMemorySize, GT_SMEM);
    cudaFuncSetAttribute(gemm_mma<true, false, true, 2>,
                         cudaFuncAttributeMaxDynamicSharedMemorySize, GT_SMEM);
    cudaFuncSetAttribute(gemm_mma<true, true, false, 0>,
                         cudaFuncAttributeMaxDynamicSharedMemorySize, GT_SMEM);

    // launch 0: LN1
    ln_kernel<<<NTOK, 128>>>(x, ln1_g, ln1_b, p_xn, p_xnf);

    // launch 1: all weight transposes (Wq folded with 1/8)
    transconv_all<<<3072, 256>>>(Wq, Wk, Wv, Wo, fc1_w, fc2_w);

    dim3 g512(CDIM / BN, NTOK / BM);
    // launches 2-4: Q, K fp16; V transposed fp16
    gemm_mma<false, false, false, 2><<<g512, 256, GT_SMEM>>>(
        p_xnf, p_wqt, nullptr, nullptr, nullptr, p_q, NTOK, CDIM, CDIM);
    gemm_mma<false, false, false, 2><<<g512, 256, GT_SMEM>>>(
        p_xnf, p_wkt, nullptr, nullptr, nullptr, p_k, NTOK, CDIM, CDIM);
    gemm_mma<false, false, false, 3><<<g512, 256, GT_SMEM>>>(
        p_xnf, p_wvt, nullptr, nullptr, nullptr, p_vt, NTOK, CDIM, CDIM);

    // launch 5 (ncu-profiled): attention
    attn_mma<<<dim3(32, NHEAD, NBATCH), 512, ATTN_SMEM>>>(probs);

    // launch 6: attn_out = O @ Wo + xn
    gemm_mma<false, true, false, 0><<<g512, 256, GT_SMEM>>>(
        p_o, p_wot, nullptr, p_xn, p_attn, nullptr, NTOK, CDIM, CDIM);

    // launch 7: LN2
    ln_kernel<<<NTOK, 128>>>(p_attn, ln2_g, ln2_b, p_yn, p_ynf);

    // launch 8: h1 = relu(yn @ fc1 + b1) -> fp16
    dim3 gff(FFDIM / BN, NTOK / BM);
    gemm_mma<true, false, true, 2><<<gff, 256, GT_SMEM>>>(
        p_ynf, p_f1t, fc1_b, nullptr, nullptr, p_h1, NTOK, FFDIM, CDIM);

    // launch 9: out = h1 @ fc2 + b2 + yn
    gemm_mma<true, true, false, 0><<<g512, 256, GT_SMEM>>>(
        p_h1, p_f2t, fc2_b, p_yn, out, nullptr, NTOK, CDIM, FFDIM);
}